// round 4
// baseline (speedup 1.0000x reference)
#include <cuda_runtime.h>
#include <math.h>
#include <stdint.h>

// Problem constants
#define NUM_B 2
#define NUM_C 256
#define IMG_H 96
#define IMG_W 320
#define NLAYER 5
#define NQ (128 * 128)           // 16384
#define NM (NUM_B * NQ)          // 32768
#define NK (NUM_C * NLAYER)      // 1280
#define HW (IMG_H * IMG_W)       // 30720
#define NROWS (NUM_B * NUM_C * IMG_H)     // 49152
#define NBOX (NUM_B * NLAYER * NQ)        // 163840

// Scratch (device globals: allocation-free per harness rules)
__device__ float  g_rowcum[NUM_B * NUM_C * IMG_H * IMG_W];     // 63MB
__device__ float  g_itrans[NUM_B * IMG_H * IMG_W * NUM_C];     // 63MB, [b][y][x][c]
__device__ float  g_wperm[NUM_C * NK];                         // 1.3MB, [co][layer*256+c], tf32-rounded
__device__ int2   g_tap[NBOX * 16];                            // {pixel idx, weight bits} (zeros if invisible)

__device__ __forceinline__ float tf32r(float v) {
    uint32_t o;
    asm("cvt.rna.tf32.f32 %0, %1;" : "=r"(o) : "f"(v));
    return __uint_as_float(o);
}
__device__ __forceinline__ uint32_t smem_u32(const void* p) {
    uint32_t a;
    asm("{ .reg .u64 t; cvta.to.shared.u64 t, %1; cvt.u32.u64 %0, t; }" : "=r"(a) : "l"(p));
    return a;
}
__device__ __forceinline__ void cp16(uint32_t saddr, const void* gptr) {
    asm volatile("cp.async.cg.shared.global [%0], [%1], 16;" :: "r"(saddr), "l"(gptr) : "memory");
}
__device__ __forceinline__ void mma_tf32(float c[4], uint32_t a0, uint32_t a1, uint32_t a2,
                                         uint32_t a3, uint32_t b0, uint32_t b1) {
    asm volatile(
        "mma.sync.aligned.m16n8k8.row.col.f32.tf32.tf32.f32 "
        "{%0,%1,%2,%3}, {%4,%5,%6,%7}, {%8,%9}, {%0,%1,%2,%3};"
        : "+f"(c[0]), "+f"(c[1]), "+f"(c[2]), "+f"(c[3])
        : "r"(a0), "r"(a1), "r"(a2), "r"(a3), "r"(b0), "r"(b1));
}

// ---------------- K1: row cumsum, warp-per-row shfl scan ----------------
__global__ void k_rowcum(const float* __restrict__ feat) {
    int w = (blockIdx.x * blockDim.x + threadIdx.x) >> 5;
    int lane = threadIdx.x & 31;
    if (w >= NROWS) return;
    const float* src = feat + (size_t)w * IMG_W;
    float* dst = g_rowcum + (size_t)w * IMG_W;
    float carry = 0.0f;
    #pragma unroll
    for (int c0 = 0; c0 < IMG_W; c0 += 32) {
        float v = src[c0 + lane];
        #pragma unroll
        for (int d = 1; d < 32; d <<= 1) {
            float n = __shfl_up_sync(0xFFFFFFFFu, v, d);
            if (lane >= d) v += n;
        }
        v += carry;
        dst[c0 + lane] = v;
        carry = __shfl_sync(0xFFFFFFFFu, v, 31);
    }
}

// ---------------- K2: column cumsum + transpose to [b][y][x][c], tiled ----------------
__global__ void k_colcum_t() {
    __shared__ float tile[32][33];
    int x0 = blockIdx.x * 32;
    int c0 = blockIdx.y * 32;
    int b  = blockIdx.z;
    int tx = threadIdx.x, ty = threadIdx.y;
    const float* src = g_rowcum + ((size_t)(b * NUM_C + c0 + ty) * IMG_H) * IMG_W + x0 + tx;
    float* dstbase = g_itrans + (size_t)b * HW * NUM_C;
    float acc = 0.0f;
    for (int y = 0; y < IMG_H; ++y) {
        acc += src[(size_t)y * IMG_W];
        tile[ty][tx] = acc;
        __syncthreads();
        dstbase[((size_t)y * IMG_W + x0 + ty) * NUM_C + c0 + tx] = tile[tx][ty];
        __syncthreads();
    }
}

// ---------------- K3: project corners -> per-box tap table (always written) ----------------
__global__ void k_boxes(const float* __restrict__ calib, const float* __restrict__ grid) {
    int i = blockIdx.x * blockDim.x + threadIdx.x;
    if (i >= NBOX) return;
    int q = i % NQ;
    int layer = (i / NQ) % NLAYER;
    int b = i / (NQ * NLAYER);

    float gx = grid[q * 3 + 0];
    float gy = grid[q * 3 + 1];
    float gz = grid[q * 3 + 2] + 32.0f * (float)layer;

    const float* M = calib + b * 12;
    float m00 = M[0], m01 = M[1], m02 = M[2],  m03 = M[3];
    float m10 = M[4], m11 = M[5], m12 = M[6],  m13 = M[7];
    float m20 = M[8], m21 = M[9], m22 = M[10], m23 = M[11];

    const float ox[8] = {-12.5f, 12.5f, 12.5f, -12.5f, -12.5f, 12.5f, 12.5f, -12.5f};
    const float oy[8] = {-12.5f, -12.5f, 12.5f, 12.5f, -12.5f, -12.5f, 12.5f, 12.5f};
    const float oz[8] = {0.0f, 0.0f, 0.0f, 0.0f, 32.0f, 32.0f, 32.0f, 32.0f};

    float mnx = 1e30f, mny = 1e30f, mxx = -1e30f, mxy = -1e30f;
    #pragma unroll
    for (int k = 0; k < 8; ++k) {
        float X = gx + ox[k];
        float Y = gy + oy[k];
        float Z = gz + oz[k];
        float px = m00 * X + m01 * Y + m02 * Z + m03;
        float py = m10 * X + m11 * Y + m12 * Z + m13;
        float pz = m20 * X + m21 * Y + m22 * Z + m23;
        float zc = fmaxf(pz, 1e-6f);
        float ix = px / zc;
        float iy = py / zc;
        float nx = fminf(fmaxf(2.0f * ix / 320.0f - 1.0f, -1.0f), 0.95f);
        float ny = fminf(fmaxf(2.0f * iy / 96.0f - 1.0f, -1.0f), 0.95f);
        mnx = fminf(mnx, nx);
        mny = fminf(mny, ny);
        mxx = fmaxf(mxx, nx);
        mxy = fmaxf(mxy, ny);
    }

    float area = ((mxx - mnx) * (mxy - mny)) * (float)HW + 1e-6f;
    bool visible = (area > 1e-6f) && (area < (float)HW * 0.3f);
    float inv = visible ? (1.0f / area) : 0.0f;

    float xs[2], ys[2];
    xs[0] = ((mnx + 1.0f) * 320.0f - 1.0f) * 0.5f;
    xs[1] = ((mxx + 1.0f) * 320.0f - 1.0f) * 0.5f;
    ys[0] = ((mny + 1.0f) * 96.0f - 1.0f) * 0.5f;
    ys[1] = ((mxy + 1.0f) * 96.0f - 1.0f) * 0.5f;

    // corners: lt(min,min,+), rb(max,max,+), rt(max,min,-), lb(min,max,-)
    const int cxi[4] = {0, 1, 1, 0};
    const int cyi[4] = {0, 1, 0, 1};
    const float csg[4] = {1.0f, 1.0f, -1.0f, -1.0f};
    int2* tp = g_tap + (size_t)i * 16;
    #pragma unroll
    for (int cc = 0; cc < 4; ++cc) {
        float sx = xs[cxi[cc]], sy = ys[cyi[cc]];
        float fx = floorf(sx), fy = floorf(sy);
        int x0 = (int)fx, y0 = (int)fy;
        float wx1 = sx - fx, wy1 = sy - fy;
        float wx0 = 1.0f - wx1, wy0 = 1.0f - wy1;
        float s = csg[cc] * inv;
        #pragma unroll
        for (int tt = 0; tt < 4; ++tt) {
            int xi = x0 + (tt & 1);
            int yi = y0 + (tt >> 1);
            float w = ((tt & 1) ? wx1 : wx0) * ((tt >> 1) ? wy1 : wy0) * s;
            bool valid = visible && ((unsigned)xi < (unsigned)IMG_W) && ((unsigned)yi < (unsigned)IMG_H);
            int idx = valid ? (yi * IMG_W + xi) : 0;
            if (!valid) w = 0.0f;
            tp[cc * 4 + tt] = make_int2(idx, __float_as_int(w));
        }
    }
}

// ---------------- K5: permute Wc to K-order layer*256+c (tf32-rounded) ----------------
__global__ void k_wperm(const float* __restrict__ Wc) {
    int idx = blockIdx.x * blockDim.x + threadIdx.x;
    if (idx >= NUM_C * NK) return;
    int co = idx / NK;
    int kd = idx % NK;
    int layer = kd / NUM_C;
    int c = kd % NUM_C;
    g_wperm[idx] = tf32r(Wc[co * NK + c * NLAYER + layer]);
}

// ---------------- K6: fused sample + GEMM (128M x 256N CTA tile, K=1280) ----------------
// 512 threads = 16 warps as 4(M)x4(N); warp tile 32x64. K-chunk 32 (8 chunks/layer).
// A produced on the fly from integral-image taps; B from g_wperm via cp.async.
// Smem: A[2][128][36] | B[2][256][36] | taps[5][128][16] (int2)
#define SM_ROW 36
#define ASZ (128 * SM_ROW)          // 4608 floats
#define BSZ (256 * SM_ROW)          // 9216 floats
#define TAP_OFF ((2 * ASZ + 2 * BSZ) * 4)        // 110592 bytes
#define FSM_BYTES (TAP_OFF + NLAYER * 128 * 16 * 8)  // 192512 bytes
#define NKT (NK / 32)               // 40

__global__ __launch_bounds__(512, 1) void k_fused(const float* __restrict__ bc,
                                                  float* __restrict__ out) {
    extern __shared__ float smf[];
    int2* staps = (int2*)((char*)smf + TAP_OFF);
    uint32_t smb = smem_u32(smf);
    int tid = threadIdx.x;
    int wid = tid >> 5;
    int lane = tid & 31;
    int g = lane >> 2;
    int tg = lane & 3;
    int wm = wid & 3;
    int wn = wid >> 2;
    int m0 = blockIdx.x * 128;
    int b = m0 >> 14;
    int q0 = m0 & (NQ - 1);

    // Preload taps for all layers of this CTA's 128 rows
    for (int e = tid; e < NLAYER * 128 * 16; e += 512) {
        int layer = e >> 11;
        int rem = e & 2047;
        int row = rem >> 4;
        int tap = rem & 15;
        staps[e] = g_tap[((size_t)((b * NLAYER + layer) * NQ + q0 + row)) * 16 + tap];
    }
    __syncthreads();

    const float* Ibase = g_itrans + (size_t)b * HW * NUM_C;

    float acc[2][8][4];
    #pragma unroll
    for (int mi = 0; mi < 2; ++mi)
        #pragma unroll
        for (int nj = 0; nj < 8; ++nj)
            #pragma unroll
            for (int cc = 0; cc < 4; ++cc) acc[mi][nj][cc] = 0.0f;

    int pc = tid & 31;        // producer channel
    int prb = tid >> 5;       // producer row base (0..15)

    // ---- fill stage for chunk kt: B via cp.async, A via sampling ----
    #define FILL(ktv) do { \
        int _kt = (ktv); \
        int _s = _kt & 1; \
        int _layer = _kt >> 3; \
        int _c0 = (_kt & 7) * 32; \
        uint32_t _bsm = smb + (uint32_t)((2 * ASZ + _s * BSZ) * 4); \
        _Pragma("unroll") \
        for (int _i = 0; _i < 4; ++_i) { \
            int _idx = tid + _i * 512; \
            int _row = _idx >> 3, _q4 = _idx & 7; \
            cp16(_bsm + (uint32_t)((_row * SM_ROW + _q4 * 4) * 4), \
                 g_wperm + (size_t)_row * NK + _layer * 256 + _c0 + _q4 * 4); \
        } \
        asm volatile("cp.async.commit_group;" ::: "memory"); \
        float* _As = smf + _s * ASZ; \
        const float* _Ic = Ibase + _c0 + pc; \
        const int2* _tpl = staps + _layer * 2048; \
        _Pragma("unroll") \
        for (int _r = 0; _r < 8; ++_r) { \
            int _row = prb + 16 * _r; \
            const int2* _tp = _tpl + _row * 16; \
            float _v = 0.0f; \
            _Pragma("unroll") \
            for (int _t = 0; _t < 16; ++_t) { \
                int2 _tw = _tp[_t]; \
                _v = fmaf(_Ic[(size_t)_tw.x * NUM_C], __int_as_float(_tw.y), _v); \
            } \
            _As[_row * SM_ROW + pc] = tf32r(_v); \
        } \
    } while (0)

    FILL(0);

    for (int kt = 0; kt < NKT; ++kt) {
        asm volatile("cp.async.wait_group 0;" ::: "memory");
        __syncthreads();
        if (kt + 1 < NKT) FILL(kt + 1);

        const float* As = smf + (kt & 1) * ASZ;
        const float* Bs = smf + 2 * ASZ + (kt & 1) * BSZ;
        #pragma unroll
        for (int ks = 0; ks < 4; ++ks) {
            int kk = ks * 8 + tg;
            uint32_t a[2][4];
            #pragma unroll
            for (int mi = 0; mi < 2; ++mi) {
                int mr = wm * 32 + mi * 16 + g;
                a[mi][0] = __float_as_uint(As[mr * SM_ROW + kk]);
                a[mi][1] = __float_as_uint(As[(mr + 8) * SM_ROW + kk]);
                a[mi][2] = __float_as_uint(As[mr * SM_ROW + kk + 4]);
                a[mi][3] = __float_as_uint(As[(mr + 8) * SM_ROW + kk + 4]);
            }
            #pragma unroll
            for (int nj = 0; nj < 8; ++nj) {
                int nr = wn * 64 + nj * 8 + g;
                uint32_t b0 = __float_as_uint(Bs[nr * SM_ROW + kk]);
                uint32_t b1 = __float_as_uint(Bs[nr * SM_ROW + kk + 4]);
                mma_tf32(acc[0][nj], a[0][0], a[0][1], a[0][2], a[0][3], b0, b1);
                mma_tf32(acc[1][nj], a[1][0], a[1][1], a[1][2], a[1][3], b0, b1);
            }
        }
        __syncthreads();
    }

    // Epilogue: out[b][n][q] = relu(acc + bc[n])
    #pragma unroll
    for (int mi = 0; mi < 2; ++mi) {
        int r0 = m0 + wm * 32 + mi * 16 + g;
        #pragma unroll
        for (int half = 0; half < 2; ++half) {
            int m = r0 + half * 8;
            int q = m & (NQ - 1);
            float* ob = out + (size_t)b * NUM_C * NQ + q;
            #pragma unroll
            for (int nj = 0; nj < 8; ++nj) {
                int n = wn * 64 + nj * 8 + tg * 2;
                float v0 = acc[mi][nj][half * 2 + 0] + __ldg(bc + n);
                float v1 = acc[mi][nj][half * 2 + 1] + __ldg(bc + n + 1);
                ob[(size_t)n * NQ] = fmaxf(v0, 0.0f);
                ob[(size_t)(n + 1) * NQ] = fmaxf(v1, 0.0f);
            }
        }
    }
}

extern "C" void kernel_launch(void* const* d_in, const int* in_sizes, int n_in,
                              void* d_out, int out_size) {
    const float* feature = (const float*)d_in[0];  // (2,256,96,320)
    const float* calib   = (const float*)d_in[1];  // (2,3,4)
    const float* grid    = (const float*)d_in[2];  // (128,128,3)
    const float* Wc      = (const float*)d_in[3];  // (256,1280)
    const float* bc      = (const float*)d_in[4];  // (256,)
    float* out = (float*)d_out;                    // (2,256,128,128)

    cudaFuncSetAttribute(k_fused, cudaFuncAttributeMaxDynamicSharedMemorySize, FSM_BYTES);

    k_rowcum<<<NROWS / 8, 256>>>(feature);
    {
        dim3 g(IMG_W / 32, NUM_C / 32, NUM_B);
        dim3 blk(32, 32);
        k_colcum_t<<<g, blk>>>();
    }
    k_boxes<<<(NBOX + 255) / 256, 256>>>(calib, grid);
    k_wperm<<<(NUM_C * NK + 255) / 256, 256>>>(Wc);
    k_fused<<<NM / 128, 512, FSM_BYTES>>>(bc, out);
}

// round 5
// speedup vs baseline: 1.4152x; 1.4152x over previous
#include <cuda_runtime.h>
#include <math.h>
#include <stdint.h>

// Problem constants
#define NUM_B 2
#define NUM_C 256
#define IMG_H 96
#define IMG_W 320
#define NLAYER 5
#define NQ (128 * 128)           // 16384
#define NM (NUM_B * NQ)          // 32768
#define NK (NUM_C * NLAYER)      // 1280
#define HW (IMG_H * IMG_W)       // 30720
#define NROWS (NUM_B * NUM_C * IMG_H)     // 49152
#define NBOX (NUM_B * NLAYER * NQ)        // 163840

// Scratch (device globals: allocation-free per harness rules)
__device__ float  g_rowcum[NUM_B * NUM_C * IMG_H * IMG_W];     // 63MB
__device__ float  g_itrans[NUM_B * IMG_H * IMG_W * NUM_C];     // 63MB, [b][y][x][c]
__device__ float  g_vox[NM * NK];                              // 168MB, [m][K-permuted], tf32
__device__ float  g_wperm[NUM_C * NK];                         // 1.3MB, [co][K-permuted], tf32
__device__ float  g_bpa[NBOX];                                 // visible ? 1/area : 0
__device__ int2   g_tap[NBOX * 16];                            // {pixel idx, weight bits}

__device__ __forceinline__ float tf32r(float v) {
    uint32_t o;
    asm("cvt.rna.tf32.f32 %0, %1;" : "=r"(o) : "f"(v));
    return __uint_as_float(o);
}
__device__ __forceinline__ uint32_t smem_u32(const void* p) {
    uint32_t a;
    asm("{ .reg .u64 t; cvta.to.shared.u64 t, %1; cvt.u32.u64 %0, t; }" : "=r"(a) : "l"(p));
    return a;
}
__device__ __forceinline__ void cp16(uint32_t saddr, const void* gptr) {
    asm volatile("cp.async.cg.shared.global [%0], [%1], 16;" :: "r"(saddr), "l"(gptr) : "memory");
}
__device__ __forceinline__ void mma_tf32(float c[4], uint32_t a0, uint32_t a1, uint32_t a2,
                                         uint32_t a3, uint32_t b0, uint32_t b1) {
    asm volatile(
        "mma.sync.aligned.m16n8k8.row.col.f32.tf32.tf32.f32 "
        "{%0,%1,%2,%3}, {%4,%5,%6,%7}, {%8,%9}, {%0,%1,%2,%3};"
        : "+f"(c[0]), "+f"(c[1]), "+f"(c[2]), "+f"(c[3])
        : "r"(a0), "r"(a1), "r"(a2), "r"(a3), "r"(b0), "r"(b1));
}

// ---------------- K1: row cumsum, warp-per-row shfl scan ----------------
__global__ void k_rowcum(const float* __restrict__ feat) {
    int w = (blockIdx.x * blockDim.x + threadIdx.x) >> 5;
    int lane = threadIdx.x & 31;
    if (w >= NROWS) return;
    const float* src = feat + (size_t)w * IMG_W;
    float* dst = g_rowcum + (size_t)w * IMG_W;
    float carry = 0.0f;
    #pragma unroll
    for (int c0 = 0; c0 < IMG_W; c0 += 32) {
        float v = src[c0 + lane];
        #pragma unroll
        for (int d = 1; d < 32; d <<= 1) {
            float n = __shfl_up_sync(0xFFFFFFFFu, v, d);
            if (lane >= d) v += n;
        }
        v += carry;
        dst[c0 + lane] = v;
        carry = __shfl_sync(0xFFFFFFFFu, v, 31);
    }
}

// ---------------- K2: column cumsum + transpose to [b][y][x][c], tiled ----------------
__global__ void k_colcum_t() {
    __shared__ float tile[32][33];
    int x0 = blockIdx.x * 32;
    int c0 = blockIdx.y * 32;
    int b  = blockIdx.z;
    int tx = threadIdx.x, ty = threadIdx.y;
    const float* src = g_rowcum + ((size_t)(b * NUM_C + c0 + ty) * IMG_H) * IMG_W + x0 + tx;
    float* dstbase = g_itrans + (size_t)b * HW * NUM_C;
    float acc = 0.0f;
    for (int y = 0; y < IMG_H; ++y) {
        acc += src[(size_t)y * IMG_W];
        tile[ty][tx] = acc;
        __syncthreads();
        dstbase[((size_t)y * IMG_W + x0 + ty) * NUM_C + c0 + tx] = tile[tx][ty];
        __syncthreads();
    }
}

// ---------------- K3: project corners -> per-box tap table (always written) ----------------
__global__ void k_boxes(const float* __restrict__ calib, const float* __restrict__ grid) {
    int i = blockIdx.x * blockDim.x + threadIdx.x;
    if (i >= NBOX) return;
    int q = i % NQ;
    int layer = (i / NQ) % NLAYER;
    int b = i / (NQ * NLAYER);

    float gx = grid[q * 3 + 0];
    float gy = grid[q * 3 + 1];
    float gz = grid[q * 3 + 2] + 32.0f * (float)layer;

    const float* M = calib + b * 12;
    float m00 = M[0], m01 = M[1], m02 = M[2],  m03 = M[3];
    float m10 = M[4], m11 = M[5], m12 = M[6],  m13 = M[7];
    float m20 = M[8], m21 = M[9], m22 = M[10], m23 = M[11];

    const float ox[8] = {-12.5f, 12.5f, 12.5f, -12.5f, -12.5f, 12.5f, 12.5f, -12.5f};
    const float oy[8] = {-12.5f, -12.5f, 12.5f, 12.5f, -12.5f, -12.5f, 12.5f, 12.5f};
    const float oz[8] = {0.0f, 0.0f, 0.0f, 0.0f, 32.0f, 32.0f, 32.0f, 32.0f};

    float mnx = 1e30f, mny = 1e30f, mxx = -1e30f, mxy = -1e30f;
    #pragma unroll
    for (int k = 0; k < 8; ++k) {
        float X = gx + ox[k];
        float Y = gy + oy[k];
        float Z = gz + oz[k];
        float px = m00 * X + m01 * Y + m02 * Z + m03;
        float py = m10 * X + m11 * Y + m12 * Z + m13;
        float pz = m20 * X + m21 * Y + m22 * Z + m23;
        float zc = fmaxf(pz, 1e-6f);
        float ix = px / zc;
        float iy = py / zc;
        float nx = fminf(fmaxf(2.0f * ix / 320.0f - 1.0f, -1.0f), 0.95f);
        float ny = fminf(fmaxf(2.0f * iy / 96.0f - 1.0f, -1.0f), 0.95f);
        mnx = fminf(mnx, nx);
        mny = fminf(mny, ny);
        mxx = fmaxf(mxx, nx);
        mxy = fmaxf(mxy, ny);
    }

    float area = ((mxx - mnx) * (mxy - mny)) * (float)HW + 1e-6f;
    bool visible = (area > 1e-6f) && (area < (float)HW * 0.3f);
    float inv = visible ? (1.0f / area) : 0.0f;
    g_bpa[i] = inv;

    float xs[2], ys[2];
    xs[0] = ((mnx + 1.0f) * 320.0f - 1.0f) * 0.5f;
    xs[1] = ((mxx + 1.0f) * 320.0f - 1.0f) * 0.5f;
    ys[0] = ((mny + 1.0f) * 96.0f - 1.0f) * 0.5f;
    ys[1] = ((mxy + 1.0f) * 96.0f - 1.0f) * 0.5f;

    // corners: lt(min,min,+), rb(max,max,+), rt(max,min,-), lb(min,max,-)
    const int cxi[4] = {0, 1, 1, 0};
    const int cyi[4] = {0, 1, 0, 1};
    const float csg[4] = {1.0f, 1.0f, -1.0f, -1.0f};
    int2* tp = g_tap + (size_t)i * 16;
    #pragma unroll
    for (int cc = 0; cc < 4; ++cc) {
        float sx = xs[cxi[cc]], sy = ys[cyi[cc]];
        float fx = floorf(sx), fy = floorf(sy);
        int x0 = (int)fx, y0 = (int)fy;
        float wx1 = sx - fx, wy1 = sy - fy;
        float wx0 = 1.0f - wx1, wy0 = 1.0f - wy1;
        float s = csg[cc] * inv;
        #pragma unroll
        for (int tt = 0; tt < 4; ++tt) {
            int xi = x0 + (tt & 1);
            int yi = y0 + (tt >> 1);
            float w = ((tt & 1) ? wx1 : wx0) * ((tt >> 1) ? wy1 : wy0) * s;
            bool valid = visible && ((unsigned)xi < (unsigned)IMG_W) && ((unsigned)yi < (unsigned)IMG_H);
            int idx = valid ? (yi * IMG_W + xi) : 0;
            if (!valid) w = 0.0f;
            tp[cc * 4 + tt] = make_int2(idx, __float_as_int(w));
        }
    }
}

// K-permutation within each 8-group: store order [0,4,1,5,2,6,3,7]
__device__ __forceinline__ int kperm(int c) {
    int t = c & 7;
    return (c & ~7) + ((t & 3) * 2 + (t >> 2));
}

// ---------------- K4: box-filter sampling -> vox (tf32, K-permuted) ----------------
__global__ __launch_bounds__(256) void k_sample() {
    __shared__ int2 st[NLAYER][16];
    __shared__ float sinv[NLAYER];
    int m = blockIdx.x;
    int b = m >> 14;
    int q = m & (NQ - 1);
    int tid = threadIdx.x;
    if (tid < NLAYER * 16) {
        int layer = tid >> 4, t = tid & 15;
        st[layer][t] = g_tap[((size_t)((b * NLAYER + layer) * NQ + q)) * 16 + t];
    } else if (tid >= 128 && tid < 128 + NLAYER) {
        sinv[tid - 128] = g_bpa[(size_t)(b * NLAYER + (tid - 128)) * NQ + q];
    }
    __syncthreads();

    const float* I = g_itrans + (size_t)b * HW * NUM_C + tid;
    int wpos = kperm(tid);
    float* vdst = g_vox + (size_t)m * NK;

    #pragma unroll
    for (int layer = 0; layer < NLAYER; ++layer) {
        float v = 0.0f;
        if (sinv[layer] != 0.0f) {
            float s0 = 0.0f, s1 = 0.0f, s2 = 0.0f, s3 = 0.0f;
            #pragma unroll
            for (int t = 0; t < 4; ++t) {
                int2 w0 = st[layer][t];
                int2 w1 = st[layer][4 + t];
                int2 w2 = st[layer][8 + t];
                int2 w3 = st[layer][12 + t];
                s0 = fmaf(I[(size_t)w0.x * NUM_C], __int_as_float(w0.y), s0);
                s1 = fmaf(I[(size_t)w1.x * NUM_C], __int_as_float(w1.y), s1);
                s2 = fmaf(I[(size_t)w2.x * NUM_C], __int_as_float(w2.y), s2);
                s3 = fmaf(I[(size_t)w3.x * NUM_C], __int_as_float(w3.y), s3);
            }
            v = (s0 + s1) + (s2 + s3);
        }
        vdst[layer * NUM_C + wpos] = tf32r(v);
    }
}

// ---------------- K5: permute Wc to K-order (layer*256 + kperm(c)), tf32 ----------------
__global__ void k_wperm(const float* __restrict__ Wc) {
    int idx = blockIdx.x * blockDim.x + threadIdx.x;
    if (idx >= NUM_C * NK) return;
    int co = idx / NK;
    int kd = idx % NK;
    int layer = kd / NUM_C;
    int c = kd % NUM_C;
    g_wperm[(size_t)co * NK + layer * NUM_C + kperm(c)] = tf32r(Wc[co * NK + c * NLAYER + layer]);
}

// ---------------- K6: mma.sync tf32 GEMM (CTA 128Mx256N, warp 64x64) + bias + relu ----------
// 256 threads = 8 warps as 2(M) x 4(N). K-chunk 32, double-buffered cp.async.
// Smem in float2 (k-pairs): row stride 20 float2 (160B) -> conflict-free LDS.64.
#define SROW2 20
#define ASZ2 (128 * SROW2)          // 2560 float2
#define BSZ2 (256 * SROW2)          // 5120 float2
#define STG2 (ASZ2 + BSZ2)          // 7680 float2 per stage
#define GSM_BYTES (2 * STG2 * 8)    // 122880 bytes
#define NKT (NK / 32)               // 40

__global__ __launch_bounds__(256, 1) void k_gemm(const float* __restrict__ bc,
                                                 float* __restrict__ out) {
    extern __shared__ float2 sm2[];
    uint32_t smb = smem_u32(sm2);
    int tid = threadIdx.x;
    int wid = tid >> 5;
    int lane = tid & 31;
    int g = lane >> 2;
    int tg = lane & 3;
    int wm = wid & 1;          // M warp (0..1)
    int wn = wid >> 1;         // N warp (0..3)
    int m0 = blockIdx.x * 128;

    float acc[4][8][4];
    #pragma unroll
    for (int ms = 0; ms < 4; ++ms)
        #pragma unroll
        for (int nj = 0; nj < 8; ++nj)
            #pragma unroll
            for (int cc = 0; cc < 4; ++cc) acc[ms][nj][cc] = 0.0f;

    // ---- stage fill via cp.async ----
    #define FILL(ktv) do { \
        int _kt = (ktv); \
        uint32_t _ab = smb + (uint32_t)(((_kt & 1) * STG2) * 8); \
        uint32_t _bb = _ab + (uint32_t)(ASZ2 * 8); \
        int _ko = _kt * 32; \
        _Pragma("unroll") \
        for (int _i = 0; _i < 4; ++_i) { \
            int _idx = tid + _i * 256; \
            int _row = _idx >> 3, _q = _idx & 7; \
            cp16(_ab + (uint32_t)(_row * (SROW2 * 8) + _q * 16), \
                 g_vox + (size_t)(m0 + _row) * NK + _ko + _q * 4); \
        } \
        _Pragma("unroll") \
        for (int _i = 0; _i < 8; ++_i) { \
            int _idx = tid + _i * 256; \
            int _row = _idx >> 3, _q = _idx & 7; \
            cp16(_bb + (uint32_t)(_row * (SROW2 * 8) + _q * 16), \
                 g_wperm + (size_t)_row * NK + _ko + _q * 4); \
        } \
        asm volatile("cp.async.commit_group;" ::: "memory"); \
    } while (0)

    FILL(0);

    for (int kt = 0; kt < NKT; ++kt) {
        if (kt + 1 < NKT) {
            FILL(kt + 1);
            asm volatile("cp.async.wait_group 1;" ::: "memory");
        } else {
            asm volatile("cp.async.wait_group 0;" ::: "memory");
        }
        __syncthreads();

        const float2* Ap = sm2 + (kt & 1) * STG2;
        const float2* Bp = Ap + ASZ2;
        #pragma unroll
        for (int ks = 0; ks < 4; ++ks) {
            int kp = ks * 4 + tg;
            float2 alo[4], ahi[4];
            #pragma unroll
            for (int ms = 0; ms < 4; ++ms) {
                int r = wm * 64 + ms * 16 + g;
                alo[ms] = Ap[r * SROW2 + kp];
                ahi[ms] = Ap[(r + 8) * SROW2 + kp];
            }
            #pragma unroll
            for (int nj = 0; nj < 8; ++nj) {
                float2 bb = Bp[(wn * 64 + nj * 8 + g) * SROW2 + kp];
                uint32_t b0 = __float_as_uint(bb.x);
                uint32_t b1 = __float_as_uint(bb.y);
                #pragma unroll
                for (int ms = 0; ms < 4; ++ms)
                    mma_tf32(acc[ms][nj],
                             __float_as_uint(alo[ms].x), __float_as_uint(ahi[ms].x),
                             __float_as_uint(alo[ms].y), __float_as_uint(ahi[ms].y),
                             b0, b1);
            }
        }
        __syncthreads();
    }

    // Epilogue: out[b][n][q] = relu(acc + bc[n])
    int b = m0 >> 14;
    #pragma unroll
    for (int ms = 0; ms < 4; ++ms) {
        int r0 = m0 + wm * 64 + ms * 16 + g;
        #pragma unroll
        for (int half = 0; half < 2; ++half) {
            int m = r0 + half * 8;
            int q = m & (NQ - 1);
            float* ob = out + (size_t)b * NUM_C * NQ + q;
            #pragma unroll
            for (int nj = 0; nj < 8; ++nj) {
                int n = wn * 64 + nj * 8 + tg * 2;
                float v0 = acc[ms][nj][half * 2 + 0] + __ldg(bc + n);
                float v1 = acc[ms][nj][half * 2 + 1] + __ldg(bc + n + 1);
                ob[(size_t)n * NQ] = fmaxf(v0, 0.0f);
                ob[(size_t)(n + 1) * NQ] = fmaxf(v1, 0.0f);
            }
        }
    }
}

extern "C" void kernel_launch(void* const* d_in, const int* in_sizes, int n_in,
                              void* d_out, int out_size) {
    const float* feature = (const float*)d_in[0];  // (2,256,96,320)
    const float* calib   = (const float*)d_in[1];  // (2,3,4)
    const float* grid    = (const float*)d_in[2];  // (128,128,3)
    const float* Wc      = (const float*)d_in[3];  // (256,1280)
    const float* bc      = (const float*)d_in[4];  // (256,)
    float* out = (float*)d_out;                    // (2,256,128,128)

    cudaFuncSetAttribute(k_gemm, cudaFuncAttributeMaxDynamicSharedMemorySize, GSM_BYTES);

    k_rowcum<<<NROWS / 8, 256>>>(feature);
    {
        dim3 g(IMG_W / 32, NUM_C / 32, NUM_B);
        dim3 blk(32, 32);
        k_colcum_t<<<g, blk>>>();
    }
    k_boxes<<<(NBOX + 255) / 256, 256>>>(calib, grid);
    k_sample<<<NM, 256>>>();
    k_wperm<<<(NUM_C * NK + 255) / 256, 256>>>(Wc);
    k_gemm<<<NM / 128, 256, GSM_BYTES>>>(bc, out);
}

// round 6
// speedup vs baseline: 1.4181x; 1.0021x over previous
#include <cuda_runtime.h>
#include <math.h>
#include <stdint.h>

// Problem constants
#define NUM_B 2
#define NUM_C 256
#define IMG_H 96
#define IMG_W 320
#define NLAYER 5
#define NQ (128 * 128)           // 16384
#define NM (NUM_B * NQ)          // 32768
#define NK (NUM_C * NLAYER)      // 1280
#define HW (IMG_H * IMG_W)       // 30720
#define NROWS (NUM_B * NUM_C * IMG_H)     // 49152
#define NBOX (NUM_B * NLAYER * NQ)        // 163840

// Scratch (device globals: allocation-free per harness rules)
__device__ float  g_rowcum[NUM_B * NUM_C * IMG_H * IMG_W];     // 63MB
__device__ float  g_itrans[NUM_B * IMG_H * IMG_W * NUM_C];     // 63MB, [b][y][x][c]
__device__ float  g_vox[NM * NK];                              // 168MB, [m][K-permuted], tf32
__device__ float  g_wperm[NUM_C * NK];                         // 1.3MB, [co][K-permuted], tf32
__device__ float  g_bpa[NBOX];                                 // visible ? 1/area : 0
__device__ int2   g_tap[NBOX * 16];                            // {pixel idx, weight bits}

__device__ __forceinline__ float tf32r(float v) {
    uint32_t o;
    asm("cvt.rna.tf32.f32 %0, %1;" : "=r"(o) : "f"(v));
    return __uint_as_float(o);
}
__device__ __forceinline__ uint32_t smem_u32(const void* p) {
    uint32_t a;
    asm("{ .reg .u64 t; cvta.to.shared.u64 t, %1; cvt.u32.u64 %0, t; }" : "=r"(a) : "l"(p));
    return a;
}
__device__ __forceinline__ void cp16(uint32_t saddr, const void* gptr) {
    asm volatile("cp.async.cg.shared.global [%0], [%1], 16;" :: "r"(saddr), "l"(gptr) : "memory");
}
__device__ __forceinline__ void mma_tf32(float c[4], uint32_t a0, uint32_t a1, uint32_t a2,
                                         uint32_t a3, uint32_t b0, uint32_t b1) {
    asm volatile(
        "mma.sync.aligned.m16n8k8.row.col.f32.tf32.tf32.f32 "
        "{%0,%1,%2,%3}, {%4,%5,%6,%7}, {%8,%9}, {%0,%1,%2,%3};"
        : "+f"(c[0]), "+f"(c[1]), "+f"(c[2]), "+f"(c[3])
        : "r"(a0), "r"(a1), "r"(a2), "r"(a3), "r"(b0), "r"(b1));
}

// ---------------- K1: row cumsum, warp-per-row shfl scan ----------------
__global__ void k_rowcum(const float* __restrict__ feat) {
    int w = (blockIdx.x * blockDim.x + threadIdx.x) >> 5;
    int lane = threadIdx.x & 31;
    if (w >= NROWS) return;
    const float* src = feat + (size_t)w * IMG_W;
    float* dst = g_rowcum + (size_t)w * IMG_W;
    float carry = 0.0f;
    #pragma unroll
    for (int c0 = 0; c0 < IMG_W; c0 += 32) {
        float v = src[c0 + lane];
        #pragma unroll
        for (int d = 1; d < 32; d <<= 1) {
            float n = __shfl_up_sync(0xFFFFFFFFu, v, d);
            if (lane >= d) v += n;
        }
        v += carry;
        dst[c0 + lane] = v;
        carry = __shfl_sync(0xFFFFFFFFu, v, 31);
    }
}

// ---------------- K2: column cumsum + transpose to [b][y][x][c], tiled ----------------
__global__ void k_colcum_t() {
    __shared__ float tile[32][33];
    int x0 = blockIdx.x * 32;
    int c0 = blockIdx.y * 32;
    int b  = blockIdx.z;
    int tx = threadIdx.x, ty = threadIdx.y;
    const float* src = g_rowcum + ((size_t)(b * NUM_C + c0 + ty) * IMG_H) * IMG_W + x0 + tx;
    float* dstbase = g_itrans + (size_t)b * HW * NUM_C;
    float acc = 0.0f;
    for (int y = 0; y < IMG_H; ++y) {
        acc += src[(size_t)y * IMG_W];
        tile[ty][tx] = acc;
        __syncthreads();
        dstbase[((size_t)y * IMG_W + x0 + ty) * NUM_C + c0 + tx] = tile[tx][ty];
        __syncthreads();
    }
}

// ---------------- K3: project corners -> per-box tap table (always written) ----------------
__global__ void k_boxes(const float* __restrict__ calib, const float* __restrict__ grid) {
    int i = blockIdx.x * blockDim.x + threadIdx.x;
    if (i >= NBOX) return;
    int q = i % NQ;
    int layer = (i / NQ) % NLAYER;
    int b = i / (NQ * NLAYER);

    float gx = grid[q * 3 + 0];
    float gy = grid[q * 3 + 1];
    float gz = grid[q * 3 + 2] + 32.0f * (float)layer;

    const float* M = calib + b * 12;
    float m00 = M[0], m01 = M[1], m02 = M[2],  m03 = M[3];
    float m10 = M[4], m11 = M[5], m12 = M[6],  m13 = M[7];
    float m20 = M[8], m21 = M[9], m22 = M[10], m23 = M[11];

    const float ox[8] = {-12.5f, 12.5f, 12.5f, -12.5f, -12.5f, 12.5f, 12.5f, -12.5f};
    const float oy[8] = {-12.5f, -12.5f, 12.5f, 12.5f, -12.5f, -12.5f, 12.5f, 12.5f};
    const float oz[8] = {0.0f, 0.0f, 0.0f, 0.0f, 32.0f, 32.0f, 32.0f, 32.0f};

    float mnx = 1e30f, mny = 1e30f, mxx = -1e30f, mxy = -1e30f;
    #pragma unroll
    for (int k = 0; k < 8; ++k) {
        float X = gx + ox[k];
        float Y = gy + oy[k];
        float Z = gz + oz[k];
        float px = m00 * X + m01 * Y + m02 * Z + m03;
        float py = m10 * X + m11 * Y + m12 * Z + m13;
        float pz = m20 * X + m21 * Y + m22 * Z + m23;
        float zc = fmaxf(pz, 1e-6f);
        float ix = px / zc;
        float iy = py / zc;
        float nx = fminf(fmaxf(2.0f * ix / 320.0f - 1.0f, -1.0f), 0.95f);
        float ny = fminf(fmaxf(2.0f * iy / 96.0f - 1.0f, -1.0f), 0.95f);
        mnx = fminf(mnx, nx);
        mny = fminf(mny, ny);
        mxx = fmaxf(mxx, nx);
        mxy = fmaxf(mxy, ny);
    }

    float area = ((mxx - mnx) * (mxy - mny)) * (float)HW + 1e-6f;
    bool visible = (area > 1e-6f) && (area < (float)HW * 0.3f);
    float inv = visible ? (1.0f / area) : 0.0f;
    g_bpa[i] = inv;

    float xs[2], ys[2];
    xs[0] = ((mnx + 1.0f) * 320.0f - 1.0f) * 0.5f;
    xs[1] = ((mxx + 1.0f) * 320.0f - 1.0f) * 0.5f;
    ys[0] = ((mny + 1.0f) * 96.0f - 1.0f) * 0.5f;
    ys[1] = ((mxy + 1.0f) * 96.0f - 1.0f) * 0.5f;

    // corners: lt(min,min,+), rb(max,max,+), rt(max,min,-), lb(min,max,-)
    const int cxi[4] = {0, 1, 1, 0};
    const int cyi[4] = {0, 1, 0, 1};
    const float csg[4] = {1.0f, 1.0f, -1.0f, -1.0f};
    int2* tp = g_tap + (size_t)i * 16;
    #pragma unroll
    for (int cc = 0; cc < 4; ++cc) {
        float sx = xs[cxi[cc]], sy = ys[cyi[cc]];
        float fx = floorf(sx), fy = floorf(sy);
        int x0 = (int)fx, y0 = (int)fy;
        float wx1 = sx - fx, wy1 = sy - fy;
        float wx0 = 1.0f - wx1, wy0 = 1.0f - wy1;
        float s = csg[cc] * inv;
        #pragma unroll
        for (int tt = 0; tt < 4; ++tt) {
            int xi = x0 + (tt & 1);
            int yi = y0 + (tt >> 1);
            float w = ((tt & 1) ? wx1 : wx0) * ((tt >> 1) ? wy1 : wy0) * s;
            bool valid = visible && ((unsigned)xi < (unsigned)IMG_W) && ((unsigned)yi < (unsigned)IMG_H);
            int idx = valid ? (yi * IMG_W + xi) : 0;
            if (!valid) w = 0.0f;
            tp[cc * 4 + tt] = make_int2(idx, __float_as_int(w));
        }
    }
}

// K-permutation within each 8-group: store order [0,4,1,5,2,6,3,7]
__device__ __forceinline__ int kperm(int c) {
    int t = c & 7;
    return (c & ~7) + ((t & 3) * 2 + (t >> 2));
}

// ---------------- K4: box-filter sampling -> vox (tf32, K-permuted) ----------------
__global__ __launch_bounds__(256) void k_sample() {
    __shared__ int2 st[NLAYER][16];
    __shared__ float sinv[NLAYER];
    int m = blockIdx.x;
    int b = m >> 14;
    int q = m & (NQ - 1);
    int tid = threadIdx.x;
    if (tid < NLAYER * 16) {
        int layer = tid >> 4, t = tid & 15;
        st[layer][t] = g_tap[((size_t)((b * NLAYER + layer) * NQ + q)) * 16 + t];
    } else if (tid >= 128 && tid < 128 + NLAYER) {
        sinv[tid - 128] = g_bpa[(size_t)(b * NLAYER + (tid - 128)) * NQ + q];
    }
    __syncthreads();

    const float* I = g_itrans + (size_t)b * HW * NUM_C + tid;
    int wpos = kperm(tid);
    float* vdst = g_vox + (size_t)m * NK;

    #pragma unroll
    for (int layer = 0; layer < NLAYER; ++layer) {
        float v = 0.0f;
        if (sinv[layer] != 0.0f) {
            float s0 = 0.0f, s1 = 0.0f, s2 = 0.0f, s3 = 0.0f;
            #pragma unroll
            for (int t = 0; t < 4; ++t) {
                int2 w0 = st[layer][t];
                int2 w1 = st[layer][4 + t];
                int2 w2 = st[layer][8 + t];
                int2 w3 = st[layer][12 + t];
                s0 = fmaf(I[(size_t)w0.x * NUM_C], __int_as_float(w0.y), s0);
                s1 = fmaf(I[(size_t)w1.x * NUM_C], __int_as_float(w1.y), s1);
                s2 = fmaf(I[(size_t)w2.x * NUM_C], __int_as_float(w2.y), s2);
                s3 = fmaf(I[(size_t)w3.x * NUM_C], __int_as_float(w3.y), s3);
            }
            v = (s0 + s1) + (s2 + s3);
        }
        vdst[layer * NUM_C + wpos] = tf32r(v);
    }
}

// ---------------- K5: permute Wc to K-order (layer*256 + kperm(c)), tf32 ----------------
__global__ void k_wperm(const float* __restrict__ Wc) {
    int idx = blockIdx.x * blockDim.x + threadIdx.x;
    if (idx >= NUM_C * NK) return;
    int co = idx / NK;
    int kd = idx % NK;
    int layer = kd / NUM_C;
    int c = kd % NUM_C;
    g_wperm[(size_t)co * NK + layer * NUM_C + kperm(c)] = tf32r(Wc[co * NK + c * NLAYER + layer]);
}

// ---------------- K6: mma.sync tf32 GEMM (CTA 128Mx256N, 16 warps 4Mx4N, warp 32x64) ------
// 512 threads. K-chunk 32, double-buffered cp.async.
// Smem float2 (k-pairs): row stride 20 float2 (160B) -> conflict-free LDS.64 per phase.
#define SROW2 20
#define ASZ2 (128 * SROW2)          // 2560 float2
#define BSZ2 (256 * SROW2)          // 5120 float2
#define STG2 (ASZ2 + BSZ2)          // 7680 float2 per stage
#define GSM_BYTES (2 * STG2 * 8)    // 122880 bytes
#define NKT (NK / 32)               // 40

__global__ __launch_bounds__(512, 1) void k_gemm(const float* __restrict__ bc,
                                                 float* __restrict__ out) {
    extern __shared__ float2 sm2[];
    uint32_t smb = smem_u32(sm2);
    int tid = threadIdx.x;
    int wid = tid >> 5;
    int lane = tid & 31;
    int g = lane >> 2;
    int tg = lane & 3;
    int wm = wid & 3;          // M warp (0..3) -> 32-row strip
    int wn = wid >> 2;         // N warp (0..3) -> 64-col strip
    int m0 = blockIdx.x * 128;

    float acc[2][8][4];
    #pragma unroll
    for (int ms = 0; ms < 2; ++ms)
        #pragma unroll
        for (int nj = 0; nj < 8; ++nj)
            #pragma unroll
            for (int cc = 0; cc < 4; ++cc) acc[ms][nj][cc] = 0.0f;

    // ---- stage fill via cp.async (512 threads: A 2 ops, B 4 ops each) ----
    #define FILL(ktv) do { \
        int _kt = (ktv); \
        uint32_t _ab = smb + (uint32_t)(((_kt & 1) * STG2) * 8); \
        uint32_t _bb = _ab + (uint32_t)(ASZ2 * 8); \
        int _ko = _kt * 32; \
        _Pragma("unroll") \
        for (int _i = 0; _i < 2; ++_i) { \
            int _idx = tid + _i * 512; \
            int _row = _idx >> 3, _q = _idx & 7; \
            cp16(_ab + (uint32_t)(_row * (SROW2 * 8) + _q * 16), \
                 g_vox + (size_t)(m0 + _row) * NK + _ko + _q * 4); \
        } \
        _Pragma("unroll") \
        for (int _i = 0; _i < 4; ++_i) { \
            int _idx = tid + _i * 512; \
            int _row = _idx >> 3, _q = _idx & 7; \
            cp16(_bb + (uint32_t)(_row * (SROW2 * 8) + _q * 16), \
                 g_wperm + (size_t)_row * NK + _ko + _q * 4); \
        } \
        asm volatile("cp.async.commit_group;" ::: "memory"); \
    } while (0)

    FILL(0);

    for (int kt = 0; kt < NKT; ++kt) {
        if (kt + 1 < NKT) {
            FILL(kt + 1);
            asm volatile("cp.async.wait_group 1;" ::: "memory");
        } else {
            asm volatile("cp.async.wait_group 0;" ::: "memory");
        }
        __syncthreads();

        const float2* Ap = sm2 + (kt & 1) * STG2;
        const float2* Bp = Ap + ASZ2;
        #pragma unroll
        for (int ks = 0; ks < 4; ++ks) {
            int kp = ks * 4 + tg;
            float2 alo[2], ahi[2];
            #pragma unroll
            for (int ms = 0; ms < 2; ++ms) {
                int r = wm * 32 + ms * 16 + g;
                alo[ms] = Ap[r * SROW2 + kp];
                ahi[ms] = Ap[(r + 8) * SROW2 + kp];
            }
            #pragma unroll
            for (int nj = 0; nj < 8; ++nj) {
                float2 bb = Bp[(wn * 64 + nj * 8 + g) * SROW2 + kp];
                uint32_t b0 = __float_as_uint(bb.x);
                uint32_t b1 = __float_as_uint(bb.y);
                #pragma unroll
                for (int ms = 0; ms < 2; ++ms)
                    mma_tf32(acc[ms][nj],
                             __float_as_uint(alo[ms].x), __float_as_uint(ahi[ms].x),
                             __float_as_uint(alo[ms].y), __float_as_uint(ahi[ms].y),
                             b0, b1);
            }
        }
        __syncthreads();
    }

    // Epilogue: out[b][n][q] = relu(acc + bc[n])
    int b = m0 >> 14;
    #pragma unroll
    for (int ms = 0; ms < 2; ++ms) {
        int r0 = m0 + wm * 32 + ms * 16 + g;
        #pragma unroll
        for (int half = 0; half < 2; ++half) {
            int m = r0 + half * 8;
            int q = m & (NQ - 1);
            float* ob = out + (size_t)b * NUM_C * NQ + q;
            #pragma unroll
            for (int nj = 0; nj < 8; ++nj) {
                int n = wn * 64 + nj * 8 + tg * 2;
                float v0 = acc[ms][nj][half * 2 + 0] + __ldg(bc + n);
                float v1 = acc[ms][nj][half * 2 + 1] + __ldg(bc + n + 1);
                ob[(size_t)n * NQ] = fmaxf(v0, 0.0f);
                ob[(size_t)(n + 1) * NQ] = fmaxf(v1, 0.0f);
            }
        }
    }
}

extern "C" void kernel_launch(void* const* d_in, const int* in_sizes, int n_in,
                              void* d_out, int out_size) {
    const float* feature = (const float*)d_in[0];  // (2,256,96,320)
    const float* calib   = (const float*)d_in[1];  // (2,3,4)
    const float* grid    = (const float*)d_in[2];  // (128,128,3)
    const float* Wc      = (const float*)d_in[3];  // (256,1280)
    const float* bc      = (const float*)d_in[4];  // (256,)
    float* out = (float*)d_out;                    // (2,256,128,128)

    cudaFuncSetAttribute(k_gemm, cudaFuncAttributeMaxDynamicSharedMemorySize, GSM_BYTES);

    k_rowcum<<<NROWS / 8, 256>>>(feature);
    {
        dim3 g(IMG_W / 32, NUM_C / 32, NUM_B);
        dim3 blk(32, 32);
        k_colcum_t<<<g, blk>>>();
    }
    k_boxes<<<(NBOX + 255) / 256, 256>>>(calib, grid);
    k_sample<<<NM, 256>>>();
    k_wperm<<<(NUM_C * NK + 255) / 256, 256>>>(Wc);
    k_gemm<<<NM / 128, 512, GSM_BYTES>>>(bc, out);
}

// round 7
// speedup vs baseline: 2.0665x; 1.4572x over previous
#include <cuda_runtime.h>
#include <cuda_fp16.h>
#include <math.h>
#include <stdint.h>

// Problem constants
#define NUM_B 2
#define NUM_C 256
#define IMG_H 96
#define IMG_W 320
#define NLAYER 5
#define NQ (128 * 128)           // 16384
#define NM (NUM_B * NQ)          // 32768
#define NK (NUM_C * NLAYER)      // 1280
#define HW (IMG_H * IMG_W)       // 30720
#define NROWS (NUM_B * NUM_C * IMG_H)     // 49152
#define NBOX (NUM_B * NLAYER * NQ)        // 163840

// Scratch (device globals: allocation-free per harness rules)
__device__ float  g_rowcum[NUM_B * NUM_C * IMG_H * IMG_W];     // 63MB
__device__ float  g_itrans[NUM_B * IMG_H * IMG_W * NUM_C];     // 63MB, [b][y][x][c]
__device__ __align__(256) __half g_vox[NM * NK];               // 84MB, [m][k] fp16
__device__ __align__(256) __half g_wperm[NUM_C * NK];          // 0.65MB, [co][k] fp16
__device__ float  g_bpa[NBOX];                                 // visible ? 1/area : 0
__device__ int2   g_tap[NBOX * 16];                            // {pixel idx, weight bits}

__device__ __forceinline__ uint32_t smem_u32(const void* p) {
    uint32_t a;
    asm("{ .reg .u64 t; cvta.to.shared.u64 t, %1; cvt.u32.u64 %0, t; }" : "=r"(a) : "l"(p));
    return a;
}
__device__ __forceinline__ void cp16(uint32_t saddr, const void* gptr) {
    asm volatile("cp.async.cg.shared.global [%0], [%1], 16;" :: "r"(saddr), "l"(gptr) : "memory");
}
#define LDSM4(r, a) \
    asm volatile("ldmatrix.sync.aligned.m8n8.x4.shared.b16 {%0,%1,%2,%3}, [%4];" \
                 : "=r"((r)[0]), "=r"((r)[1]), "=r"((r)[2]), "=r"((r)[3]) : "r"(a))
__device__ __forceinline__ void mma_f16(float c[4], const uint32_t a[4], uint32_t b0, uint32_t b1) {
    asm volatile(
        "mma.sync.aligned.m16n8k16.row.col.f32.f16.f16.f32 "
        "{%0,%1,%2,%3}, {%4,%5,%6,%7}, {%8,%9}, {%0,%1,%2,%3};"
        : "+f"(c[0]), "+f"(c[1]), "+f"(c[2]), "+f"(c[3])
        : "r"(a[0]), "r"(a[1]), "r"(a[2]), "r"(a[3]), "r"(b0), "r"(b1));
}

// ---------------- K1: row cumsum, warp-per-row shfl scan ----------------
__global__ void k_rowcum(const float* __restrict__ feat) {
    int w = (blockIdx.x * blockDim.x + threadIdx.x) >> 5;
    int lane = threadIdx.x & 31;
    if (w >= NROWS) return;
    const float* src = feat + (size_t)w * IMG_W;
    float* dst = g_rowcum + (size_t)w * IMG_W;
    float carry = 0.0f;
    #pragma unroll
    for (int c0 = 0; c0 < IMG_W; c0 += 32) {
        float v = src[c0 + lane];
        #pragma unroll
        for (int d = 1; d < 32; d <<= 1) {
            float n = __shfl_up_sync(0xFFFFFFFFu, v, d);
            if (lane >= d) v += n;
        }
        v += carry;
        dst[c0 + lane] = v;
        carry = __shfl_sync(0xFFFFFFFFu, v, 31);
    }
}

// ---------------- K2: column cumsum + transpose to [b][y][x][c], tiled ----------------
__global__ void k_colcum_t() {
    __shared__ float tile[32][33];
    int x0 = blockIdx.x * 32;
    int c0 = blockIdx.y * 32;
    int b  = blockIdx.z;
    int tx = threadIdx.x, ty = threadIdx.y;
    const float* src = g_rowcum + ((size_t)(b * NUM_C + c0 + ty) * IMG_H) * IMG_W + x0 + tx;
    float* dstbase = g_itrans + (size_t)b * HW * NUM_C;
    float acc = 0.0f;
    for (int y = 0; y < IMG_H; ++y) {
        acc += src[(size_t)y * IMG_W];
        tile[ty][tx] = acc;
        __syncthreads();
        dstbase[((size_t)y * IMG_W + x0 + ty) * NUM_C + c0 + tx] = tile[tx][ty];
        __syncthreads();
    }
}

// ---------------- K3: project corners -> per-box tap table (always written) ----------------
__global__ void k_boxes(const float* __restrict__ calib, const float* __restrict__ grid) {
    int i = blockIdx.x * blockDim.x + threadIdx.x;
    if (i >= NBOX) return;
    int q = i % NQ;
    int layer = (i / NQ) % NLAYER;
    int b = i / (NQ * NLAYER);

    float gx = grid[q * 3 + 0];
    float gy = grid[q * 3 + 1];
    float gz = grid[q * 3 + 2] + 32.0f * (float)layer;

    const float* M = calib + b * 12;
    float m00 = M[0], m01 = M[1], m02 = M[2],  m03 = M[3];
    float m10 = M[4], m11 = M[5], m12 = M[6],  m13 = M[7];
    float m20 = M[8], m21 = M[9], m22 = M[10], m23 = M[11];

    const float ox[8] = {-12.5f, 12.5f, 12.5f, -12.5f, -12.5f, 12.5f, 12.5f, -12.5f};
    const float oy[8] = {-12.5f, -12.5f, 12.5f, 12.5f, -12.5f, -12.5f, 12.5f, 12.5f};
    const float oz[8] = {0.0f, 0.0f, 0.0f, 0.0f, 32.0f, 32.0f, 32.0f, 32.0f};

    float mnx = 1e30f, mny = 1e30f, mxx = -1e30f, mxy = -1e30f;
    #pragma unroll
    for (int k = 0; k < 8; ++k) {
        float X = gx + ox[k];
        float Y = gy + oy[k];
        float Z = gz + oz[k];
        float px = m00 * X + m01 * Y + m02 * Z + m03;
        float py = m10 * X + m11 * Y + m12 * Z + m13;
        float pz = m20 * X + m21 * Y + m22 * Z + m23;
        float zc = fmaxf(pz, 1e-6f);
        float ix = px / zc;
        float iy = py / zc;
        float nx = fminf(fmaxf(2.0f * ix / 320.0f - 1.0f, -1.0f), 0.95f);
        float ny = fminf(fmaxf(2.0f * iy / 96.0f - 1.0f, -1.0f), 0.95f);
        mnx = fminf(mnx, nx);
        mny = fminf(mny, ny);
        mxx = fmaxf(mxx, nx);
        mxy = fmaxf(mxy, ny);
    }

    float area = ((mxx - mnx) * (mxy - mny)) * (float)HW + 1e-6f;
    bool visible = (area > 1e-6f) && (area < (float)HW * 0.3f);
    float inv = visible ? (1.0f / area) : 0.0f;
    g_bpa[i] = inv;

    float xs[2], ys[2];
    xs[0] = ((mnx + 1.0f) * 320.0f - 1.0f) * 0.5f;
    xs[1] = ((mxx + 1.0f) * 320.0f - 1.0f) * 0.5f;
    ys[0] = ((mny + 1.0f) * 96.0f - 1.0f) * 0.5f;
    ys[1] = ((mxy + 1.0f) * 96.0f - 1.0f) * 0.5f;

    // corners: lt(min,min,+), rb(max,max,+), rt(max,min,-), lb(min,max,-)
    const int cxi[4] = {0, 1, 1, 0};
    const int cyi[4] = {0, 1, 0, 1};
    const float csg[4] = {1.0f, 1.0f, -1.0f, -1.0f};
    int2* tp = g_tap + (size_t)i * 16;
    #pragma unroll
    for (int cc = 0; cc < 4; ++cc) {
        float sx = xs[cxi[cc]], sy = ys[cyi[cc]];
        float fx = floorf(sx), fy = floorf(sy);
        int x0 = (int)fx, y0 = (int)fy;
        float wx1 = sx - fx, wy1 = sy - fy;
        float wx0 = 1.0f - wx1, wy0 = 1.0f - wy1;
        float s = csg[cc] * inv;
        #pragma unroll
        for (int tt = 0; tt < 4; ++tt) {
            int xi = x0 + (tt & 1);
            int yi = y0 + (tt >> 1);
            float w = ((tt & 1) ? wx1 : wx0) * ((tt >> 1) ? wy1 : wy0) * s;
            bool valid = visible && ((unsigned)xi < (unsigned)IMG_W) && ((unsigned)yi < (unsigned)IMG_H);
            int idx = valid ? (yi * IMG_W + xi) : 0;
            if (!valid) w = 0.0f;
            tp[cc * 4 + tt] = make_int2(idx, __float_as_int(w));
        }
    }
}

// ---------------- K4: box-filter sampling -> vox (fp16) ----------------
__global__ __launch_bounds__(256) void k_sample() {
    __shared__ int2 st[NLAYER][16];
    __shared__ float sinv[NLAYER];
    int m = blockIdx.x;
    int b = m >> 14;
    int q = m & (NQ - 1);
    int tid = threadIdx.x;
    if (tid < NLAYER * 16) {
        int layer = tid >> 4, t = tid & 15;
        st[layer][t] = g_tap[((size_t)((b * NLAYER + layer) * NQ + q)) * 16 + t];
    } else if (tid >= 128 && tid < 128 + NLAYER) {
        sinv[tid - 128] = g_bpa[(size_t)(b * NLAYER + (tid - 128)) * NQ + q];
    }
    __syncthreads();

    const float* I = g_itrans + (size_t)b * HW * NUM_C + tid;
    __half* vdst = g_vox + (size_t)m * NK;

    #pragma unroll
    for (int layer = 0; layer < NLAYER; ++layer) {
        float v = 0.0f;
        if (sinv[layer] != 0.0f) {
            float s0 = 0.0f, s1 = 0.0f, s2 = 0.0f, s3 = 0.0f;
            #pragma unroll
            for (int t = 0; t < 4; ++t) {
                int2 w0 = st[layer][t];
                int2 w1 = st[layer][4 + t];
                int2 w2 = st[layer][8 + t];
                int2 w3 = st[layer][12 + t];
                s0 = fmaf(I[(size_t)w0.x * NUM_C], __int_as_float(w0.y), s0);
                s1 = fmaf(I[(size_t)w1.x * NUM_C], __int_as_float(w1.y), s1);
                s2 = fmaf(I[(size_t)w2.x * NUM_C], __int_as_float(w2.y), s2);
                s3 = fmaf(I[(size_t)w3.x * NUM_C], __int_as_float(w3.y), s3);
            }
            v = (s0 + s1) + (s2 + s3);
        }
        vdst[layer * NUM_C + tid] = __float2half(v);
    }
}

// ---------------- K5: permute Wc to K-order layer*256+c (fp16) ----------------
__global__ void k_wperm(const float* __restrict__ Wc) {
    int idx = blockIdx.x * blockDim.x + threadIdx.x;
    if (idx >= NUM_C * NK) return;
    int co = idx / NK;
    int kd = idx % NK;
    int layer = kd / NUM_C;
    int c = kd % NUM_C;
    g_wperm[(size_t)co * NK + layer * NUM_C + c] = __float2half(Wc[co * NK + c * NLAYER + layer]);
}

// ---------------- K6: fp16 mma GEMM (CTA 128Mx128N, 8 warps 2Mx4N, warp 64x32) ------------
// K-chunk 64 halfs (128B rows). Smem per stage: A 16KB + B 16KB; double buffer 64KB total.
// XOR swizzle (c16 ^= row&7) -> conflict-free ldmatrix.x4. 2 CTAs/SM.
#define STAGE_BYTES 32768
#define GSM_BYTES (2 * STAGE_BYTES)
#define NKT (NK / 64)   // 20

__global__ __launch_bounds__(256, 2) void k_gemm(const float* __restrict__ bc,
                                                 float* __restrict__ out) {
    extern __shared__ char smc[];
    uint32_t smb = smem_u32(smc);
    int tid = threadIdx.x;
    int wid = tid >> 5;
    int lane = tid & 31;
    int g = lane >> 2;
    int tg = lane & 3;
    int wm = wid & 1;          // 2 M halves (64 rows)
    int wn = wid >> 1;         // 4 N quarters (32 cols)
    int n0 = blockIdx.x * 128;
    int m0 = blockIdx.y * 128;

    float acc[4][4][4];
    #pragma unroll
    for (int ms = 0; ms < 4; ++ms)
        #pragma unroll
        for (int ns = 0; ns < 4; ++ns)
            #pragma unroll
            for (int cc = 0; cc < 4; ++cc) acc[ms][ns][cc] = 0.0f;

    // ldmatrix per-lane row components
    int a_row_l = wm * 64 + (lane & 7) + (((lane >> 3) & 1) << 3);  // + ms*16
    int a_cadd  = lane >> 4;                                        // c16 += this
    int b_row_l = wn * 32 + (lane & 7) + ((lane >> 4) << 3);        // + np*16
    int b_cadd  = (lane >> 3) & 1;

    #define FILL(ktv) do { \
        int _kt = (ktv); \
        uint32_t _sb = smb + (uint32_t)((_kt & 1) * STAGE_BYTES); \
        int _ko = _kt * 64; \
        _Pragma("unroll") \
        for (int _i = 0; _i < 4; ++_i) { \
            int _idx = tid + _i * 256; \
            int _row = _idx >> 3, _c16 = _idx & 7; \
            cp16(_sb + (uint32_t)(_row * 128 + ((_c16 ^ (_row & 7)) << 4)), \
                 (const char*)g_vox + ((size_t)(m0 + _row) * NK + _ko) * 2 + _c16 * 16); \
        } \
        _Pragma("unroll") \
        for (int _i = 0; _i < 4; ++_i) { \
            int _idx = tid + _i * 256; \
            int _row = _idx >> 3, _c16 = _idx & 7; \
            cp16(_sb + 16384u + (uint32_t)(_row * 128 + ((_c16 ^ (_row & 7)) << 4)), \
                 (const char*)g_wperm + ((size_t)(n0 + _row) * NK + _ko) * 2 + _c16 * 16); \
        } \
        asm volatile("cp.async.commit_group;" ::: "memory"); \
    } while (0)

    FILL(0);

    for (int kt = 0; kt < NKT; ++kt) {
        if (kt + 1 < NKT) {
            FILL(kt + 1);
            asm volatile("cp.async.wait_group 1;" ::: "memory");
        } else {
            asm volatile("cp.async.wait_group 0;" ::: "memory");
        }
        __syncthreads();

        uint32_t sA = smb + (uint32_t)((kt & 1) * STAGE_BYTES);
        uint32_t sB = sA + 16384u;
        #pragma unroll
        for (int ks = 0; ks < 4; ++ks) {
            uint32_t a[4][4];
            #pragma unroll
            for (int ms = 0; ms < 4; ++ms) {
                int row = a_row_l + ms * 16;
                int c16 = 2 * ks + a_cadd;
                LDSM4(a[ms], sA + (uint32_t)(row * 128 + ((c16 ^ (row & 7)) << 4)));
            }
            uint32_t bf[2][4];
            #pragma unroll
            for (int np = 0; np < 2; ++np) {
                int row = b_row_l + np * 16;
                int c16 = 2 * ks + b_cadd;
                LDSM4(bf[np], sB + (uint32_t)(row * 128 + ((c16 ^ (row & 7)) << 4)));
            }
            #pragma unroll
            for (int ms = 0; ms < 4; ++ms)
                #pragma unroll
                for (int ns = 0; ns < 4; ++ns)
                    mma_f16(acc[ms][ns], a[ms], bf[ns >> 1][(ns & 1) * 2], bf[ns >> 1][(ns & 1) * 2 + 1]);
        }
        __syncthreads();
    }

    // Epilogue: out[b][n][q] = relu(acc + bc[n])
    int b = m0 >> 14;
    #pragma unroll
    for (int ms = 0; ms < 4; ++ms) {
        #pragma unroll
        for (int h = 0; h < 2; ++h) {
            int m = m0 + wm * 64 + ms * 16 + g + h * 8;
            int q = m & (NQ - 1);
            float* ob = out + (size_t)b * NUM_C * NQ + q;
            #pragma unroll
            for (int ns = 0; ns < 4; ++ns) {
                int n = n0 + wn * 32 + ns * 8 + tg * 2;
                float v0 = acc[ms][ns][h * 2 + 0] + __ldg(bc + n);
                float v1 = acc[ms][ns][h * 2 + 1] + __ldg(bc + n + 1);
                ob[(size_t)n * NQ] = fmaxf(v0, 0.0f);
                ob[(size_t)(n + 1) * NQ] = fmaxf(v1, 0.0f);
            }
        }
    }
}

extern "C" void kernel_launch(void* const* d_in, const int* in_sizes, int n_in,
                              void* d_out, int out_size) {
    const float* feature = (const float*)d_in[0];  // (2,256,96,320)
    const float* calib   = (const float*)d_in[1];  // (2,3,4)
    const float* grid    = (const float*)d_in[2];  // (128,128,3)
    const float* Wc      = (const float*)d_in[3];  // (256,1280)
    const float* bc      = (const float*)d_in[4];  // (256,)
    float* out = (float*)d_out;                    // (2,256,128,128)

    cudaFuncSetAttribute(k_gemm, cudaFuncAttributeMaxDynamicSharedMemorySize, GSM_BYTES);

    k_rowcum<<<NROWS / 8, 256>>>(feature);
    {
        dim3 g(IMG_W / 32, NUM_C / 32, NUM_B);
        dim3 blk(32, 32);
        k_colcum_t<<<g, blk>>>();
    }
    k_boxes<<<(NBOX + 255) / 256, 256>>>(calib, grid);
    k_sample<<<NM, 256>>>();
    k_wperm<<<(NUM_C * NK + 255) / 256, 256>>>(Wc);
    {
        dim3 gg(NUM_C / 128, NM / 128);   // N fastest -> A-sharing CTAs adjacent
        k_gemm<<<gg, 256, GSM_BYTES>>>(bc, out);
    }
}

// round 8
// speedup vs baseline: 2.8128x; 1.3611x over previous
#include <cuda_runtime.h>
#include <cuda_fp16.h>
#include <math.h>
#include <stdint.h>

// Problem constants
#define NUM_B 2
#define NUM_C 256
#define IMG_H 96
#define IMG_W 320
#define NLAYER 5
#define NQ (128 * 128)           // 16384
#define NM (NUM_B * NQ)          // 32768
#define NK (NUM_C * NLAYER)      // 1280
#define HW (IMG_H * IMG_W)       // 30720
#define NROWS (NUM_B * NUM_C * IMG_H)     // 49152
#define NBOX (NUM_B * NLAYER * NQ)        // 163840
#define NWP (NUM_C * NK)                  // 327680

// Scratch (device globals: allocation-free per harness rules)
__device__ float  g_rowcum[NUM_B * NUM_C * IMG_H * IMG_W];     // 63MB
__device__ float  g_itrans[NUM_B * IMG_H * IMG_W * NUM_C];     // 63MB, [b][y][x][c]
__device__ __align__(256) __half g_vox[NM * NK];               // 84MB, [m][k] fp16
__device__ __align__(256) __half g_wperm[NUM_C * NK];          // 0.65MB, [co][k] fp16
__device__ float  g_bpa[NBOX];                                 // visible ? 1/area : 0
__device__ int2   g_tap[NBOX * 16];                            // {pixel idx, weight bits}

__device__ __forceinline__ uint32_t smem_u32(const void* p) {
    uint32_t a;
    asm("{ .reg .u64 t; cvta.to.shared.u64 t, %1; cvt.u32.u64 %0, t; }" : "=r"(a) : "l"(p));
    return a;
}
__device__ __forceinline__ void cp16(uint32_t saddr, const void* gptr) {
    asm volatile("cp.async.cg.shared.global [%0], [%1], 16;" :: "r"(saddr), "l"(gptr) : "memory");
}
#define LDSM4(r, a) \
    asm volatile("ldmatrix.sync.aligned.m8n8.x4.shared.b16 {%0,%1,%2,%3}, [%4];" \
                 : "=r"((r)[0]), "=r"((r)[1]), "=r"((r)[2]), "=r"((r)[3]) : "r"(a))
__device__ __forceinline__ void mma_f16(float c[4], const uint32_t a[4], uint32_t b0, uint32_t b1) {
    asm volatile(
        "mma.sync.aligned.m16n8k16.row.col.f32.f16.f16.f32 "
        "{%0,%1,%2,%3}, {%4,%5,%6,%7}, {%8,%9}, {%0,%1,%2,%3};"
        : "+f"(c[0]), "+f"(c[1]), "+f"(c[2]), "+f"(c[3])
        : "r"(a[0]), "r"(a[1]), "r"(a[2]), "r"(a[3]), "r"(b0), "r"(b1));
}

// ---------------- K1: row cumsum, warp-per-row shfl scan ----------------
__global__ void k_rowcum(const float* __restrict__ feat) {
    int w = (blockIdx.x * blockDim.x + threadIdx.x) >> 5;
    int lane = threadIdx.x & 31;
    if (w >= NROWS) return;
    const float* src = feat + (size_t)w * IMG_W;
    float* dst = g_rowcum + (size_t)w * IMG_W;
    float carry = 0.0f;
    #pragma unroll
    for (int c0 = 0; c0 < IMG_W; c0 += 32) {
        float v = src[c0 + lane];
        #pragma unroll
        for (int d = 1; d < 32; d <<= 1) {
            float n = __shfl_up_sync(0xFFFFFFFFu, v, d);
            if (lane >= d) v += n;
        }
        v += carry;
        dst[c0 + lane] = v;
        carry = __shfl_sync(0xFFFFFFFFu, v, 31);
    }
}

// ---------------- K2: column cumsum + transpose to [b][y][x][c], 4x y-unroll ----------------
__global__ void k_colcum_t() {
    __shared__ float tile[4][32][33];
    int x0 = blockIdx.x * 32;
    int c0 = blockIdx.y * 32;
    int b  = blockIdx.z;
    int tx = threadIdx.x, ty = threadIdx.y;
    const float* src = g_rowcum + ((size_t)(b * NUM_C + c0 + ty) * IMG_H) * IMG_W + x0 + tx;
    float* dstbase = g_itrans + (size_t)b * HW * NUM_C;
    float acc = 0.0f;
    for (int y0 = 0; y0 < IMG_H; y0 += 4) {
        float v0 = src[(size_t)(y0 + 0) * IMG_W];
        float v1 = src[(size_t)(y0 + 1) * IMG_W];
        float v2 = src[(size_t)(y0 + 2) * IMG_W];
        float v3 = src[(size_t)(y0 + 3) * IMG_W];
        v0 += acc; v1 += v0; v2 += v1; v3 += v2; acc = v3;
        tile[0][ty][tx] = v0;
        tile[1][ty][tx] = v1;
        tile[2][ty][tx] = v2;
        tile[3][ty][tx] = v3;
        __syncthreads();
        #pragma unroll
        for (int j = 0; j < 4; ++j)
            dstbase[((size_t)(y0 + j) * IMG_W + x0 + ty) * NUM_C + c0 + tx] = tile[j][tx][ty];
        __syncthreads();
    }
}

// ---------------- K3: boxes (tap table) + Wc permute, merged ----------------
__global__ void k_prep(const float* __restrict__ calib, const float* __restrict__ grid,
                       const float* __restrict__ Wc) {
    int gi = blockIdx.x * blockDim.x + threadIdx.x;
    if (gi >= NBOX) {
        int idx = gi - NBOX;
        if (idx < NWP) {
            int co = idx / NK;
            int kd = idx % NK;
            int layer = kd / NUM_C;
            int c = kd % NUM_C;
            g_wperm[(size_t)co * NK + layer * NUM_C + c] = __float2half(Wc[co * NK + c * NLAYER + layer]);
        }
        return;
    }
    int i = gi;
    int q = i % NQ;
    int layer = (i / NQ) % NLAYER;
    int b = i / (NQ * NLAYER);

    float gx = grid[q * 3 + 0];
    float gy = grid[q * 3 + 1];
    float gz = grid[q * 3 + 2] + 32.0f * (float)layer;

    const float* M = calib + b * 12;
    float m00 = M[0], m01 = M[1], m02 = M[2],  m03 = M[3];
    float m10 = M[4], m11 = M[5], m12 = M[6],  m13 = M[7];
    float m20 = M[8], m21 = M[9], m22 = M[10], m23 = M[11];

    const float ox[8] = {-12.5f, 12.5f, 12.5f, -12.5f, -12.5f, 12.5f, 12.5f, -12.5f};
    const float oy[8] = {-12.5f, -12.5f, 12.5f, 12.5f, -12.5f, -12.5f, 12.5f, 12.5f};
    const float oz[8] = {0.0f, 0.0f, 0.0f, 0.0f, 32.0f, 32.0f, 32.0f, 32.0f};

    float mnx = 1e30f, mny = 1e30f, mxx = -1e30f, mxy = -1e30f;
    #pragma unroll
    for (int k = 0; k < 8; ++k) {
        float X = gx + ox[k];
        float Y = gy + oy[k];
        float Z = gz + oz[k];
        float px = m00 * X + m01 * Y + m02 * Z + m03;
        float py = m10 * X + m11 * Y + m12 * Z + m13;
        float pz = m20 * X + m21 * Y + m22 * Z + m23;
        float zc = fmaxf(pz, 1e-6f);
        float ix = px / zc;
        float iy = py / zc;
        float nx = fminf(fmaxf(2.0f * ix / 320.0f - 1.0f, -1.0f), 0.95f);
        float ny = fminf(fmaxf(2.0f * iy / 96.0f - 1.0f, -1.0f), 0.95f);
        mnx = fminf(mnx, nx);
        mny = fminf(mny, ny);
        mxx = fmaxf(mxx, nx);
        mxy = fmaxf(mxy, ny);
    }

    float area = ((mxx - mnx) * (mxy - mny)) * (float)HW + 1e-6f;
    bool visible = (area > 1e-6f) && (area < (float)HW * 0.3f);
    float inv = visible ? (1.0f / area) : 0.0f;
    g_bpa[i] = inv;

    float xs[2], ys[2];
    xs[0] = ((mnx + 1.0f) * 320.0f - 1.0f) * 0.5f;
    xs[1] = ((mxx + 1.0f) * 320.0f - 1.0f) * 0.5f;
    ys[0] = ((mny + 1.0f) * 96.0f - 1.0f) * 0.5f;
    ys[1] = ((mxy + 1.0f) * 96.0f - 1.0f) * 0.5f;

    // corners: lt(min,min,+), rb(max,max,+), rt(max,min,-), lb(min,max,-)
    const int cxi[4] = {0, 1, 1, 0};
    const int cyi[4] = {0, 1, 0, 1};
    const float csg[4] = {1.0f, 1.0f, -1.0f, -1.0f};
    int2* tp = g_tap + (size_t)i * 16;
    #pragma unroll
    for (int cc = 0; cc < 4; ++cc) {
        float sx = xs[cxi[cc]], sy = ys[cyi[cc]];
        float fx = floorf(sx), fy = floorf(sy);
        int x0 = (int)fx, y0 = (int)fy;
        float wx1 = sx - fx, wy1 = sy - fy;
        float wx0 = 1.0f - wx1, wy0 = 1.0f - wy1;
        float s = csg[cc] * inv;
        #pragma unroll
        for (int tt = 0; tt < 4; ++tt) {
            int xi = x0 + (tt & 1);
            int yi = y0 + (tt >> 1);
            float w = ((tt & 1) ? wx1 : wx0) * ((tt >> 1) ? wy1 : wy0) * s;
            bool valid = visible && ((unsigned)xi < (unsigned)IMG_W) && ((unsigned)yi < (unsigned)IMG_H);
            int idx = valid ? (yi * IMG_W + xi) : 0;
            if (!valid) w = 0.0f;
            tp[cc * 4 + tt] = make_int2(idx, __float_as_int(w));
        }
    }
}

// ---------------- K4: box-filter sampling -> vox (fp16), 2 channels/thread ----------------
__global__ __launch_bounds__(128) void k_sample() {
    __shared__ int2 st[NLAYER][16];
    __shared__ float sinv[NLAYER];
    int m = blockIdx.x;
    int b = m >> 14;
    int q = m & (NQ - 1);
    int tid = threadIdx.x;
    if (tid < NLAYER * 16) {
        int layer = tid >> 4, t = tid & 15;
        st[layer][t] = g_tap[((size_t)((b * NLAYER + layer) * NQ + q)) * 16 + t];
    } else if (tid >= 96 && tid < 96 + NLAYER) {
        sinv[tid - 96] = g_bpa[(size_t)(b * NLAYER + (tid - 96)) * NQ + q];
    }
    __syncthreads();

    const float2* I2 = (const float2*)(g_itrans + (size_t)b * HW * NUM_C) + tid;
    __half2* vdst = (__half2*)(g_vox + (size_t)m * NK) + tid;

    #pragma unroll
    for (int layer = 0; layer < NLAYER; ++layer) {
        float vx = 0.0f, vy = 0.0f;
        if (sinv[layer] != 0.0f) {
            float ax0 = 0.0f, ax1 = 0.0f, ax2 = 0.0f, ax3 = 0.0f;
            float ay0 = 0.0f, ay1 = 0.0f, ay2 = 0.0f, ay3 = 0.0f;
            #pragma unroll
            for (int t = 0; t < 4; ++t) {
                int2 w0 = st[layer][t];
                int2 w1 = st[layer][4 + t];
                int2 w2 = st[layer][8 + t];
                int2 w3 = st[layer][12 + t];
                float2 d0 = I2[(size_t)w0.x * 128];
                float2 d1 = I2[(size_t)w1.x * 128];
                float2 d2 = I2[(size_t)w2.x * 128];
                float2 d3 = I2[(size_t)w3.x * 128];
                float f0 = __int_as_float(w0.y), f1 = __int_as_float(w1.y);
                float f2 = __int_as_float(w2.y), f3 = __int_as_float(w3.y);
                ax0 = fmaf(d0.x, f0, ax0); ay0 = fmaf(d0.y, f0, ay0);
                ax1 = fmaf(d1.x, f1, ax1); ay1 = fmaf(d1.y, f1, ay1);
                ax2 = fmaf(d2.x, f2, ax2); ay2 = fmaf(d2.y, f2, ay2);
                ax3 = fmaf(d3.x, f3, ax3); ay3 = fmaf(d3.y, f3, ay3);
            }
            vx = (ax0 + ax1) + (ax2 + ax3);
            vy = (ay0 + ay1) + (ay2 + ay3);
        }
        vdst[layer * 128] = __floats2half2_rn(vx, vy);
    }
}

// ---------------- K6: fp16 mma GEMM (CTA 128Mx128N, 8 warps 2Mx4N, warp 64x32) ------------
// K-chunk 64 halfs (128B rows). 3-stage cp.async pipeline; 96KB smem; 2 CTAs/SM.
// XOR swizzle (c16 ^= row&7) -> conflict-free ldmatrix.x4.
#define STAGE_BYTES 32768
#define GSM_BYTES (3 * STAGE_BYTES)
#define NKT (NK / 64)   // 20

__global__ __launch_bounds__(256, 2) void k_gemm(const float* __restrict__ bc,
                                                 float* __restrict__ out) {
    extern __shared__ char smc[];
    uint32_t smb = smem_u32(smc);
    int tid = threadIdx.x;
    int wid = tid >> 5;
    int lane = tid & 31;
    int g = lane >> 2;
    int tg = lane & 3;
    int wm = wid & 1;
    int wn = wid >> 1;
    int n0 = blockIdx.x * 128;
    int m0 = blockIdx.y * 128;

    float acc[4][4][4];
    #pragma unroll
    for (int ms = 0; ms < 4; ++ms)
        #pragma unroll
        for (int ns = 0; ns < 4; ++ns)
            #pragma unroll
            for (int cc = 0; cc < 4; ++cc) acc[ms][ns][cc] = 0.0f;

    int a_row_l = wm * 64 + (lane & 7) + (((lane >> 3) & 1) << 3);
    int a_cadd  = lane >> 4;
    int b_row_l = wn * 32 + (lane & 7) + ((lane >> 4) << 3);
    int b_cadd  = (lane >> 3) & 1;

    #define FILL(ktv) do { \
        int _kt = (ktv); \
        uint32_t _sb = smb + (uint32_t)((_kt % 3) * STAGE_BYTES); \
        int _ko = _kt * 64; \
        _Pragma("unroll") \
        for (int _i = 0; _i < 4; ++_i) { \
            int _idx = tid + _i * 256; \
            int _row = _idx >> 3, _c16 = _idx & 7; \
            cp16(_sb + (uint32_t)(_row * 128 + ((_c16 ^ (_row & 7)) << 4)), \
                 (const char*)g_vox + ((size_t)(m0 + _row) * NK + _ko) * 2 + _c16 * 16); \
        } \
        _Pragma("unroll") \
        for (int _i = 0; _i < 4; ++_i) { \
            int _idx = tid + _i * 256; \
            int _row = _idx >> 3, _c16 = _idx & 7; \
            cp16(_sb + 16384u + (uint32_t)(_row * 128 + ((_c16 ^ (_row & 7)) << 4)), \
                 (const char*)g_wperm + ((size_t)(n0 + _row) * NK + _ko) * 2 + _c16 * 16); \
        } \
        asm volatile("cp.async.commit_group;" ::: "memory"); \
    } while (0)

    FILL(0);
    FILL(1);

    for (int kt = 0; kt < NKT; ++kt) {
        if (kt + 1 < NKT) {
            asm volatile("cp.async.wait_group 1;" ::: "memory");
        } else {
            asm volatile("cp.async.wait_group 0;" ::: "memory");
        }
        __syncthreads();
        if (kt + 2 < NKT) FILL(kt + 2);

        uint32_t sA = smb + (uint32_t)((kt % 3) * STAGE_BYTES);
        uint32_t sB = sA + 16384u;
        #pragma unroll
        for (int ks = 0; ks < 4; ++ks) {
            uint32_t a[4][4];
            #pragma unroll
            for (int ms = 0; ms < 4; ++ms) {
                int row = a_row_l + ms * 16;
                int c16 = 2 * ks + a_cadd;
                LDSM4(a[ms], sA + (uint32_t)(row * 128 + ((c16 ^ (row & 7)) << 4)));
            }
            uint32_t bf[2][4];
            #pragma unroll
            for (int np = 0; np < 2; ++np) {
                int row = b_row_l + np * 16;
                int c16 = 2 * ks + b_cadd;
                LDSM4(bf[np], sB + (uint32_t)(row * 128 + ((c16 ^ (row & 7)) << 4)));
            }
            #pragma unroll
            for (int ms = 0; ms < 4; ++ms)
                #pragma unroll
                for (int ns = 0; ns < 4; ++ns)
                    mma_f16(acc[ms][ns], a[ms], bf[ns >> 1][(ns & 1) * 2], bf[ns >> 1][(ns & 1) * 2 + 1]);
        }
        __syncthreads();
    }

    // Epilogue: out[b][n][q] = relu(acc + bc[n])
    int b = m0 >> 14;
    #pragma unroll
    for (int ms = 0; ms < 4; ++ms) {
        #pragma unroll
        for (int h = 0; h < 2; ++h) {
            int m = m0 + wm * 64 + ms * 16 + g + h * 8;
            int q = m & (NQ - 1);
            float* ob = out + (size_t)b * NUM_C * NQ + q;
            #pragma unroll
            for (int ns = 0; ns < 4; ++ns) {
                int n = n0 + wn * 32 + ns * 8 + tg * 2;
                float v0 = acc[ms][ns][h * 2 + 0] + __ldg(bc + n);
                float v1 = acc[ms][ns][h * 2 + 1] + __ldg(bc + n + 1);
                ob[(size_t)n * NQ] = fmaxf(v0, 0.0f);
                ob[(size_t)(n + 1) * NQ] = fmaxf(v1, 0.0f);
            }
        }
    }
}

extern "C" void kernel_launch(void* const* d_in, const int* in_sizes, int n_in,
                              void* d_out, int out_size) {
    const float* feature = (const float*)d_in[0];  // (2,256,96,320)
    const float* calib   = (const float*)d_in[1];  // (2,3,4)
    const float* grid    = (const float*)d_in[2];  // (128,128,3)
    const float* Wc      = (const float*)d_in[3];  // (256,1280)
    const float* bc      = (const float*)d_in[4];  // (256,)
    float* out = (float*)d_out;                    // (2,256,128,128)

    cudaFuncSetAttribute(k_gemm, cudaFuncAttributeMaxDynamicSharedMemorySize, GSM_BYTES);

    k_rowcum<<<NROWS / 8, 256>>>(feature);
    {
        dim3 g(IMG_W / 32, NUM_C / 32, NUM_B);
        dim3 blk(32, 32);
        k_colcum_t<<<g, blk>>>();
    }
    k_prep<<<(NBOX + NWP + 255) / 256, 256>>>(calib, grid, Wc);
    k_sample<<<NM, 128>>>();
    {
        dim3 gg(NUM_C / 128, NM / 128);   // N fastest -> A-sharing CTAs adjacent
        k_gemm<<<gg, 256, GSM_BYTES>>>(bc, out);
    }
}

// round 9
// speedup vs baseline: 2.8765x; 1.0227x over previous
#include <cuda_runtime.h>
#include <cuda_fp16.h>
#include <math.h>
#include <stdint.h>

// Problem constants
#define NUM_B 2
#define NUM_C 256
#define IMG_H 96
#define IMG_W 320
#define NLAYER 5
#define NQ (128 * 128)           // 16384
#define NM (NUM_B * NQ)          // 32768
#define NK (NUM_C * NLAYER)      // 1280
#define HW (IMG_H * IMG_W)       // 30720
#define NROWS (NUM_B * NUM_C * IMG_H)     // 49152
#define NBOX (NUM_B * NLAYER * NQ)        // 163840
#define NWP (NUM_C * NK)                  // 327680

// Scratch (device globals: allocation-free per harness rules)
__device__ float  g_rowcum[NUM_B * NUM_C * IMG_H * IMG_W];     // 63MB
__device__ float  g_itrans[NUM_B * IMG_H * IMG_W * NUM_C];     // 63MB, [b][y][x][c]
__device__ __align__(256) __half g_vox[NM * NK];               // 84MB, [m][k] fp16
__device__ __align__(256) __half g_wperm[NUM_C * NK];          // 0.65MB, [co][k] fp16
__device__ float  g_bpa[NBOX];                                 // visible ? 1/area : 0
__device__ int2   g_tap[NBOX * 16];                            // {pixel idx, weight bits}

__device__ __forceinline__ uint32_t smem_u32(const void* p) {
    uint32_t a;
    asm("{ .reg .u64 t; cvta.to.shared.u64 t, %1; cvt.u32.u64 %0, t; }" : "=r"(a) : "l"(p));
    return a;
}
__device__ __forceinline__ void cp16(uint32_t saddr, const void* gptr) {
    asm volatile("cp.async.cg.shared.global [%0], [%1], 16;" :: "r"(saddr), "l"(gptr) : "memory");
}
#define LDSM4(r, a) \
    asm volatile("ldmatrix.sync.aligned.m8n8.x4.shared.b16 {%0,%1,%2,%3}, [%4];" \
                 : "=r"((r)[0]), "=r"((r)[1]), "=r"((r)[2]), "=r"((r)[3]) : "r"(a))
__device__ __forceinline__ void mma_f16(float c[4], const uint32_t a[4], uint32_t b0, uint32_t b1) {
    asm volatile(
        "mma.sync.aligned.m16n8k16.row.col.f32.f16.f16.f32 "
        "{%0,%1,%2,%3}, {%4,%5,%6,%7}, {%8,%9}, {%0,%1,%2,%3};"
        : "+f"(c[0]), "+f"(c[1]), "+f"(c[2]), "+f"(c[3])
        : "r"(a[0]), "r"(a[1]), "r"(a[2]), "r"(a[3]), "r"(b0), "r"(b1));
}

// ---------------- K1: row cumsum (warp-per-row) + prep (boxes/wperm), merged ----------------
#define ROWCUM_BLOCKS (NROWS / 8)     // 6144 blocks of 8 warps
#define PREP_BLOCKS ((NBOX + NWP + 255) / 256)

__global__ __launch_bounds__(256) void k_rowprep(const float* __restrict__ feat,
                                                 const float* __restrict__ calib,
                                                 const float* __restrict__ grid,
                                                 const float* __restrict__ Wc) {
    if (blockIdx.x < ROWCUM_BLOCKS) {
        int w = blockIdx.x * 8 + (threadIdx.x >> 5);
        int lane = threadIdx.x & 31;
        const float* src = feat + (size_t)w * IMG_W;
        float* dst = g_rowcum + (size_t)w * IMG_W;
        float carry = 0.0f;
        #pragma unroll
        for (int c0 = 0; c0 < IMG_W; c0 += 32) {
            float v = src[c0 + lane];
            #pragma unroll
            for (int d = 1; d < 32; d <<= 1) {
                float n = __shfl_up_sync(0xFFFFFFFFu, v, d);
                if (lane >= d) v += n;
            }
            v += carry;
            dst[c0 + lane] = v;
            carry = __shfl_sync(0xFFFFFFFFu, v, 31);
        }
        return;
    }

    int gi = (blockIdx.x - ROWCUM_BLOCKS) * blockDim.x + threadIdx.x;
    if (gi >= NBOX) {
        int idx = gi - NBOX;
        if (idx < NWP) {
            int co = idx / NK;
            int kd = idx % NK;
            int layer = kd / NUM_C;
            int c = kd % NUM_C;
            g_wperm[(size_t)co * NK + layer * NUM_C + c] = __float2half(Wc[co * NK + c * NLAYER + layer]);
        }
        return;
    }
    int i = gi;
    int q = i % NQ;
    int layer = (i / NQ) % NLAYER;
    int b = i / (NQ * NLAYER);

    float gx = grid[q * 3 + 0];
    float gy = grid[q * 3 + 1];
    float gz = grid[q * 3 + 2] + 32.0f * (float)layer;

    const float* M = calib + b * 12;
    float m00 = M[0], m01 = M[1], m02 = M[2],  m03 = M[3];
    float m10 = M[4], m11 = M[5], m12 = M[6],  m13 = M[7];
    float m20 = M[8], m21 = M[9], m22 = M[10], m23 = M[11];

    const float ox[8] = {-12.5f, 12.5f, 12.5f, -12.5f, -12.5f, 12.5f, 12.5f, -12.5f};
    const float oy[8] = {-12.5f, -12.5f, 12.5f, 12.5f, -12.5f, -12.5f, 12.5f, 12.5f};
    const float oz[8] = {0.0f, 0.0f, 0.0f, 0.0f, 32.0f, 32.0f, 32.0f, 32.0f};

    float mnx = 1e30f, mny = 1e30f, mxx = -1e30f, mxy = -1e30f;
    #pragma unroll
    for (int k = 0; k < 8; ++k) {
        float X = gx + ox[k];
        float Y = gy + oy[k];
        float Z = gz + oz[k];
        float px = m00 * X + m01 * Y + m02 * Z + m03;
        float py = m10 * X + m11 * Y + m12 * Z + m13;
        float pz = m20 * X + m21 * Y + m22 * Z + m23;
        float zc = fmaxf(pz, 1e-6f);
        float ix = px / zc;
        float iy = py / zc;
        float nx = fminf(fmaxf(2.0f * ix / 320.0f - 1.0f, -1.0f), 0.95f);
        float ny = fminf(fmaxf(2.0f * iy / 96.0f - 1.0f, -1.0f), 0.95f);
        mnx = fminf(mnx, nx);
        mny = fminf(mny, ny);
        mxx = fmaxf(mxx, nx);
        mxy = fmaxf(mxy, ny);
    }

    float area = ((mxx - mnx) * (mxy - mny)) * (float)HW + 1e-6f;
    bool visible = (area > 1e-6f) && (area < (float)HW * 0.3f);
    float inv = visible ? (1.0f / area) : 0.0f;
    g_bpa[i] = inv;

    float xs[2], ys[2];
    xs[0] = ((mnx + 1.0f) * 320.0f - 1.0f) * 0.5f;
    xs[1] = ((mxx + 1.0f) * 320.0f - 1.0f) * 0.5f;
    ys[0] = ((mny + 1.0f) * 96.0f - 1.0f) * 0.5f;
    ys[1] = ((mxy + 1.0f) * 96.0f - 1.0f) * 0.5f;

    // corners: lt(min,min,+), rb(max,max,+), rt(max,min,-), lb(min,max,-)
    const int cxi[4] = {0, 1, 1, 0};
    const int cyi[4] = {0, 1, 0, 1};
    const float csg[4] = {1.0f, 1.0f, -1.0f, -1.0f};
    int2* tp = g_tap + (size_t)i * 16;
    #pragma unroll
    for (int cc = 0; cc < 4; ++cc) {
        float sx = xs[cxi[cc]], sy = ys[cyi[cc]];
        float fx = floorf(sx), fy = floorf(sy);
        int x0 = (int)fx, y0 = (int)fy;
        float wx1 = sx - fx, wy1 = sy - fy;
        float wx0 = 1.0f - wx1, wy0 = 1.0f - wy1;
        float s = csg[cc] * inv;
        #pragma unroll
        for (int tt = 0; tt < 4; ++tt) {
            int xi = x0 + (tt & 1);
            int yi = y0 + (tt >> 1);
            float w = ((tt & 1) ? wx1 : wx0) * ((tt >> 1) ? wy1 : wy0) * s;
            bool valid = visible && ((unsigned)xi < (unsigned)IMG_W) && ((unsigned)yi < (unsigned)IMG_H);
            int idx = valid ? (yi * IMG_W + xi) : 0;
            if (!valid) w = 0.0f;
            tp[cc * 4 + tt] = make_int2(idx, __float_as_int(w));
        }
    }
}

// ---------------- K2: column cumsum + transpose to [b][y][x][c], 8x y-unroll ----------------
__global__ void k_colcum_t() {
    __shared__ float tile[8][32][33];
    int x0 = blockIdx.x * 32;
    int c0 = blockIdx.y * 32;
    int b  = blockIdx.z;
    int tx = threadIdx.x, ty = threadIdx.y;
    const float* src = g_rowcum + ((size_t)(b * NUM_C + c0 + ty) * IMG_H) * IMG_W + x0 + tx;
    float* dstbase = g_itrans + (size_t)b * HW * NUM_C;
    float acc = 0.0f;
    for (int y0 = 0; y0 < IMG_H; y0 += 8) {
        float v[8];
        #pragma unroll
        for (int j = 0; j < 8; ++j) v[j] = src[(size_t)(y0 + j) * IMG_W];
        #pragma unroll
        for (int j = 0; j < 8; ++j) { acc += v[j]; tile[j][ty][tx] = acc; }
        __syncthreads();
        #pragma unroll
        for (int j = 0; j < 8; ++j)
            dstbase[((size_t)(y0 + j) * IMG_W + x0 + ty) * NUM_C + c0 + tx] = tile[j][tx][ty];
        __syncthreads();
    }
}

// ---------------- K4: box-filter sampling -> vox (fp16), 16-deep gather burst ----------------
__global__ __launch_bounds__(128) void k_sample() {
    __shared__ int2 st[NLAYER][16];
    __shared__ float sinv[NLAYER];
    int m = blockIdx.x;
    int b = m >> 14;
    int q = m & (NQ - 1);
    int tid = threadIdx.x;
    if (tid < NLAYER * 16) {
        int layer = tid >> 4, t = tid & 15;
        st[layer][t] = g_tap[((size_t)((b * NLAYER + layer) * NQ + q)) * 16 + t];
    } else if (tid >= 96 && tid < 96 + NLAYER) {
        sinv[tid - 96] = g_bpa[(size_t)(b * NLAYER + (tid - 96)) * NQ + q];
    }
    __syncthreads();

    const float2* I2 = (const float2*)(g_itrans + (size_t)b * HW * NUM_C) + tid;
    __half2* vdst = (__half2*)(g_vox + (size_t)m * NK) + tid;

    #pragma unroll
    for (int layer = 0; layer < NLAYER; ++layer) {
        float vx = 0.0f, vy = 0.0f;
        if (sinv[layer] != 0.0f) {
            // 16 independent gathers in flight (MLP=16)
            float2 d[16];
            #pragma unroll
            for (int t = 0; t < 16; ++t)
                d[t] = I2[(size_t)st[layer][t].x * 128];
            float ax0 = 0.0f, ax1 = 0.0f, ax2 = 0.0f, ax3 = 0.0f;
            float ay0 = 0.0f, ay1 = 0.0f, ay2 = 0.0f, ay3 = 0.0f;
            #pragma unroll
            for (int t = 0; t < 4; ++t) {
                float f0 = __int_as_float(st[layer][t].y);
                float f1 = __int_as_float(st[layer][4 + t].y);
                float f2 = __int_as_float(st[layer][8 + t].y);
                float f3 = __int_as_float(st[layer][12 + t].y);
                ax0 = fmaf(d[t].x, f0, ax0);      ay0 = fmaf(d[t].y, f0, ay0);
                ax1 = fmaf(d[4 + t].x, f1, ax1);  ay1 = fmaf(d[4 + t].y, f1, ay1);
                ax2 = fmaf(d[8 + t].x, f2, ax2);  ay2 = fmaf(d[8 + t].y, f2, ay2);
                ax3 = fmaf(d[12 + t].x, f3, ax3); ay3 = fmaf(d[12 + t].y, f3, ay3);
            }
            vx = (ax0 + ax1) + (ax2 + ax3);
            vy = (ay0 + ay1) + (ay2 + ay3);
        }
        vdst[layer * 128] = __floats2half2_rn(vx, vy);
    }
}

// ---------------- K6: fp16 mma GEMM (CTA 128Mx128N, 8 warps 2Mx4N, warp 64x32) ------------
// K-chunk 64 halfs (128B rows). 3-stage cp.async pipeline; 96KB smem; 2 CTAs/SM.
// XOR swizzle (c16 ^= row&7) -> conflict-free ldmatrix.x4.
#define STAGE_BYTES 32768
#define GSM_BYTES (3 * STAGE_BYTES)
#define NKT (NK / 64)   // 20

__global__ __launch_bounds__(256, 2) void k_gemm(const float* __restrict__ bc,
                                                 float* __restrict__ out) {
    extern __shared__ char smc[];
    uint32_t smb = smem_u32(smc);
    int tid = threadIdx.x;
    int wid = tid >> 5;
    int lane = tid & 31;
    int g = lane >> 2;
    int tg = lane & 3;
    int wm = wid & 1;
    int wn = wid >> 1;
    int n0 = blockIdx.x * 128;
    int m0 = blockIdx.y * 128;

    float acc[4][4][4];
    #pragma unroll
    for (int ms = 0; ms < 4; ++ms)
        #pragma unroll
        for (int ns = 0; ns < 4; ++ns)
            #pragma unroll
            for (int cc = 0; cc < 4; ++cc) acc[ms][ns][cc] = 0.0f;

    int a_row_l = wm * 64 + (lane & 7) + (((lane >> 3) & 1) << 3);
    int a_cadd  = lane >> 4;
    int b_row_l = wn * 32 + (lane & 7) + ((lane >> 4) << 3);
    int b_cadd  = (lane >> 3) & 1;

    #define FILL(ktv) do { \
        int _kt = (ktv); \
        uint32_t _sb = smb + (uint32_t)((_kt % 3) * STAGE_BYTES); \
        int _ko = _kt * 64; \
        _Pragma("unroll") \
        for (int _i = 0; _i < 4; ++_i) { \
            int _idx = tid + _i * 256; \
            int _row = _idx >> 3, _c16 = _idx & 7; \
            cp16(_sb + (uint32_t)(_row * 128 + ((_c16 ^ (_row & 7)) << 4)), \
                 (const char*)g_vox + ((size_t)(m0 + _row) * NK + _ko) * 2 + _c16 * 16); \
        } \
        _Pragma("unroll") \
        for (int _i = 0; _i < 4; ++_i) { \
            int _idx = tid + _i * 256; \
            int _row = _idx >> 3, _c16 = _idx & 7; \
            cp16(_sb + 16384u + (uint32_t)(_row * 128 + ((_c16 ^ (_row & 7)) << 4)), \
                 (const char*)g_wperm + ((size_t)(n0 + _row) * NK + _ko) * 2 + _c16 * 16); \
        } \
        asm volatile("cp.async.commit_group;" ::: "memory"); \
    } while (0)

    FILL(0);
    FILL(1);

    for (int kt = 0; kt < NKT; ++kt) {
        if (kt + 1 < NKT) {
            asm volatile("cp.async.wait_group 1;" ::: "memory");
        } else {
            asm volatile("cp.async.wait_group 0;" ::: "memory");
        }
        __syncthreads();
        if (kt + 2 < NKT) FILL(kt + 2);

        uint32_t sA = smb + (uint32_t)((kt % 3) * STAGE_BYTES);
        uint32_t sB = sA + 16384u;
        #pragma unroll
        for (int ks = 0; ks < 4; ++ks) {
            uint32_t a[4][4];
            #pragma unroll
            for (int ms = 0; ms < 4; ++ms) {
                int row = a_row_l + ms * 16;
                int c16 = 2 * ks + a_cadd;
                LDSM4(a[ms], sA + (uint32_t)(row * 128 + ((c16 ^ (row & 7)) << 4)));
            }
            uint32_t bf[2][4];
            #pragma unroll
            for (int np = 0; np < 2; ++np) {
                int row = b_row_l + np * 16;
                int c16 = 2 * ks + b_cadd;
                LDSM4(bf[np], sB + (uint32_t)(row * 128 + ((c16 ^ (row & 7)) << 4)));
            }
            #pragma unroll
            for (int ms = 0; ms < 4; ++ms)
                #pragma unroll
                for (int ns = 0; ns < 4; ++ns)
                    mma_f16(acc[ms][ns], a[ms], bf[ns >> 1][(ns & 1) * 2], bf[ns >> 1][(ns & 1) * 2 + 1]);
        }
        __syncthreads();
    }

    // Epilogue: out[b][n][q] = relu(acc + bc[n])
    int b = m0 >> 14;
    #pragma unroll
    for (int ms = 0; ms < 4; ++ms) {
        #pragma unroll
        for (int h = 0; h < 2; ++h) {
            int m = m0 + wm * 64 + ms * 16 + g + h * 8;
            int q = m & (NQ - 1);
            float* ob = out + (size_t)b * NUM_C * NQ + q;
            #pragma unroll
            for (int ns = 0; ns < 4; ++ns) {
                int n = n0 + wn * 32 + ns * 8 + tg * 2;
                float v0 = acc[ms][ns][h * 2 + 0] + __ldg(bc + n);
                float v1 = acc[ms][ns][h * 2 + 1] + __ldg(bc + n + 1);
                ob[(size_t)n * NQ] = fmaxf(v0, 0.0f);
                ob[(size_t)(n + 1) * NQ] = fmaxf(v1, 0.0f);
            }
        }
    }
}

extern "C" void kernel_launch(void* const* d_in, const int* in_sizes, int n_in,
                              void* d_out, int out_size) {
    const float* feature = (const float*)d_in[0];  // (2,256,96,320)
    const float* calib   = (const float*)d_in[1];  // (2,3,4)
    const float* grid    = (const float*)d_in[2];  // (128,128,3)
    const float* Wc      = (const float*)d_in[3];  // (256,1280)
    const float* bc      = (const float*)d_in[4];  // (256,)
    float* out = (float*)d_out;                    // (2,256,128,128)

    cudaFuncSetAttribute(k_gemm, cudaFuncAttributeMaxDynamicSharedMemorySize, GSM_BYTES);

    k_rowprep<<<ROWCUM_BLOCKS + PREP_BLOCKS, 256>>>(feature, calib, grid, Wc);
    {
        dim3 g(IMG_W / 32, NUM_C / 32, NUM_B);
        dim3 blk(32, 32);
        k_colcum_t<<<g, blk>>>();
    }
    k_sample<<<NM, 128>>>();
    {
        dim3 gg(NUM_C / 128, NM / 128);   // N fastest -> A-sharing CTAs adjacent
        k_gemm<<<gg, 256, GSM_BYTES>>>(bc, out);
    }
}

// round 10
// speedup vs baseline: 2.9117x; 1.0122x over previous
#include <cuda_runtime.h>
#include <cuda_fp16.h>
#include <math.h>
#include <stdint.h>

// Problem constants
#define NUM_B 2
#define NUM_C 256
#define IMG_H 96
#define IMG_W 320
#define NLAYER 5
#define NQ (128 * 128)           // 16384
#define NM (NUM_B * NQ)          // 32768
#define NK (NUM_C * NLAYER)      // 1280
#define HW (IMG_H * IMG_W)       // 30720
#define NROWS (NUM_B * NUM_C * IMG_H)     // 49152
#define NBOX (NUM_B * NLAYER * NQ)        // 163840
#define NWP (NUM_C * NK)                  // 327680

// Scratch (device globals: allocation-free per harness rules)
__device__ float  g_rowcum[NUM_B * NUM_C * IMG_H * IMG_W];     // 63MB
__device__ float  g_itrans[NUM_B * IMG_H * IMG_W * NUM_C];     // 63MB, [b][y][x][c]
__device__ __align__(256) __half g_vox[NM * NK];               // 84MB, [m][k] fp16
__device__ __align__(256) __half g_wperm[NUM_C * NK];          // 0.65MB, [co][k] fp16
__device__ float  g_bpa[NBOX];                                 // visible ? 1/area : 0
__device__ int2   g_tap[NBOX * 16];                            // {pixel idx, weight bits}

__device__ __forceinline__ uint32_t smem_u32(const void* p) {
    uint32_t a;
    asm("{ .reg .u64 t; cvta.to.shared.u64 t, %1; cvt.u32.u64 %0, t; }" : "=r"(a) : "l"(p));
    return a;
}
__device__ __forceinline__ void cp16(uint32_t saddr, const void* gptr) {
    asm volatile("cp.async.cg.shared.global [%0], [%1], 16;" :: "r"(saddr), "l"(gptr) : "memory");
}
#define LDSM4(r, a) \
    asm volatile("ldmatrix.sync.aligned.m8n8.x4.shared.b16 {%0,%1,%2,%3}, [%4];" \
                 : "=r"((r)[0]), "=r"((r)[1]), "=r"((r)[2]), "=r"((r)[3]) : "r"(a))
__device__ __forceinline__ void mma_f16(float c[4], const uint32_t a[4], uint32_t b0, uint32_t b1) {
    asm volatile(
        "mma.sync.aligned.m16n8k16.row.col.f32.f16.f16.f32 "
        "{%0,%1,%2,%3}, {%4,%5,%6,%7}, {%8,%9}, {%0,%1,%2,%3};"
        : "+f"(c[0]), "+f"(c[1]), "+f"(c[2]), "+f"(c[3])
        : "r"(a[0]), "r"(a[1]), "r"(a[2]), "r"(a[3]), "r"(b0), "r"(b1));
}

// ---------------- K1: row cumsum (warp-per-row) + prep (boxes/wperm), merged ----------------
#define ROWCUM_BLOCKS (NROWS / 8)     // 6144 blocks of 8 warps
#define PREP_BLOCKS ((NBOX + NWP + 255) / 256)

__global__ __launch_bounds__(256) void k_rowprep(const float* __restrict__ feat,
                                                 const float* __restrict__ calib,
                                                 const float* __restrict__ grid,
                                                 const float* __restrict__ Wc) {
    if (blockIdx.x < ROWCUM_BLOCKS) {
        int w = blockIdx.x * 8 + (threadIdx.x >> 5);
        int lane = threadIdx.x & 31;
        const float* src = feat + (size_t)w * IMG_W;
        float* dst = g_rowcum + (size_t)w * IMG_W;
        float carry = 0.0f;
        #pragma unroll
        for (int c0 = 0; c0 < IMG_W; c0 += 32) {
            float v = src[c0 + lane];
            #pragma unroll
            for (int d = 1; d < 32; d <<= 1) {
                float n = __shfl_up_sync(0xFFFFFFFFu, v, d);
                if (lane >= d) v += n;
            }
            v += carry;
            dst[c0 + lane] = v;
            carry = __shfl_sync(0xFFFFFFFFu, v, 31);
        }
        return;
    }

    int gi = (blockIdx.x - ROWCUM_BLOCKS) * blockDim.x + threadIdx.x;
    if (gi >= NBOX) {
        int idx = gi - NBOX;
        if (idx < NWP) {
            int co = idx / NK;
            int kd = idx % NK;
            int layer = kd / NUM_C;
            int c = kd % NUM_C;
            g_wperm[(size_t)co * NK + layer * NUM_C + c] = __float2half(Wc[co * NK + c * NLAYER + layer]);
        }
        return;
    }
    int i = gi;
    int q = i % NQ;
    int layer = (i / NQ) % NLAYER;
    int b = i / (NQ * NLAYER);

    float gx = grid[q * 3 + 0];
    float gy = grid[q * 3 + 1];
    float gz = grid[q * 3 + 2] + 32.0f * (float)layer;

    const float* M = calib + b * 12;
    float m00 = M[0], m01 = M[1], m02 = M[2],  m03 = M[3];
    float m10 = M[4], m11 = M[5], m12 = M[6],  m13 = M[7];
    float m20 = M[8], m21 = M[9], m22 = M[10], m23 = M[11];

    const float ox[8] = {-12.5f, 12.5f, 12.5f, -12.5f, -12.5f, 12.5f, 12.5f, -12.5f};
    const float oy[8] = {-12.5f, -12.5f, 12.5f, 12.5f, -12.5f, -12.5f, 12.5f, 12.5f};
    const float oz[8] = {0.0f, 0.0f, 0.0f, 0.0f, 32.0f, 32.0f, 32.0f, 32.0f};

    float mnx = 1e30f, mny = 1e30f, mxx = -1e30f, mxy = -1e30f;
    #pragma unroll
    for (int k = 0; k < 8; ++k) {
        float X = gx + ox[k];
        float Y = gy + oy[k];
        float Z = gz + oz[k];
        float px = m00 * X + m01 * Y + m02 * Z + m03;
        float py = m10 * X + m11 * Y + m12 * Z + m13;
        float pz = m20 * X + m21 * Y + m22 * Z + m23;
        float zc = fmaxf(pz, 1e-6f);
        float ix = px / zc;
        float iy = py / zc;
        float nx = fminf(fmaxf(2.0f * ix / 320.0f - 1.0f, -1.0f), 0.95f);
        float ny = fminf(fmaxf(2.0f * iy / 96.0f - 1.0f, -1.0f), 0.95f);
        mnx = fminf(mnx, nx);
        mny = fminf(mny, ny);
        mxx = fmaxf(mxx, nx);
        mxy = fmaxf(mxy, ny);
    }

    float area = ((mxx - mnx) * (mxy - mny)) * (float)HW + 1e-6f;
    bool visible = (area > 1e-6f) && (area < (float)HW * 0.3f);
    float inv = visible ? (1.0f / area) : 0.0f;
    g_bpa[i] = inv;

    float xs[2], ys[2];
    xs[0] = ((mnx + 1.0f) * 320.0f - 1.0f) * 0.5f;
    xs[1] = ((mxx + 1.0f) * 320.0f - 1.0f) * 0.5f;
    ys[0] = ((mny + 1.0f) * 96.0f - 1.0f) * 0.5f;
    ys[1] = ((mxy + 1.0f) * 96.0f - 1.0f) * 0.5f;

    // corners: lt(min,min,+), rb(max,max,+), rt(max,min,-), lb(min,max,-)
    const int cxi[4] = {0, 1, 1, 0};
    const int cyi[4] = {0, 1, 0, 1};
    const float csg[4] = {1.0f, 1.0f, -1.0f, -1.0f};
    int2* tp = g_tap + (size_t)i * 16;
    #pragma unroll
    for (int cc = 0; cc < 4; ++cc) {
        float sx = xs[cxi[cc]], sy = ys[cyi[cc]];
        float fx = floorf(sx), fy = floorf(sy);
        int x0 = (int)fx, y0 = (int)fy;
        float wx1 = sx - fx, wy1 = sy - fy;
        float wx0 = 1.0f - wx1, wy0 = 1.0f - wy1;
        float s = csg[cc] * inv;
        #pragma unroll
        for (int tt = 0; tt < 4; ++tt) {
            int xi = x0 + (tt & 1);
            int yi = y0 + (tt >> 1);
            float w = ((tt & 1) ? wx1 : wx0) * ((tt >> 1) ? wy1 : wy0) * s;
            bool valid = visible && ((unsigned)xi < (unsigned)IMG_W) && ((unsigned)yi < (unsigned)IMG_H);
            int idx = valid ? (yi * IMG_W + xi) : 0;
            if (!valid) w = 0.0f;
            tp[cc * 4 + tt] = make_int2(idx, __float_as_int(w));
        }
    }
}

// ---------------- K2: column cumsum + transpose, (16x,16c) tiles, 640 blocks ----------------
__global__ __launch_bounds__(256) void k_colcum_t() {
    __shared__ float tile[8][16][17];
    int x0 = blockIdx.x * 16;
    int c0 = blockIdx.y * 16;
    int b  = blockIdx.z;
    int tx = threadIdx.x, ty = threadIdx.y;   // read: x = x0+tx, c = c0+ty
    const float* src = g_rowcum + ((size_t)(b * NUM_C + c0 + ty) * IMG_H) * IMG_W + x0 + tx;
    float* dstbase = g_itrans + (size_t)b * HW * NUM_C;
    float acc = 0.0f;
    for (int y0 = 0; y0 < IMG_H; y0 += 8) {
        float v[8];
        #pragma unroll
        for (int j = 0; j < 8; ++j) v[j] = src[(size_t)(y0 + j) * IMG_W];
        #pragma unroll
        for (int j = 0; j < 8; ++j) { acc += v[j]; tile[j][ty][tx] = acc; }
        __syncthreads();
        // write: x = x0+ty, c = c0+tx
        #pragma unroll
        for (int j = 0; j < 8; ++j)
            dstbase[((size_t)(y0 + j) * IMG_W + x0 + ty) * NUM_C + c0 + tx] = tile[j][tx][ty];
        __syncthreads();
    }
}

// ---------------- K4: box-filter sampling -> vox (fp16), 2 queries per block ----------------
__global__ __launch_bounds__(256) void k_sample() {
    __shared__ int2 st[2][NLAYER][16];
    __shared__ float sinv[2][NLAYER];
    int m0 = blockIdx.x * 2;
    int b = m0 >> 14;
    int q0 = m0 & (NQ - 1);
    int tid = threadIdx.x;
    if (tid < 2 * NLAYER * 16) {
        int pair = tid / 80;
        int rem = tid % 80;
        int layer = rem >> 4, t = rem & 15;
        st[pair][layer][t] = g_tap[((size_t)((b * NLAYER + layer) * NQ + q0 + pair)) * 16 + t];
    } else if (tid >= 192 && tid < 192 + 2 * NLAYER) {
        int e = tid - 192;
        int pair = e / NLAYER, layer = e % NLAYER;
        sinv[pair][layer] = g_bpa[(size_t)(b * NLAYER + layer) * NQ + q0 + pair];
    }
    __syncthreads();

    int pair = tid >> 7;
    int ch = tid & 127;
    int m = m0 + pair;
    const float2* I2 = (const float2*)(g_itrans + (size_t)b * HW * NUM_C) + ch;
    __half2* vdst = (__half2*)(g_vox + (size_t)m * NK) + ch;

    #pragma unroll
    for (int layer = 0; layer < NLAYER; ++layer) {
        float vx = 0.0f, vy = 0.0f;
        if (sinv[pair][layer] != 0.0f) {
            float2 d[16];
            #pragma unroll
            for (int t = 0; t < 16; ++t)
                d[t] = I2[(size_t)st[pair][layer][t].x * 128];
            float ax0 = 0.0f, ax1 = 0.0f, ax2 = 0.0f, ax3 = 0.0f;
            float ay0 = 0.0f, ay1 = 0.0f, ay2 = 0.0f, ay3 = 0.0f;
            #pragma unroll
            for (int t = 0; t < 4; ++t) {
                float f0 = __int_as_float(st[pair][layer][t].y);
                float f1 = __int_as_float(st[pair][layer][4 + t].y);
                float f2 = __int_as_float(st[pair][layer][8 + t].y);
                float f3 = __int_as_float(st[pair][layer][12 + t].y);
                ax0 = fmaf(d[t].x, f0, ax0);      ay0 = fmaf(d[t].y, f0, ay0);
                ax1 = fmaf(d[4 + t].x, f1, ax1);  ay1 = fmaf(d[4 + t].y, f1, ay1);
                ax2 = fmaf(d[8 + t].x, f2, ax2);  ay2 = fmaf(d[8 + t].y, f2, ay2);
                ax3 = fmaf(d[12 + t].x, f3, ax3); ay3 = fmaf(d[12 + t].y, f3, ay3);
            }
            vx = (ax0 + ax1) + (ax2 + ax3);
            vy = (ay0 + ay1) + (ay2 + ay3);
        }
        vdst[layer * 128] = __floats2half2_rn(vx, vy);
    }
}

// ---------------- K6: fp16 mma GEMM (CTA 128Mx128N, 8 warps 2Mx4N, warp 64x32) ------------
// K-chunk 64 halfs (128B rows). 3-stage cp.async pipeline, FILL-before-wait; 2 CTAs/SM.
#define STAGE_BYTES 32768
#define GSM_BYTES (3 * STAGE_BYTES)
#define NKT (NK / 64)   // 20

__global__ __launch_bounds__(256, 2) void k_gemm(const float* __restrict__ bc,
                                                 float* __restrict__ out) {
    extern __shared__ char smc[];
    uint32_t smb = smem_u32(smc);
    int tid = threadIdx.x;
    int wid = tid >> 5;
    int lane = tid & 31;
    int g = lane >> 2;
    int tg = lane & 3;
    int wm = wid & 1;
    int wn = wid >> 1;
    int n0 = blockIdx.x * 128;
    int m0 = blockIdx.y * 128;

    float acc[4][4][4];
    #pragma unroll
    for (int ms = 0; ms < 4; ++ms)
        #pragma unroll
        for (int ns = 0; ns < 4; ++ns)
            #pragma unroll
            for (int cc = 0; cc < 4; ++cc) acc[ms][ns][cc] = 0.0f;

    int a_row_l = wm * 64 + (lane & 7) + (((lane >> 3) & 1) << 3);
    int a_cadd  = lane >> 4;
    int b_row_l = wn * 32 + (lane & 7) + ((lane >> 4) << 3);
    int b_cadd  = (lane >> 3) & 1;

    #define FILL(ktv) do { \
        int _kt = (ktv); \
        uint32_t _sb = smb + (uint32_t)((_kt % 3) * STAGE_BYTES); \
        int _ko = _kt * 64; \
        _Pragma("unroll") \
        for (int _i = 0; _i < 4; ++_i) { \
            int _idx = tid + _i * 256; \
            int _row = _idx >> 3, _c16 = _idx & 7; \
            cp16(_sb + (uint32_t)(_row * 128 + ((_c16 ^ (_row & 7)) << 4)), \
                 (const char*)g_vox + ((size_t)(m0 + _row) * NK + _ko) * 2 + _c16 * 16); \
        } \
        _Pragma("unroll") \
        for (int _i = 0; _i < 4; ++_i) { \
            int _idx = tid + _i * 256; \
            int _row = _idx >> 3, _c16 = _idx & 7; \
            cp16(_sb + 16384u + (uint32_t)(_row * 128 + ((_c16 ^ (_row & 7)) << 4)), \
                 (const char*)g_wperm + ((size_t)(n0 + _row) * NK + _ko) * 2 + _c16 * 16); \
        } \
        asm volatile("cp.async.commit_group;" ::: "memory"); \
    } while (0)

    FILL(0);
    FILL(1);

    for (int kt = 0; kt < NKT; ++kt) {
        // Prefetch next-next stage BEFORE waiting: stage (kt+2)%3 was released at the
        // bottom barrier of chunk kt-1, so the cp.async writes cannot race reads.
        if (kt + 2 < NKT) {
            FILL(kt + 2);
            asm volatile("cp.async.wait_group 2;" ::: "memory");
        } else if (kt + 1 < NKT) {
            asm volatile("cp.async.wait_group 1;" ::: "memory");
        } else {
            asm volatile("cp.async.wait_group 0;" ::: "memory");
        }
        __syncthreads();

        uint32_t sA = smb + (uint32_t)((kt % 3) * STAGE_BYTES);
        uint32_t sB = sA + 16384u;
        #pragma unroll
        for (int ks = 0; ks < 4; ++ks) {
            uint32_t a[4][4];
            #pragma unroll
            for (int ms = 0; ms < 4; ++ms) {
                int row = a_row_l + ms * 16;
                int c16 = 2 * ks + a_cadd;
                LDSM4(a[ms], sA + (uint32_t)(row * 128 + ((c16 ^ (row & 7)) << 4)));
            }
            uint32_t bf[2][4];
            #pragma unroll
            for (int np = 0; np < 2; ++np) {
                int row = b_row_l + np * 16;
                int c16 = 2 * ks + b_cadd;
                LDSM4(bf[np], sB + (uint32_t)(row * 128 + ((c16 ^ (row & 7)) << 4)));
            }
            #pragma unroll
            for (int ms = 0; ms < 4; ++ms)
                #pragma unroll
                for (int ns = 0; ns < 4; ++ns)
                    mma_f16(acc[ms][ns], a[ms], bf[ns >> 1][(ns & 1) * 2], bf[ns >> 1][(ns & 1) * 2 + 1]);
        }
        __syncthreads();
    }

    // Epilogue: out[b][n][q] = relu(acc + bc[n])
    int b = m0 >> 14;
    #pragma unroll
    for (int ms = 0; ms < 4; ++ms) {
        #pragma unroll
        for (int h = 0; h < 2; ++h) {
            int m = m0 + wm * 64 + ms * 16 + g + h * 8;
            int q = m & (NQ - 1);
            float* ob = out + (size_t)b * NUM_C * NQ + q;
            #pragma unroll
            for (int ns = 0; ns < 4; ++ns) {
                int n = n0 + wn * 32 + ns * 8 + tg * 2;
                float v0 = acc[ms][ns][h * 2 + 0] + __ldg(bc + n);
                float v1 = acc[ms][ns][h * 2 + 1] + __ldg(bc + n + 1);
                ob[(size_t)n * NQ] = fmaxf(v0, 0.0f);
                ob[(size_t)(n + 1) * NQ] = fmaxf(v1, 0.0f);
            }
        }
    }
}

extern "C" void kernel_launch(void* const* d_in, const int* in_sizes, int n_in,
                              void* d_out, int out_size) {
    const float* feature = (const float*)d_in[0];  // (2,256,96,320)
    const float* calib   = (const float*)d_in[1];  // (2,3,4)
    const float* grid    = (const float*)d_in[2];  // (128,128,3)
    const float* Wc      = (const float*)d_in[3];  // (256,1280)
    const float* bc      = (const float*)d_in[4];  // (256,)
    float* out = (float*)d_out;                    // (2,256,128,128)

    cudaFuncSetAttribute(k_gemm, cudaFuncAttributeMaxDynamicSharedMemorySize, GSM_BYTES);

    k_rowprep<<<ROWCUM_BLOCKS + PREP_BLOCKS, 256>>>(feature, calib, grid, Wc);
    {
        dim3 g(IMG_W / 16, NUM_C / 16, NUM_B);   // 20 x 16 x 2 = 640 blocks
        dim3 blk(16, 16);
        k_colcum_t<<<g, blk>>>();
    }
    k_sample<<<NM / 2, 256>>>();
    {
        dim3 gg(NUM_C / 128, NM / 128);   // N fastest -> A-sharing CTAs adjacent
        k_gemm<<<gg, 256, GSM_BYTES>>>(bc, out);
    }
}

// round 11
// speedup vs baseline: 2.9537x; 1.0144x over previous
#include <cuda_runtime.h>
#include <cuda_fp16.h>
#include <math.h>
#include <stdint.h>

// Problem constants
#define NUM_B 2
#define NUM_C 256
#define IMG_H 96
#define IMG_W 320
#define NLAYER 5
#define NQ (128 * 128)           // 16384
#define NM (NUM_B * NQ)          // 32768
#define NK (NUM_C * NLAYER)      // 1280
#define HW (IMG_H * IMG_W)       // 30720
#define NROWS (NUM_B * NUM_C * IMG_H)     // 49152
#define NBOX (NUM_B * NLAYER * NQ)        // 163840
#define NWP (NUM_C * NK)                  // 327680

// Scratch (device globals: allocation-free per harness rules)
__device__ float  g_rowcum[NUM_B * NUM_C * IMG_H * IMG_W];     // 63MB
__device__ float  g_itrans[NUM_B * IMG_H * IMG_W * NUM_C];     // 63MB, [b][y][x][c]
__device__ __align__(256) __half g_vox[NM * NK];               // 84MB, [m][k] fp16
__device__ __align__(256) __half g_wperm[NUM_C * NK];          // 0.65MB, [co][k] fp16
__device__ float  g_bpa[NBOX];                                 // visible ? 1/area : 0
__device__ int2   g_tap[NBOX * 16];                            // {pixel idx, weight bits}

__device__ __forceinline__ uint32_t smem_u32(const void* p) {
    uint32_t a;
    asm("{ .reg .u64 t; cvta.to.shared.u64 t, %1; cvt.u32.u64 %0, t; }" : "=r"(a) : "l"(p));
    return a;
}
__device__ __forceinline__ void cp16(uint32_t saddr, const void* gptr) {
    asm volatile("cp.async.cg.shared.global [%0], [%1], 16;" :: "r"(saddr), "l"(gptr) : "memory");
}
#define LDSM4(r, a) \
    asm volatile("ldmatrix.sync.aligned.m8n8.x4.shared.b16 {%0,%1,%2,%3}, [%4];" \
                 : "=r"((r)[0]), "=r"((r)[1]), "=r"((r)[2]), "=r"((r)[3]) : "r"(a))
__device__ __forceinline__ void mma_f16(float c[4], const uint32_t a[4], uint32_t b0, uint32_t b1) {
    asm volatile(
        "mma.sync.aligned.m16n8k16.row.col.f32.f16.f16.f32 "
        "{%0,%1,%2,%3}, {%4,%5,%6,%7}, {%8,%9}, {%0,%1,%2,%3};"
        : "+f"(c[0]), "+f"(c[1]), "+f"(c[2]), "+f"(c[3])
        : "r"(a[0]), "r"(a[1]), "r"(a[2]), "r"(a[3]), "r"(b0), "r"(b1));
}

// ---------------- K1: row cumsum (warp-per-row) + prep (boxes/wperm), merged ----------------
#define ROWCUM_BLOCKS (NROWS / 8)     // 6144 blocks of 8 warps
#define PREP_BLOCKS ((NBOX + NWP + 255) / 256)

__global__ __launch_bounds__(256) void k_rowprep(const float* __restrict__ feat,
                                                 const float* __restrict__ calib,
                                                 const float* __restrict__ grid,
                                                 const float* __restrict__ Wc) {
    if (blockIdx.x < ROWCUM_BLOCKS) {
        int w = blockIdx.x * 8 + (threadIdx.x >> 5);
        int lane = threadIdx.x & 31;
        const float* src = feat + (size_t)w * IMG_W;
        float* dst = g_rowcum + (size_t)w * IMG_W;
        float carry = 0.0f;
        #pragma unroll
        for (int c0 = 0; c0 < IMG_W; c0 += 32) {
            float v = src[c0 + lane];
            #pragma unroll
            for (int d = 1; d < 32; d <<= 1) {
                float n = __shfl_up_sync(0xFFFFFFFFu, v, d);
                if (lane >= d) v += n;
            }
            v += carry;
            dst[c0 + lane] = v;
            carry = __shfl_sync(0xFFFFFFFFu, v, 31);
        }
        return;
    }

    int gi = (blockIdx.x - ROWCUM_BLOCKS) * blockDim.x + threadIdx.x;
    if (gi >= NBOX) {
        int idx = gi - NBOX;
        if (idx < NWP) {
            int co = idx / NK;
            int kd = idx % NK;
            int layer = kd / NUM_C;
            int c = kd % NUM_C;
            g_wperm[(size_t)co * NK + layer * NUM_C + c] = __float2half(Wc[co * NK + c * NLAYER + layer]);
        }
        return;
    }
    int i = gi;
    int q = i % NQ;
    int layer = (i / NQ) % NLAYER;
    int b = i / (NQ * NLAYER);

    float gx = grid[q * 3 + 0];
    float gy = grid[q * 3 + 1];
    float gz = grid[q * 3 + 2] + 32.0f * (float)layer;

    const float* M = calib + b * 12;
    float m00 = M[0], m01 = M[1], m02 = M[2],  m03 = M[3];
    float m10 = M[4], m11 = M[5], m12 = M[6],  m13 = M[7];
    float m20 = M[8], m21 = M[9], m22 = M[10], m23 = M[11];

    const float ox[8] = {-12.5f, 12.5f, 12.5f, -12.5f, -12.5f, 12.5f, 12.5f, -12.5f};
    const float oy[8] = {-12.5f, -12.5f, 12.5f, 12.5f, -12.5f, -12.5f, 12.5f, 12.5f};
    const float oz[8] = {0.0f, 0.0f, 0.0f, 0.0f, 32.0f, 32.0f, 32.0f, 32.0f};

    float mnx = 1e30f, mny = 1e30f, mxx = -1e30f, mxy = -1e30f;
    #pragma unroll
    for (int k = 0; k < 8; ++k) {
        float X = gx + ox[k];
        float Y = gy + oy[k];
        float Z = gz + oz[k];
        float px = m00 * X + m01 * Y + m02 * Z + m03;
        float py = m10 * X + m11 * Y + m12 * Z + m13;
        float pz = m20 * X + m21 * Y + m22 * Z + m23;
        float zc = fmaxf(pz, 1e-6f);
        float ix = px / zc;
        float iy = py / zc;
        float nx = fminf(fmaxf(2.0f * ix / 320.0f - 1.0f, -1.0f), 0.95f);
        float ny = fminf(fmaxf(2.0f * iy / 96.0f - 1.0f, -1.0f), 0.95f);
        mnx = fminf(mnx, nx);
        mny = fminf(mny, ny);
        mxx = fmaxf(mxx, nx);
        mxy = fmaxf(mxy, ny);
    }

    float area = ((mxx - mnx) * (mxy - mny)) * (float)HW + 1e-6f;
    bool visible = (area > 1e-6f) && (area < (float)HW * 0.3f);
    float inv = visible ? (1.0f / area) : 0.0f;
    g_bpa[i] = inv;

    float xs[2], ys[2];
    xs[0] = ((mnx + 1.0f) * 320.0f - 1.0f) * 0.5f;
    xs[1] = ((mxx + 1.0f) * 320.0f - 1.0f) * 0.5f;
    ys[0] = ((mny + 1.0f) * 96.0f - 1.0f) * 0.5f;
    ys[1] = ((mxy + 1.0f) * 96.0f - 1.0f) * 0.5f;

    // corners: lt(min,min,+), rb(max,max,+), rt(max,min,-), lb(min,max,-)
    const int cxi[4] = {0, 1, 1, 0};
    const int cyi[4] = {0, 1, 0, 1};
    const float csg[4] = {1.0f, 1.0f, -1.0f, -1.0f};
    int2* tp = g_tap + (size_t)i * 16;
    #pragma unroll
    for (int cc = 0; cc < 4; ++cc) {
        float sx = xs[cxi[cc]], sy = ys[cyi[cc]];
        float fx = floorf(sx), fy = floorf(sy);
        int x0 = (int)fx, y0 = (int)fy;
        float wx1 = sx - fx, wy1 = sy - fy;
        float wx0 = 1.0f - wx1, wy0 = 1.0f - wy1;
        float s = csg[cc] * inv;
        #pragma unroll
        for (int tt = 0; tt < 4; ++tt) {
            int xi = x0 + (tt & 1);
            int yi = y0 + (tt >> 1);
            float w = ((tt & 1) ? wx1 : wx0) * ((tt >> 1) ? wy1 : wy0) * s;
            bool valid = visible && ((unsigned)xi < (unsigned)IMG_W) && ((unsigned)yi < (unsigned)IMG_H);
            int idx = valid ? (yi * IMG_W + xi) : 0;
            if (!valid) w = 0.0f;
            tp[cc * 4 + tt] = make_int2(idx, __float_as_int(w));
        }
    }
}

// ---------------- K2: column cumsum + transpose, (16x,16c) tiles, 640 blocks ----------------
__global__ __launch_bounds__(256) void k_colcum_t() {
    __shared__ float tile[8][16][17];
    int x0 = blockIdx.x * 16;
    int c0 = blockIdx.y * 16;
    int b  = blockIdx.z;
    int tx = threadIdx.x, ty = threadIdx.y;   // read: x = x0+tx, c = c0+ty
    const float* src = g_rowcum + ((size_t)(b * NUM_C + c0 + ty) * IMG_H) * IMG_W + x0 + tx;
    float* dstbase = g_itrans + (size_t)b * HW * NUM_C;
    float acc = 0.0f;
    for (int y0 = 0; y0 < IMG_H; y0 += 8) {
        float v[8];
        #pragma unroll
        for (int j = 0; j < 8; ++j) v[j] = src[(size_t)(y0 + j) * IMG_W];
        #pragma unroll
        for (int j = 0; j < 8; ++j) { acc += v[j]; tile[j][ty][tx] = acc; }
        __syncthreads();
        // write: x = x0+ty, c = c0+tx
        #pragma unroll
        for (int j = 0; j < 8; ++j)
            dstbase[((size_t)(y0 + j) * IMG_W + x0 + ty) * NUM_C + c0 + tx] = tile[j][tx][ty];
        __syncthreads();
    }
}

// ---------------- K4: box-filter sampling -> vox (fp16), 2 queries per block ----------------
__global__ __launch_bounds__(256) void k_sample() {
    __shared__ int2 st[2][NLAYER][16];
    __shared__ float sinv[2][NLAYER];
    int m0 = blockIdx.x * 2;
    int b = m0 >> 14;
    int q0 = m0 & (NQ - 1);
    int tid = threadIdx.x;
    if (tid < 2 * NLAYER * 16) {
        int pair = tid / 80;
        int rem = tid % 80;
        int layer = rem >> 4, t = rem & 15;
        st[pair][layer][t] = g_tap[((size_t)((b * NLAYER + layer) * NQ + q0 + pair)) * 16 + t];
    } else if (tid >= 192 && tid < 192 + 2 * NLAYER) {
        int e = tid - 192;
        int pair = e / NLAYER, layer = e % NLAYER;
        sinv[pair][layer] = g_bpa[(size_t)(b * NLAYER + layer) * NQ + q0 + pair];
    }
    __syncthreads();

    int pair = tid >> 7;
    int ch = tid & 127;
    int m = m0 + pair;
    const float2* I2 = (const float2*)(g_itrans + (size_t)b * HW * NUM_C) + ch;
    __half2* vdst = (__half2*)(g_vox + (size_t)m * NK) + ch;

    #pragma unroll
    for (int layer = 0; layer < NLAYER; ++layer) {
        float vx = 0.0f, vy = 0.0f;
        if (sinv[pair][layer] != 0.0f) {
            float2 d[16];
            #pragma unroll
            for (int t = 0; t < 16; ++t)
                d[t] = I2[(size_t)st[pair][layer][t].x * 128];
            float ax0 = 0.0f, ax1 = 0.0f, ax2 = 0.0f, ax3 = 0.0f;
            float ay0 = 0.0f, ay1 = 0.0f, ay2 = 0.0f, ay3 = 0.0f;
            #pragma unroll
            for (int t = 0; t < 4; ++t) {
                float f0 = __int_as_float(st[pair][layer][t].y);
                float f1 = __int_as_float(st[pair][layer][4 + t].y);
                float f2 = __int_as_float(st[pair][layer][8 + t].y);
                float f3 = __int_as_float(st[pair][layer][12 + t].y);
                ax0 = fmaf(d[t].x, f0, ax0);      ay0 = fmaf(d[t].y, f0, ay0);
                ax1 = fmaf(d[4 + t].x, f1, ax1);  ay1 = fmaf(d[4 + t].y, f1, ay1);
                ax2 = fmaf(d[8 + t].x, f2, ax2);  ay2 = fmaf(d[8 + t].y, f2, ay2);
                ax3 = fmaf(d[12 + t].x, f3, ax3); ay3 = fmaf(d[12 + t].y, f3, ay3);
            }
            vx = (ax0 + ax1) + (ax2 + ax3);
            vy = (ay0 + ay1) + (ay2 + ay3);
        }
        vdst[layer * 128] = __floats2half2_rn(vx, vy);
    }
}

// ---------------- K6: fp16 mma GEMM (CTA 64Mx128N, 8 warps 2Mx4N, warp 32x32) -------------
// K-chunk 64 halfs (128B rows). Stage = A 8KB + B 16KB = 24KB; 3 stages = 72KB; 3 CTAs/SM.
// XOR swizzle (c16 ^= row&7) -> conflict-free ldmatrix.x4.
#define STAGE_BYTES 24576
#define A_BYTES 8192
#define GSM_BYTES (3 * STAGE_BYTES)
#define NKT (NK / 64)   // 20

__global__ __launch_bounds__(256, 3) void k_gemm(const float* __restrict__ bc,
                                                 float* __restrict__ out) {
    extern __shared__ char smc[];
    uint32_t smb = smem_u32(smc);
    int tid = threadIdx.x;
    int wid = tid >> 5;
    int lane = tid & 31;
    int g = lane >> 2;
    int tg = lane & 3;
    int wm = wid & 1;          // 2 M halves (32 rows each)
    int wn = wid >> 1;         // 4 N quarters (32 cols each)
    int n0 = blockIdx.x * 128;
    int m0 = blockIdx.y * 64;

    float acc[2][4][4];
    #pragma unroll
    for (int ms = 0; ms < 2; ++ms)
        #pragma unroll
        for (int ns = 0; ns < 4; ++ns)
            #pragma unroll
            for (int cc = 0; cc < 4; ++cc) acc[ms][ns][cc] = 0.0f;

    int a_row_l = wm * 32 + (lane & 7) + (((lane >> 3) & 1) << 3);
    int a_cadd  = lane >> 4;
    int b_row_l = wn * 32 + (lane & 7) + ((lane >> 4) << 3);
    int b_cadd  = (lane >> 3) & 1;

    #define FILL(ktv) do { \
        int _kt = (ktv); \
        uint32_t _sb = smb + (uint32_t)((_kt % 3) * STAGE_BYTES); \
        int _ko = _kt * 64; \
        _Pragma("unroll") \
        for (int _i = 0; _i < 2; ++_i) { \
            int _idx = tid + _i * 256; \
            int _row = _idx >> 3, _c16 = _idx & 7; \
            cp16(_sb + (uint32_t)(_row * 128 + ((_c16 ^ (_row & 7)) << 4)), \
                 (const char*)g_vox + ((size_t)(m0 + _row) * NK + _ko) * 2 + _c16 * 16); \
        } \
        _Pragma("unroll") \
        for (int _i = 0; _i < 4; ++_i) { \
            int _idx = tid + _i * 256; \
            int _row = _idx >> 3, _c16 = _idx & 7; \
            cp16(_sb + (uint32_t)A_BYTES + (uint32_t)(_row * 128 + ((_c16 ^ (_row & 7)) << 4)), \
                 (const char*)g_wperm + ((size_t)(n0 + _row) * NK + _ko) * 2 + _c16 * 16); \
        } \
        asm volatile("cp.async.commit_group;" ::: "memory"); \
    } while (0)

    FILL(0);
    FILL(1);

    for (int kt = 0; kt < NKT; ++kt) {
        if (kt + 2 < NKT) {
            FILL(kt + 2);
            asm volatile("cp.async.wait_group 2;" ::: "memory");
        } else if (kt + 1 < NKT) {
            asm volatile("cp.async.wait_group 1;" ::: "memory");
        } else {
            asm volatile("cp.async.wait_group 0;" ::: "memory");
        }
        __syncthreads();

        uint32_t sA = smb + (uint32_t)((kt % 3) * STAGE_BYTES);
        uint32_t sB = sA + (uint32_t)A_BYTES;
        #pragma unroll
        for (int ks = 0; ks < 4; ++ks) {
            uint32_t a[2][4];
            #pragma unroll
            for (int ms = 0; ms < 2; ++ms) {
                int row = a_row_l + ms * 16;
                int c16 = 2 * ks + a_cadd;
                LDSM4(a[ms], sA + (uint32_t)(row * 128 + ((c16 ^ (row & 7)) << 4)));
            }
            uint32_t bf[2][4];
            #pragma unroll
            for (int np = 0; np < 2; ++np) {
                int row = b_row_l + np * 16;
                int c16 = 2 * ks + b_cadd;
                LDSM4(bf[np], sB + (uint32_t)(row * 128 + ((c16 ^ (row & 7)) << 4)));
            }
            #pragma unroll
            for (int ms = 0; ms < 2; ++ms)
                #pragma unroll
                for (int ns = 0; ns < 4; ++ns)
                    mma_f16(acc[ms][ns], a[ms], bf[ns >> 1][(ns & 1) * 2], bf[ns >> 1][(ns & 1) * 2 + 1]);
        }
        __syncthreads();
    }

    // Epilogue: out[b][n][q] = relu(acc + bc[n])
    int b = m0 >> 14;
    #pragma unroll
    for (int ms = 0; ms < 2; ++ms) {
        #pragma unroll
        for (int h = 0; h < 2; ++h) {
            int m = m0 + wm * 32 + ms * 16 + g + h * 8;
            int q = m & (NQ - 1);
            float* ob = out + (size_t)b * NUM_C * NQ + q;
            #pragma unroll
            for (int ns = 0; ns < 4; ++ns) {
                int n = n0 + wn * 32 + ns * 8 + tg * 2;
                float v0 = acc[ms][ns][h * 2 + 0] + __ldg(bc + n);
                float v1 = acc[ms][ns][h * 2 + 1] + __ldg(bc + n + 1);
                ob[(size_t)n * NQ] = fmaxf(v0, 0.0f);
                ob[(size_t)(n + 1) * NQ] = fmaxf(v1, 0.0f);
            }
        }
    }
}

extern "C" void kernel_launch(void* const* d_in, const int* in_sizes, int n_in,
                              void* d_out, int out_size) {
    const float* feature = (const float*)d_in[0];  // (2,256,96,320)
    const float* calib   = (const float*)d_in[1];  // (2,3,4)
    const float* grid    = (const float*)d_in[2];  // (128,128,3)
    const float* Wc      = (const float*)d_in[3];  // (256,1280)
    const float* bc      = (const float*)d_in[4];  // (256,)
    float* out = (float*)d_out;                    // (2,256,128,128)

    cudaFuncSetAttribute(k_gemm, cudaFuncAttributeMaxDynamicSharedMemorySize, GSM_BYTES);

    k_rowprep<<<ROWCUM_BLOCKS + PREP_BLOCKS, 256>>>(feature, calib, grid, Wc);
    {
        dim3 g(IMG_W / 16, NUM_C / 16, NUM_B);   // 640 blocks
        dim3 blk(16, 16);
        k_colcum_t<<<g, blk>>>();
    }
    k_sample<<<NM / 2, 256>>>();
    {
        dim3 gg(NUM_C / 128, NM / 64);   // 2 x 512 = 1024 CTAs; N fastest for A reuse
        k_gemm<<<gg, 256, GSM_BYTES>>>(bc, out);
    }
}

// round 12
// speedup vs baseline: 3.7370x; 1.2652x over previous
#include <cuda_runtime.h>
#include <cuda_fp16.h>
#include <math.h>
#include <stdint.h>

// Problem constants
#define NUM_B 2
#define NUM_C 256
#define IMG_H 96
#define IMG_W 320
#define NLAYER 5
#define NQ (128 * 128)           // 16384
#define NM (NUM_B * NQ)          // 32768
#define NK (NUM_C * NLAYER)      // 1280
#define HW (IMG_H * IMG_W)       // 30720
#define NROWS (NUM_B * NUM_C * IMG_H)     // 49152
#define NBOX (NUM_B * NLAYER * NQ)        // 163840
#define NWP (NUM_C * NK)                  // 327680
#define NMT (NM / 64)                     // 512 M-tiles

// Scratch (device globals: allocation-free per harness rules)
__device__ float  g_rowcum[NUM_B * NUM_C * IMG_H * IMG_W];     // 63MB
__device__ float  g_itrans[NUM_B * IMG_H * IMG_W * NUM_C];     // 63MB, [b][y][x][c]
__device__ __align__(256) __half g_vox[NM * NK];               // 84MB, [m][k] fp16
__device__ __align__(256) __half g_wperm[NUM_C * NK];          // 0.65MB, [co][k] fp16
__device__ float  g_bpa[NBOX];                                 // visible ? 1/area : 0
__device__ int2   g_tap[NBOX * 16];                            // {pixel idx, weight bits}
__device__ unsigned g_vis[NMT];                                // per-Mtile layer visibility bits

__device__ __forceinline__ uint32_t smem_u32(const void* p) {
    uint32_t a;
    asm("{ .reg .u64 t; cvta.to.shared.u64 t, %1; cvt.u32.u64 %0, t; }" : "=r"(a) : "l"(p));
    return a;
}
__device__ __forceinline__ void cp16(uint32_t saddr, const void* gptr) {
    asm volatile("cp.async.cg.shared.global [%0], [%1], 16;" :: "r"(saddr), "l"(gptr) : "memory");
}
#define LDSM4(r, a) \
    asm volatile("ldmatrix.sync.aligned.m8n8.x4.shared.b16 {%0,%1,%2,%3}, [%4];" \
                 : "=r"((r)[0]), "=r"((r)[1]), "=r"((r)[2]), "=r"((r)[3]) : "r"(a))
__device__ __forceinline__ void mma_f16(float c[4], const uint32_t a[4], uint32_t b0, uint32_t b1) {
    asm volatile(
        "mma.sync.aligned.m16n8k16.row.col.f32.f16.f16.f32 "
        "{%0,%1,%2,%3}, {%4,%5,%6,%7}, {%8,%9}, {%0,%1,%2,%3};"
        : "+f"(c[0]), "+f"(c[1]), "+f"(c[2]), "+f"(c[3])
        : "r"(a[0]), "r"(a[1]), "r"(a[2]), "r"(a[3]), "r"(b0), "r"(b1));
}

// ---------------- K1: row cumsum (warp-per-row) + prep (boxes/wperm), merged ----------------
#define ROWCUM_BLOCKS (NROWS / 8)     // 6144 blocks of 8 warps
#define PREP_BLOCKS ((NBOX + NWP + 255) / 256)

__global__ __launch_bounds__(256) void k_rowprep(const float* __restrict__ feat,
                                                 const float* __restrict__ calib,
                                                 const float* __restrict__ grid,
                                                 const float* __restrict__ Wc) {
    if (blockIdx.x < ROWCUM_BLOCKS) {
        int w = blockIdx.x * 8 + (threadIdx.x >> 5);
        int lane = threadIdx.x & 31;
        const float* src = feat + (size_t)w * IMG_W;
        float* dst = g_rowcum + (size_t)w * IMG_W;
        float carry = 0.0f;
        #pragma unroll
        for (int c0 = 0; c0 < IMG_W; c0 += 32) {
            float v = src[c0 + lane];
            #pragma unroll
            for (int d = 1; d < 32; d <<= 1) {
                float n = __shfl_up_sync(0xFFFFFFFFu, v, d);
                if (lane >= d) v += n;
            }
            v += carry;
            dst[c0 + lane] = v;
            carry = __shfl_sync(0xFFFFFFFFu, v, 31);
        }
        return;
    }

    int gi = (blockIdx.x - ROWCUM_BLOCKS) * blockDim.x + threadIdx.x;
    if (gi >= NBOX) {
        int idx = gi - NBOX;
        if (idx < NWP) {
            int co = idx / NK;
            int kd = idx % NK;
            int layer = kd / NUM_C;
            int c = kd % NUM_C;
            g_wperm[(size_t)co * NK + layer * NUM_C + c] = __float2half(Wc[co * NK + c * NLAYER + layer]);
        }
        return;
    }
    int i = gi;
    int q = i % NQ;
    int layer = (i / NQ) % NLAYER;
    int b = i / (NQ * NLAYER);

    float gx = grid[q * 3 + 0];
    float gy = grid[q * 3 + 1];
    float gz = grid[q * 3 + 2] + 32.0f * (float)layer;

    const float* M = calib + b * 12;
    float m00 = M[0], m01 = M[1], m02 = M[2],  m03 = M[3];
    float m10 = M[4], m11 = M[5], m12 = M[6],  m13 = M[7];
    float m20 = M[8], m21 = M[9], m22 = M[10], m23 = M[11];

    const float ox[8] = {-12.5f, 12.5f, 12.5f, -12.5f, -12.5f, 12.5f, 12.5f, -12.5f};
    const float oy[8] = {-12.5f, -12.5f, 12.5f, 12.5f, -12.5f, -12.5f, 12.5f, 12.5f};
    const float oz[8] = {0.0f, 0.0f, 0.0f, 0.0f, 32.0f, 32.0f, 32.0f, 32.0f};

    float mnx = 1e30f, mny = 1e30f, mxx = -1e30f, mxy = -1e30f;
    #pragma unroll
    for (int k = 0; k < 8; ++k) {
        float X = gx + ox[k];
        float Y = gy + oy[k];
        float Z = gz + oz[k];
        float px = m00 * X + m01 * Y + m02 * Z + m03;
        float py = m10 * X + m11 * Y + m12 * Z + m13;
        float pz = m20 * X + m21 * Y + m22 * Z + m23;
        float zc = fmaxf(pz, 1e-6f);
        float ix = px / zc;
        float iy = py / zc;
        float nx = fminf(fmaxf(2.0f * ix / 320.0f - 1.0f, -1.0f), 0.95f);
        float ny = fminf(fmaxf(2.0f * iy / 96.0f - 1.0f, -1.0f), 0.95f);
        mnx = fminf(mnx, nx);
        mny = fminf(mny, ny);
        mxx = fmaxf(mxx, nx);
        mxy = fmaxf(mxy, ny);
    }

    float area = ((mxx - mnx) * (mxy - mny)) * (float)HW + 1e-6f;
    bool visible = (area > 1e-6f) && (area < (float)HW * 0.3f);
    float inv = visible ? (1.0f / area) : 0.0f;
    g_bpa[i] = inv;
    if (visible)
        atomicOr(&g_vis[(b * NQ + q) >> 6], 1u << layer);

    float xs[2], ys[2];
    xs[0] = ((mnx + 1.0f) * 320.0f - 1.0f) * 0.5f;
    xs[1] = ((mxx + 1.0f) * 320.0f - 1.0f) * 0.5f;
    ys[0] = ((mny + 1.0f) * 96.0f - 1.0f) * 0.5f;
    ys[1] = ((mxy + 1.0f) * 96.0f - 1.0f) * 0.5f;

    // corners: lt(min,min,+), rb(max,max,+), rt(max,min,-), lb(min,max,-)
    const int cxi[4] = {0, 1, 1, 0};
    const int cyi[4] = {0, 1, 0, 1};
    const float csg[4] = {1.0f, 1.0f, -1.0f, -1.0f};
    int2* tp = g_tap + (size_t)i * 16;
    #pragma unroll
    for (int cc = 0; cc < 4; ++cc) {
        float sx = xs[cxi[cc]], sy = ys[cyi[cc]];
        float fx = floorf(sx), fy = floorf(sy);
        int x0 = (int)fx, y0 = (int)fy;
        float wx1 = sx - fx, wy1 = sy - fy;
        float wx0 = 1.0f - wx1, wy0 = 1.0f - wy1;
        float s = csg[cc] * inv;
        #pragma unroll
        for (int tt = 0; tt < 4; ++tt) {
            int xi = x0 + (tt & 1);
            int yi = y0 + (tt >> 1);
            float w = ((tt & 1) ? wx1 : wx0) * ((tt >> 1) ? wy1 : wy0) * s;
            bool valid = visible && ((unsigned)xi < (unsigned)IMG_W) && ((unsigned)yi < (unsigned)IMG_H);
            int idx = valid ? (yi * IMG_W + xi) : 0;
            if (!valid) w = 0.0f;
            tp[cc * 4 + tt] = make_int2(idx, __float_as_int(w));
        }
    }
}

// ---------------- K2: column cumsum + transpose, (16x,16c) tiles, 640 blocks ----------------
__global__ __launch_bounds__(256) void k_colcum_t() {
    __shared__ float tile[8][16][17];
    int x0 = blockIdx.x * 16;
    int c0 = blockIdx.y * 16;
    int b  = blockIdx.z;
    int tx = threadIdx.x, ty = threadIdx.y;   // read: x = x0+tx, c = c0+ty
    const float* src = g_rowcum + ((size_t)(b * NUM_C + c0 + ty) * IMG_H) * IMG_W + x0 + tx;
    float* dstbase = g_itrans + (size_t)b * HW * NUM_C;
    float acc = 0.0f;
    for (int y0 = 0; y0 < IMG_H; y0 += 8) {
        float v[8];
        #pragma unroll
        for (int j = 0; j < 8; ++j) v[j] = src[(size_t)(y0 + j) * IMG_W];
        #pragma unroll
        for (int j = 0; j < 8; ++j) { acc += v[j]; tile[j][ty][tx] = acc; }
        __syncthreads();
        // write: x = x0+ty, c = c0+tx
        #pragma unroll
        for (int j = 0; j < 8; ++j)
            dstbase[((size_t)(y0 + j) * IMG_W + x0 + ty) * NUM_C + c0 + tx] = tile[j][tx][ty];
        __syncthreads();
    }
}

// ---------------- K4: box-filter sampling -> vox (fp16), 2 queries per block ----------------
__global__ __launch_bounds__(256) void k_sample() {
    __shared__ int2 st[2][NLAYER][16];
    __shared__ float sinv[2][NLAYER];
    int m0 = blockIdx.x * 2;
    int b = m0 >> 14;
    int q0 = m0 & (NQ - 1);
    int tid = threadIdx.x;
    if (tid < 2 * NLAYER * 16) {
        int pair = tid / 80;
        int rem = tid % 80;
        int layer = rem >> 4, t = rem & 15;
        st[pair][layer][t] = g_tap[((size_t)((b * NLAYER + layer) * NQ + q0 + pair)) * 16 + t];
    } else if (tid >= 192 && tid < 192 + 2 * NLAYER) {
        int e = tid - 192;
        int pair = e / NLAYER, layer = e % NLAYER;
        sinv[pair][layer] = g_bpa[(size_t)(b * NLAYER + layer) * NQ + q0 + pair];
    }
    __syncthreads();

    int pair = tid >> 7;
    int ch = tid & 127;
    int m = m0 + pair;
    const float2* I2 = (const float2*)(g_itrans + (size_t)b * HW * NUM_C) + ch;
    __half2* vdst = (__half2*)(g_vox + (size_t)m * NK) + ch;

    #pragma unroll
    for (int layer = 0; layer < NLAYER; ++layer) {
        float vx = 0.0f, vy = 0.0f;
        if (sinv[pair][layer] != 0.0f) {
            float2 d[16];
            #pragma unroll
            for (int t = 0; t < 16; ++t)
                d[t] = I2[(size_t)st[pair][layer][t].x * 128];
            float ax0 = 0.0f, ax1 = 0.0f, ax2 = 0.0f, ax3 = 0.0f;
            float ay0 = 0.0f, ay1 = 0.0f, ay2 = 0.0f, ay3 = 0.0f;
            #pragma unroll
            for (int t = 0; t < 4; ++t) {
                float f0 = __int_as_float(st[pair][layer][t].y);
                float f1 = __int_as_float(st[pair][layer][4 + t].y);
                float f2 = __int_as_float(st[pair][layer][8 + t].y);
                float f3 = __int_as_float(st[pair][layer][12 + t].y);
                ax0 = fmaf(d[t].x, f0, ax0);      ay0 = fmaf(d[t].y, f0, ay0);
                ax1 = fmaf(d[4 + t].x, f1, ax1);  ay1 = fmaf(d[4 + t].y, f1, ay1);
                ax2 = fmaf(d[8 + t].x, f2, ax2);  ay2 = fmaf(d[8 + t].y, f2, ay2);
                ax3 = fmaf(d[12 + t].x, f3, ax3); ay3 = fmaf(d[12 + t].y, f3, ay3);
            }
            vx = (ax0 + ax1) + (ax2 + ax3);
            vy = (ay0 + ay1) + (ay2 + ay3);
        }
        vdst[layer * 128] = __floats2half2_rn(vx, vy);
    }
}

// ---------------- K6: fp16 mma GEMM (CTA 64Mx128N, 8 warps 2Mx4N, warp 32x32) -------------
// K-chunks compacted by per-(Mtile,layer) visibility: skipped chunks are all-zero A rows.
#define STAGE_BYTES 24576
#define A_BYTES 8192
#define GSM_BYTES (3 * STAGE_BYTES)
#define NKT (NK / 64)   // 20

__global__ __launch_bounds__(256, 3) void k_gemm(const float* __restrict__ bc,
                                                 float* __restrict__ out) {
    extern __shared__ char smc[];
    __shared__ int s_list[NKT];
    __shared__ int s_n;
    uint32_t smb = smem_u32(smc);
    int tid = threadIdx.x;
    int wid = tid >> 5;
    int lane = tid & 31;
    int g = lane >> 2;
    int tg = lane & 3;
    int wm = wid & 1;          // 2 M halves (32 rows each)
    int wn = wid >> 1;         // 4 N quarters (32 cols each)
    int n0 = blockIdx.x * 128;
    int m0 = blockIdx.y * 64;

    if (tid == 0) {
        unsigned vis = g_vis[blockIdx.y];
        int n = 0;
        #pragma unroll
        for (int kt = 0; kt < NKT; ++kt)
            if ((vis >> (kt >> 2)) & 1u) s_list[n++] = kt;
        s_n = n;
    }
    __syncthreads();
    int nact = s_n;

    float acc[2][4][4];
    #pragma unroll
    for (int ms = 0; ms < 2; ++ms)
        #pragma unroll
        for (int ns = 0; ns < 4; ++ns)
            #pragma unroll
            for (int cc = 0; cc < 4; ++cc) acc[ms][ns][cc] = 0.0f;

    int a_row_l = wm * 32 + (lane & 7) + (((lane >> 3) & 1) << 3);
    int a_cadd  = lane >> 4;
    int b_row_l = wn * 32 + (lane & 7) + ((lane >> 4) << 3);
    int b_cadd  = (lane >> 3) & 1;

    #define FILL(slot, ktv) do { \
        int _kt = (ktv); \
        uint32_t _sb = smb + (uint32_t)((slot) * STAGE_BYTES); \
        int _ko = _kt * 64; \
        _Pragma("unroll") \
        for (int _i = 0; _i < 2; ++_i) { \
            int _idx = tid + _i * 256; \
            int _row = _idx >> 3, _c16 = _idx & 7; \
            cp16(_sb + (uint32_t)(_row * 128 + ((_c16 ^ (_row & 7)) << 4)), \
                 (const char*)g_vox + ((size_t)(m0 + _row) * NK + _ko) * 2 + _c16 * 16); \
        } \
        _Pragma("unroll") \
        for (int _i = 0; _i < 4; ++_i) { \
            int _idx = tid + _i * 256; \
            int _row = _idx >> 3, _c16 = _idx & 7; \
            cp16(_sb + (uint32_t)A_BYTES + (uint32_t)(_row * 128 + ((_c16 ^ (_row & 7)) << 4)), \
                 (const char*)g_wperm + ((size_t)(n0 + _row) * NK + _ko) * 2 + _c16 * 16); \
        } \
        asm volatile("cp.async.commit_group;" ::: "memory"); \
    } while (0)

    if (nact > 0) FILL(0, s_list[0]);
    if (nact > 1) FILL(1, s_list[1]);

    for (int it = 0; it < nact; ++it) {
        if (it + 2 < nact) {
            FILL((it + 2) % 3, s_list[it + 2]);
            asm volatile("cp.async.wait_group 2;" ::: "memory");
        } else if (it + 1 < nact) {
            asm volatile("cp.async.wait_group 1;" ::: "memory");
        } else {
            asm volatile("cp.async.wait_group 0;" ::: "memory");
        }
        __syncthreads();

        uint32_t sA = smb + (uint32_t)((it % 3) * STAGE_BYTES);
        uint32_t sB = sA + (uint32_t)A_BYTES;
        #pragma unroll
        for (int ks = 0; ks < 4; ++ks) {
            uint32_t a[2][4];
            #pragma unroll
            for (int ms = 0; ms < 2; ++ms) {
                int row = a_row_l + ms * 16;
                int c16 = 2 * ks + a_cadd;
                LDSM4(a[ms], sA + (uint32_t)(row * 128 + ((c16 ^ (row & 7)) << 4)));
            }
            uint32_t bf[2][4];
            #pragma unroll
            for (int np = 0; np < 2; ++np) {
                int row = b_row_l + np * 16;
                int c16 = 2 * ks + b_cadd;
                LDSM4(bf[np], sB + (uint32_t)(row * 128 + ((c16 ^ (row & 7)) << 4)));
            }
            #pragma unroll
            for (int ms = 0; ms < 2; ++ms)
                #pragma unroll
                for (int ns = 0; ns < 4; ++ns)
                    mma_f16(acc[ms][ns], a[ms], bf[ns >> 1][(ns & 1) * 2], bf[ns >> 1][(ns & 1) * 2 + 1]);
        }
        __syncthreads();
    }

    // Epilogue: out[b][n][q] = relu(acc + bc[n])
    int b = m0 >> 14;
    #pragma unroll
    for (int ms = 0; ms < 2; ++ms) {
        #pragma unroll
        for (int h = 0; h < 2; ++h) {
            int m = m0 + wm * 32 + ms * 16 + g + h * 8;
            int q = m & (NQ - 1);
            float* ob = out + (size_t)b * NUM_C * NQ + q;
            #pragma unroll
            for (int ns = 0; ns < 4; ++ns) {
                int n = n0 + wn * 32 + ns * 8 + tg * 2;
                float v0 = acc[ms][ns][h * 2 + 0] + __ldg(bc + n);
                float v1 = acc[ms][ns][h * 2 + 1] + __ldg(bc + n + 1);
                ob[(size_t)n * NQ] = fmaxf(v0, 0.0f);
                ob[(size_t)(n + 1) * NQ] = fmaxf(v1, 0.0f);
            }
        }
    }
}

extern "C" void kernel_launch(void* const* d_in, const int* in_sizes, int n_in,
                              void* d_out, int out_size) {
    const float* feature = (const float*)d_in[0];  // (2,256,96,320)
    const float* calib   = (const float*)d_in[1];  // (2,3,4)
    const float* grid    = (const float*)d_in[2];  // (128,128,3)
    const float* Wc      = (const float*)d_in[3];  // (256,1280)
    const float* bc      = (const float*)d_in[4];  // (256,)
    float* out = (float*)d_out;                    // (2,256,128,128)

    cudaFuncSetAttribute(k_gemm, cudaFuncAttributeMaxDynamicSharedMemorySize, GSM_BYTES);

    void* visptr = nullptr;
    cudaGetSymbolAddress(&visptr, g_vis);
    cudaMemsetAsync(visptr, 0, NMT * sizeof(unsigned));

    k_rowprep<<<ROWCUM_BLOCKS + PREP_BLOCKS, 256>>>(feature, calib, grid, Wc);
    {
        dim3 g(IMG_W / 16, NUM_C / 16, NUM_B);   // 640 blocks
        dim3 blk(16, 16);
        k_colcum_t<<<g, blk>>>();
    }
    k_sample<<<NM / 2, 256>>>();
    {
        dim3 gg(NUM_C / 128, NM / 64);   // 2 x 512 = 1024 CTAs; N fastest for A reuse
        k_gemm<<<gg, 256, GSM_BYTES>>>(bc, out);
    }
}

// round 13
// speedup vs baseline: 4.2551x; 1.1386x over previous
#include <cuda_runtime.h>
#include <cuda_fp16.h>
#include <math.h>
#include <stdint.h>

// Problem constants
#define NUM_B 2
#define NUM_C 256
#define IMG_H 96
#define IMG_W 320
#define NLAYER 5
#define NQ (128 * 128)           // 16384
#define NM (NUM_B * NQ)          // 32768
#define NK (NUM_C * NLAYER)      // 1280
#define HW (IMG_H * IMG_W)       // 30720
#define NROWS (NUM_B * NUM_C * IMG_H)     // 49152
#define NBOX (NUM_B * NLAYER * NQ)        // 163840
#define NWP (NUM_C * NK)                  // 327680
#define NMT (NM / 64)                     // 512 M-tiles

// Scratch (device globals: allocation-free per harness rules)
__device__ float  g_rowcum[NUM_B * NUM_C * IMG_H * IMG_W];     // 63MB
__device__ float  g_itrans[NUM_B * IMG_H * IMG_W * NUM_C];     // 63MB, [b][y][x][c]
__device__ __align__(256) __half g_vox[NM * NK];               // 84MB, [m][k] fp16
__device__ __align__(256) __half g_wperm[NUM_C * NK];          // 0.65MB, [co][k] fp16
__device__ float  g_bpa[NBOX];                                 // visible ? 1/area : 0
__device__ int2   g_tap[NBOX * 16];                            // {pixel idx, weight bits}
__device__ unsigned g_vis[NMT];                                // per-Mtile layer visibility bits

__device__ __forceinline__ uint32_t smem_u32(const void* p) {
    uint32_t a;
    asm("{ .reg .u64 t; cvta.to.shared.u64 t, %1; cvt.u32.u64 %0, t; }" : "=r"(a) : "l"(p));
    return a;
}
__device__ __forceinline__ void cp16(uint32_t saddr, const void* gptr) {
    asm volatile("cp.async.cg.shared.global [%0], [%1], 16;" :: "r"(saddr), "l"(gptr) : "memory");
}
#define LDSM4(r, a) \
    asm volatile("ldmatrix.sync.aligned.m8n8.x4.shared.b16 {%0,%1,%2,%3}, [%4];" \
                 : "=r"((r)[0]), "=r"((r)[1]), "=r"((r)[2]), "=r"((r)[3]) : "r"(a))
__device__ __forceinline__ void mma_f16(float c[4], const uint32_t a[4], uint32_t b0, uint32_t b1) {
    asm volatile(
        "mma.sync.aligned.m16n8k16.row.col.f32.f16.f16.f32 "
        "{%0,%1,%2,%3}, {%4,%5,%6,%7}, {%8,%9}, {%0,%1,%2,%3};"
        : "+f"(c[0]), "+f"(c[1]), "+f"(c[2]), "+f"(c[3])
        : "r"(a[0]), "r"(a[1]), "r"(a[2]), "r"(a[3]), "r"(b0), "r"(b1));
}

// ---------------- K1: row cumsum (warp-per-row) + prep (boxes/wperm), merged ----------------
#define ROWCUM_BLOCKS (NROWS / 8)     // 6144 blocks of 8 warps
#define PREP_BLOCKS ((NBOX + NWP + 255) / 256)

__global__ __launch_bounds__(256) void k_rowprep(const float* __restrict__ feat,
                                                 const float* __restrict__ calib,
                                                 const float* __restrict__ grid,
                                                 const float* __restrict__ Wc) {
    if (blockIdx.x < ROWCUM_BLOCKS) {
        int w = blockIdx.x * 8 + (threadIdx.x >> 5);
        int lane = threadIdx.x & 31;
        const float* src = feat + (size_t)w * IMG_W;
        float* dst = g_rowcum + (size_t)w * IMG_W;
        float carry = 0.0f;
        #pragma unroll
        for (int c0 = 0; c0 < IMG_W; c0 += 32) {
            float v = src[c0 + lane];
            #pragma unroll
            for (int d = 1; d < 32; d <<= 1) {
                float n = __shfl_up_sync(0xFFFFFFFFu, v, d);
                if (lane >= d) v += n;
            }
            v += carry;
            dst[c0 + lane] = v;
            carry = __shfl_sync(0xFFFFFFFFu, v, 31);
        }
        return;
    }

    int gi = (blockIdx.x - ROWCUM_BLOCKS) * blockDim.x + threadIdx.x;
    if (gi >= NBOX) {
        int idx = gi - NBOX;
        if (idx < NWP) {
            int co = idx / NK;
            int kd = idx % NK;
            int layer = kd / NUM_C;
            int c = kd % NUM_C;
            g_wperm[(size_t)co * NK + layer * NUM_C + c] = __float2half(Wc[co * NK + c * NLAYER + layer]);
        }
        return;
    }
    int i = gi;
    int q = i % NQ;
    int layer = (i / NQ) % NLAYER;
    int b = i / (NQ * NLAYER);

    float gx = grid[q * 3 + 0];
    float gy = grid[q * 3 + 1];
    float gz = grid[q * 3 + 2] + 32.0f * (float)layer;

    const float* M = calib + b * 12;
    float m00 = M[0], m01 = M[1], m02 = M[2],  m03 = M[3];
    float m10 = M[4], m11 = M[5], m12 = M[6],  m13 = M[7];
    float m20 = M[8], m21 = M[9], m22 = M[10], m23 = M[11];

    const float ox[8] = {-12.5f, 12.5f, 12.5f, -12.5f, -12.5f, 12.5f, 12.5f, -12.5f};
    const float oy[8] = {-12.5f, -12.5f, 12.5f, 12.5f, -12.5f, -12.5f, 12.5f, 12.5f};
    const float oz[8] = {0.0f, 0.0f, 0.0f, 0.0f, 32.0f, 32.0f, 32.0f, 32.0f};

    float mnx = 1e30f, mny = 1e30f, mxx = -1e30f, mxy = -1e30f;
    #pragma unroll
    for (int k = 0; k < 8; ++k) {
        float X = gx + ox[k];
        float Y = gy + oy[k];
        float Z = gz + oz[k];
        float px = m00 * X + m01 * Y + m02 * Z + m03;
        float py = m10 * X + m11 * Y + m12 * Z + m13;
        float pz = m20 * X + m21 * Y + m22 * Z + m23;
        float zc = fmaxf(pz, 1e-6f);
        float ix = px / zc;
        float iy = py / zc;
        float nx = fminf(fmaxf(2.0f * ix / 320.0f - 1.0f, -1.0f), 0.95f);
        float ny = fminf(fmaxf(2.0f * iy / 96.0f - 1.0f, -1.0f), 0.95f);
        mnx = fminf(mnx, nx);
        mny = fminf(mny, ny);
        mxx = fmaxf(mxx, nx);
        mxy = fmaxf(mxy, ny);
    }

    float area = ((mxx - mnx) * (mxy - mny)) * (float)HW + 1e-6f;
    bool visible = (area > 1e-6f) && (area < (float)HW * 0.3f);
    float inv = visible ? (1.0f / area) : 0.0f;
    g_bpa[i] = inv;
    if (visible)
        atomicOr(&g_vis[(b * NQ + q) >> 6], 1u << layer);

    float xs[2], ys[2];
    xs[0] = ((mnx + 1.0f) * 320.0f - 1.0f) * 0.5f;
    xs[1] = ((mxx + 1.0f) * 320.0f - 1.0f) * 0.5f;
    ys[0] = ((mny + 1.0f) * 96.0f - 1.0f) * 0.5f;
    ys[1] = ((mxy + 1.0f) * 96.0f - 1.0f) * 0.5f;

    // corners: lt(min,min,+), rb(max,max,+), rt(max,min,-), lb(min,max,-)
    const int cxi[4] = {0, 1, 1, 0};
    const int cyi[4] = {0, 1, 0, 1};
    const float csg[4] = {1.0f, 1.0f, -1.0f, -1.0f};
    int2* tp = g_tap + (size_t)i * 16;
    #pragma unroll
    for (int cc = 0; cc < 4; ++cc) {
        float sx = xs[cxi[cc]], sy = ys[cyi[cc]];
        float fx = floorf(sx), fy = floorf(sy);
        int x0 = (int)fx, y0 = (int)fy;
        float wx1 = sx - fx, wy1 = sy - fy;
        float wx0 = 1.0f - wx1, wy0 = 1.0f - wy1;
        float s = csg[cc] * inv;
        #pragma unroll
        for (int tt = 0; tt < 4; ++tt) {
            int xi = x0 + (tt & 1);
            int yi = y0 + (tt >> 1);
            float w = ((tt & 1) ? wx1 : wx0) * ((tt >> 1) ? wy1 : wy0) * s;
            bool valid = visible && ((unsigned)xi < (unsigned)IMG_W) && ((unsigned)yi < (unsigned)IMG_H);
            int idx = valid ? (yi * IMG_W + xi) : 0;
            if (!valid) w = 0.0f;
            tp[cc * 4 + tt] = make_int2(idx, __float_as_int(w));
        }
    }
}

// ---------------- K2: column cumsum + transpose, (16x,16c) tiles, 640 blocks ----------------
__global__ __launch_bounds__(256) void k_colcum_t() {
    __shared__ float tile[8][16][17];
    int x0 = blockIdx.x * 16;
    int c0 = blockIdx.y * 16;
    int b  = blockIdx.z;
    int tx = threadIdx.x, ty = threadIdx.y;   // read: x = x0+tx, c = c0+ty
    const float* src = g_rowcum + ((size_t)(b * NUM_C + c0 + ty) * IMG_H) * IMG_W + x0 + tx;
    float* dstbase = g_itrans + (size_t)b * HW * NUM_C;
    float acc = 0.0f;
    for (int y0 = 0; y0 < IMG_H; y0 += 8) {
        float v[8];
        #pragma unroll
        for (int j = 0; j < 8; ++j) v[j] = src[(size_t)(y0 + j) * IMG_W];
        #pragma unroll
        for (int j = 0; j < 8; ++j) { acc += v[j]; tile[j][ty][tx] = acc; }
        __syncthreads();
        // write: x = x0+ty, c = c0+tx
        #pragma unroll
        for (int j = 0; j < 8; ++j)
            dstbase[((size_t)(y0 + j) * IMG_W + x0 + ty) * NUM_C + c0 + tx] = tile[j][tx][ty];
        __syncthreads();
    }
}

// ---------------- K4: sampling -> vox (fp16), vis-gated stores + block early-exit ----------
__global__ __launch_bounds__(256) void k_sample() {
    __shared__ int2 st[2][NLAYER][16];
    __shared__ float sinv[2][NLAYER];
    int m0 = blockIdx.x * 2;
    int b = m0 >> 14;
    int q0 = m0 & (NQ - 1);
    int tid = threadIdx.x;

    unsigned visw = g_vis[m0 >> 6];
    if (visw == 0) return;          // GEMM never reads any layer of this tile

    if (tid < 2 * NLAYER * 16) {
        int pair = tid / 80;
        int rem = tid % 80;
        int layer = rem >> 4, t = rem & 15;
        if ((visw >> layer) & 1u)
            st[pair][layer][t] = g_tap[((size_t)((b * NLAYER + layer) * NQ + q0 + pair)) * 16 + t];
    } else if (tid >= 192 && tid < 192 + 2 * NLAYER) {
        int e = tid - 192;
        int pair = e / NLAYER, layer = e % NLAYER;
        sinv[pair][layer] = g_bpa[(size_t)(b * NLAYER + layer) * NQ + q0 + pair];
    }
    __syncthreads();

    int pair = tid >> 7;
    int ch = tid & 127;
    int m = m0 + pair;
    const float2* I2 = (const float2*)(g_itrans + (size_t)b * HW * NUM_C) + ch;
    __half2* vdst = (__half2*)(g_vox + (size_t)m * NK) + ch;

    #pragma unroll
    for (int layer = 0; layer < NLAYER; ++layer) {
        if (!((visw >> layer) & 1u)) continue;   // chunk never read by GEMM
        float vx = 0.0f, vy = 0.0f;
        if (sinv[pair][layer] != 0.0f) {
            float2 d[16];
            #pragma unroll
            for (int t = 0; t < 16; ++t)
                d[t] = I2[(size_t)st[pair][layer][t].x * 128];
            float ax0 = 0.0f, ax1 = 0.0f, ax2 = 0.0f, ax3 = 0.0f;
            float ay0 = 0.0f, ay1 = 0.0f, ay2 = 0.0f, ay3 = 0.0f;
            #pragma unroll
            for (int t = 0; t < 4; ++t) {
                float f0 = __int_as_float(st[pair][layer][t].y);
                float f1 = __int_as_float(st[pair][layer][4 + t].y);
                float f2 = __int_as_float(st[pair][layer][8 + t].y);
                float f3 = __int_as_float(st[pair][layer][12 + t].y);
                ax0 = fmaf(d[t].x, f0, ax0);      ay0 = fmaf(d[t].y, f0, ay0);
                ax1 = fmaf(d[4 + t].x, f1, ax1);  ay1 = fmaf(d[4 + t].y, f1, ay1);
                ax2 = fmaf(d[8 + t].x, f2, ax2);  ay2 = fmaf(d[8 + t].y, f2, ay2);
                ax3 = fmaf(d[12 + t].x, f3, ax3); ay3 = fmaf(d[12 + t].y, f3, ay3);
            }
            vx = (ax0 + ax1) + (ax2 + ax3);
            vy = (ay0 + ay1) + (ay2 + ay3);
        }
        vdst[layer * 128] = __floats2half2_rn(vx, vy);
    }
}

// ---------------- K6: fp16 mma GEMM (CTA 64Mx128N, 8 warps 2Mx4N, warp 32x32) -------------
// K-chunks compacted by per-(Mtile,layer) visibility: skipped chunks are all-zero A rows.
#define STAGE_BYTES 24576
#define A_BYTES 8192
#define GSM_BYTES (3 * STAGE_BYTES)
#define NKT (NK / 64)   // 20

__global__ __launch_bounds__(256, 3) void k_gemm(const float* __restrict__ bc,
                                                 float* __restrict__ out) {
    extern __shared__ char smc[];
    __shared__ int s_list[NKT];
    __shared__ int s_n;
    uint32_t smb = smem_u32(smc);
    int tid = threadIdx.x;
    int wid = tid >> 5;
    int lane = tid & 31;
    int g = lane >> 2;
    int tg = lane & 3;
    int wm = wid & 1;          // 2 M halves (32 rows each)
    int wn = wid >> 1;         // 4 N quarters (32 cols each)
    int n0 = blockIdx.x * 128;
    int m0 = blockIdx.y * 64;

    if (tid == 0) {
        unsigned vis = g_vis[blockIdx.y];
        int n = 0;
        #pragma unroll
        for (int kt = 0; kt < NKT; ++kt)
            if ((vis >> (kt >> 2)) & 1u) s_list[n++] = kt;
        s_n = n;
    }
    __syncthreads();
    int nact = s_n;

    float acc[2][4][4];
    #pragma unroll
    for (int ms = 0; ms < 2; ++ms)
        #pragma unroll
        for (int ns = 0; ns < 4; ++ns)
            #pragma unroll
            for (int cc = 0; cc < 4; ++cc) acc[ms][ns][cc] = 0.0f;

    int a_row_l = wm * 32 + (lane & 7) + (((lane >> 3) & 1) << 3);
    int a_cadd  = lane >> 4;
    int b_row_l = wn * 32 + (lane & 7) + ((lane >> 4) << 3);
    int b_cadd  = (lane >> 3) & 1;

    #define FILL(slot, ktv) do { \
        int _kt = (ktv); \
        uint32_t _sb = smb + (uint32_t)((slot) * STAGE_BYTES); \
        int _ko = _kt * 64; \
        _Pragma("unroll") \
        for (int _i = 0; _i < 2; ++_i) { \
            int _idx = tid + _i * 256; \
            int _row = _idx >> 3, _c16 = _idx & 7; \
            cp16(_sb + (uint32_t)(_row * 128 + ((_c16 ^ (_row & 7)) << 4)), \
                 (const char*)g_vox + ((size_t)(m0 + _row) * NK + _ko) * 2 + _c16 * 16); \
        } \
        _Pragma("unroll") \
        for (int _i = 0; _i < 4; ++_i) { \
            int _idx = tid + _i * 256; \
            int _row = _idx >> 3, _c16 = _idx & 7; \
            cp16(_sb + (uint32_t)A_BYTES + (uint32_t)(_row * 128 + ((_c16 ^ (_row & 7)) << 4)), \
                 (const char*)g_wperm + ((size_t)(n0 + _row) * NK + _ko) * 2 + _c16 * 16); \
        } \
        asm volatile("cp.async.commit_group;" ::: "memory"); \
    } while (0)

    if (nact > 0) FILL(0, s_list[0]);
    if (nact > 1) FILL(1, s_list[1]);

    for (int it = 0; it < nact; ++it) {
        if (it + 2 < nact) {
            FILL((it + 2) % 3, s_list[it + 2]);
            asm volatile("cp.async.wait_group 2;" ::: "memory");
        } else if (it + 1 < nact) {
            asm volatile("cp.async.wait_group 1;" ::: "memory");
        } else {
            asm volatile("cp.async.wait_group 0;" ::: "memory");
        }
        __syncthreads();

        uint32_t sA = smb + (uint32_t)((it % 3) * STAGE_BYTES);
        uint32_t sB = sA + (uint32_t)A_BYTES;
        #pragma unroll
        for (int ks = 0; ks < 4; ++ks) {
            uint32_t a[2][4];
            #pragma unroll
            for (int ms = 0; ms < 2; ++ms) {
                int row = a_row_l + ms * 16;
                int c16 = 2 * ks + a_cadd;
                LDSM4(a[ms], sA + (uint32_t)(row * 128 + ((c16 ^ (row & 7)) << 4)));
            }
            uint32_t bf[2][4];
            #pragma unroll
            for (int np = 0; np < 2; ++np) {
                int row = b_row_l + np * 16;
                int c16 = 2 * ks + b_cadd;
                LDSM4(bf[np], sB + (uint32_t)(row * 128 + ((c16 ^ (row & 7)) << 4)));
            }
            #pragma unroll
            for (int ms = 0; ms < 2; ++ms)
                #pragma unroll
                for (int ns = 0; ns < 4; ++ns)
                    mma_f16(acc[ms][ns], a[ms], bf[ns >> 1][(ns & 1) * 2], bf[ns >> 1][(ns & 1) * 2 + 1]);
        }
        __syncthreads();
    }

    // Epilogue: out[b][n][q] = relu(acc + bc[n])
    int b = m0 >> 14;
    #pragma unroll
    for (int ms = 0; ms < 2; ++ms) {
        #pragma unroll
        for (int h = 0; h < 2; ++h) {
            int m = m0 + wm * 32 + ms * 16 + g + h * 8;
            int q = m & (NQ - 1);
            float* ob = out + (size_t)b * NUM_C * NQ + q;
            #pragma unroll
            for (int ns = 0; ns < 4; ++ns) {
                int n = n0 + wn * 32 + ns * 8 + tg * 2;
                float v0 = acc[ms][ns][h * 2 + 0] + __ldg(bc + n);
                float v1 = acc[ms][ns][h * 2 + 1] + __ldg(bc + n + 1);
                ob[(size_t)n * NQ] = fmaxf(v0, 0.0f);
                ob[(size_t)(n + 1) * NQ] = fmaxf(v1, 0.0f);
            }
        }
    }
}

extern "C" void kernel_launch(void* const* d_in, const int* in_sizes, int n_in,
                              void* d_out, int out_size) {
    const float* feature = (const float*)d_in[0];  // (2,256,96,320)
    const float* calib   = (const float*)d_in[1];  // (2,3,4)
    const float* grid    = (const float*)d_in[2];  // (128,128,3)
    const float* Wc      = (const float*)d_in[3];  // (256,1280)
    const float* bc      = (const float*)d_in[4];  // (256,)
    float* out = (float*)d_out;                    // (2,256,128,128)

    cudaFuncSetAttribute(k_gemm, cudaFuncAttributeMaxDynamicSharedMemorySize, GSM_BYTES);

    void* visptr = nullptr;
    cudaGetSymbolAddress(&visptr, g_vis);
    cudaMemsetAsync(visptr, 0, NMT * sizeof(unsigned));

    k_rowprep<<<ROWCUM_BLOCKS + PREP_BLOCKS, 256>>>(feature, calib, grid, Wc);
    {
        dim3 g(IMG_W / 16, NUM_C / 16, NUM_B);   // 640 blocks
        dim3 blk(16, 16);
        k_colcum_t<<<g, blk>>>();
    }
    k_sample<<<NM / 2, 256>>>();
    {
        dim3 gg(NUM_C / 128, NM / 64);   // 2 x 512 = 1024 CTAs; N fastest for A reuse
        k_gemm<<<gg, 256, GSM_BYTES>>>(bc, out);
    }
}

// round 14
// speedup vs baseline: 4.4524x; 1.0464x over previous
#include <cuda_runtime.h>
#include <cuda_fp16.h>
#include <math.h>
#include <stdint.h>

// Problem constants
#define NUM_B 2
#define NUM_C 256
#define IMG_H 96
#define IMG_W 320
#define NLAYER 5
#define NQ (128 * 128)           // 16384
#define NM (NUM_B * NQ)          // 32768
#define NK (NUM_C * NLAYER)      // 1280
#define HW (IMG_H * IMG_W)       // 30720
#define NROWS (NUM_B * NUM_C * IMG_H)     // 49152
#define NBOX (NUM_B * NLAYER * NQ)        // 163840
#define NWP (NUM_C * NK)                  // 327680
#define NMT (NM / 64)                     // 512 M-tiles

// Scratch (device globals: allocation-free per harness rules)
__device__ float  g_rowcum[NUM_B * NUM_C * IMG_H * IMG_W];     // 63MB
__device__ float  g_itrans[NUM_B * IMG_H * IMG_W * NUM_C];     // 63MB, [b][y][x][c]
__device__ __align__(256) __half g_vox[NM * NK];               // 84MB, [m][k] fp16
__device__ __align__(256) __half g_wperm[NUM_C * NK];          // 0.65MB, [co][k] fp16
__device__ float  g_bpa[NBOX];                                 // visible ? 1/area : 0
__device__ int2   g_tap[NBOX * 16];                            // {pixel idx, weight bits}
__device__ unsigned g_vis[NMT];                                // per-Mtile layer visibility bits

__device__ __forceinline__ uint32_t smem_u32(const void* p) {
    uint32_t a;
    asm("{ .reg .u64 t; cvta.to.shared.u64 t, %1; cvt.u32.u64 %0, t; }" : "=r"(a) : "l"(p));
    return a;
}
__device__ __forceinline__ void cp16(uint32_t saddr, const void* gptr) {
    asm volatile("cp.async.cg.shared.global [%0], [%1], 16;" :: "r"(saddr), "l"(gptr) : "memory");
}
#define LDSM4(r, a) \
    asm volatile("ldmatrix.sync.aligned.m8n8.x4.shared.b16 {%0,%1,%2,%3}, [%4];" \
                 : "=r"((r)[0]), "=r"((r)[1]), "=r"((r)[2]), "=r"((r)[3]) : "r"(a))
__device__ __forceinline__ void mma_f16(float c[4], const uint32_t a[4], uint32_t b0, uint32_t b1) {
    asm volatile(
        "mma.sync.aligned.m16n8k16.row.col.f32.f16.f16.f32 "
        "{%0,%1,%2,%3}, {%4,%5,%6,%7}, {%8,%9}, {%0,%1,%2,%3};"
        : "+f"(c[0]), "+f"(c[1]), "+f"(c[2]), "+f"(c[3])
        : "r"(a[0]), "r"(a[1]), "r"(a[2]), "r"(a[3]), "r"(b0), "r"(b1));
}

// ---------------- K1a: row cumsum, warp-per-row, 2 elems/lane (5 chunks) ----------------
__global__ __launch_bounds__(512) void k_rowcum(const float* __restrict__ feat) {
    int w = blockIdx.x * 16 + (threadIdx.x >> 5);
    int lane = threadIdx.x & 31;
    const float2* src = (const float2*)(feat + (size_t)w * IMG_W);
    float2* dst = (float2*)(g_rowcum + (size_t)w * IMG_W);
    float carry = 0.0f;
    #pragma unroll
    for (int c = 0; c < 5; ++c) {
        float2 v = src[c * 32 + lane];
        float s = v.x + v.y;
        float incl = s;
        #pragma unroll
        for (int d = 1; d < 32; d <<= 1) {
            float n = __shfl_up_sync(0xFFFFFFFFu, incl, d);
            if (lane >= d) incl += n;
        }
        float excl = incl - s;
        float lo = carry + excl + v.x;
        float hi = lo + v.y;
        dst[c * 32 + lane] = make_float2(lo, hi);
        carry += __shfl_sync(0xFFFFFFFFu, incl, 31);
    }
}

// ---------------- K1b: prep (boxes tap table + vis bits + Wc permute) ----------------
#define PREP_BLOCKS ((NBOX + NWP + 255) / 256)

__global__ __launch_bounds__(256) void k_prep(const float* __restrict__ calib,
                                              const float* __restrict__ grid,
                                              const float* __restrict__ Wc) {
    int gi = blockIdx.x * blockDim.x + threadIdx.x;
    if (gi >= NBOX) {
        int idx = gi - NBOX;
        if (idx < NWP) {
            int co = idx / NK;
            int kd = idx % NK;
            int layer = kd / NUM_C;
            int c = kd % NUM_C;
            g_wperm[(size_t)co * NK + layer * NUM_C + c] = __float2half(Wc[co * NK + c * NLAYER + layer]);
        }
        return;
    }
    int i = gi;
    int q = i % NQ;
    int layer = (i / NQ) % NLAYER;
    int b = i / (NQ * NLAYER);

    float gx = grid[q * 3 + 0];
    float gy = grid[q * 3 + 1];
    float gz = grid[q * 3 + 2] + 32.0f * (float)layer;

    const float* M = calib + b * 12;
    float m00 = M[0], m01 = M[1], m02 = M[2],  m03 = M[3];
    float m10 = M[4], m11 = M[5], m12 = M[6],  m13 = M[7];
    float m20 = M[8], m21 = M[9], m22 = M[10], m23 = M[11];

    const float ox[8] = {-12.5f, 12.5f, 12.5f, -12.5f, -12.5f, 12.5f, 12.5f, -12.5f};
    const float oy[8] = {-12.5f, -12.5f, 12.5f, 12.5f, -12.5f, -12.5f, 12.5f, 12.5f};
    const float oz[8] = {0.0f, 0.0f, 0.0f, 0.0f, 32.0f, 32.0f, 32.0f, 32.0f};

    float mnx = 1e30f, mny = 1e30f, mxx = -1e30f, mxy = -1e30f;
    #pragma unroll
    for (int k = 0; k < 8; ++k) {
        float X = gx + ox[k];
        float Y = gy + oy[k];
        float Z = gz + oz[k];
        float px = m00 * X + m01 * Y + m02 * Z + m03;
        float py = m10 * X + m11 * Y + m12 * Z + m13;
        float pz = m20 * X + m21 * Y + m22 * Z + m23;
        float zc = fmaxf(pz, 1e-6f);
        float ix = px / zc;
        float iy = py / zc;
        float nx = fminf(fmaxf(2.0f * ix / 320.0f - 1.0f, -1.0f), 0.95f);
        float ny = fminf(fmaxf(2.0f * iy / 96.0f - 1.0f, -1.0f), 0.95f);
        mnx = fminf(mnx, nx);
        mny = fminf(mny, ny);
        mxx = fmaxf(mxx, nx);
        mxy = fmaxf(mxy, ny);
    }

    float area = ((mxx - mnx) * (mxy - mny)) * (float)HW + 1e-6f;
    bool visible = (area > 1e-6f) && (area < (float)HW * 0.3f);
    float inv = visible ? (1.0f / area) : 0.0f;
    g_bpa[i] = inv;
    if (visible)
        atomicOr(&g_vis[(b * NQ + q) >> 6], 1u << layer);

    float xs[2], ys[2];
    xs[0] = ((mnx + 1.0f) * 320.0f - 1.0f) * 0.5f;
    xs[1] = ((mxx + 1.0f) * 320.0f - 1.0f) * 0.5f;
    ys[0] = ((mny + 1.0f) * 96.0f - 1.0f) * 0.5f;
    ys[1] = ((mxy + 1.0f) * 96.0f - 1.0f) * 0.5f;

    // corners: lt(min,min,+), rb(max,max,+), rt(max,min,-), lb(min,max,-)
    const int cxi[4] = {0, 1, 1, 0};
    const int cyi[4] = {0, 1, 0, 1};
    const float csg[4] = {1.0f, 1.0f, -1.0f, -1.0f};
    int2* tp = g_tap + (size_t)i * 16;
    #pragma unroll
    for (int cc = 0; cc < 4; ++cc) {
        float sx = xs[cxi[cc]], sy = ys[cyi[cc]];
        float fx = floorf(sx), fy = floorf(sy);
        int x0 = (int)fx, y0 = (int)fy;
        float wx1 = sx - fx, wy1 = sy - fy;
        float wx0 = 1.0f - wx1, wy0 = 1.0f - wy1;
        float s = csg[cc] * inv;
        #pragma unroll
        for (int tt = 0; tt < 4; ++tt) {
            int xi = x0 + (tt & 1);
            int yi = y0 + (tt >> 1);
            float w = ((tt & 1) ? wx1 : wx0) * ((tt >> 1) ? wy1 : wy0) * s;
            bool valid = visible && ((unsigned)xi < (unsigned)IMG_W) && ((unsigned)yi < (unsigned)IMG_H);
            int idx = valid ? (yi * IMG_W + xi) : 0;
            if (!valid) w = 0.0f;
            tp[cc * 4 + tt] = make_int2(idx, __float_as_int(w));
        }
    }
}

// ---------------- K2: column cumsum + transpose, (16x,16c) tiles, 640 blocks ----------------
__global__ __launch_bounds__(256) void k_colcum_t() {
    __shared__ float tile[8][16][17];
    int x0 = blockIdx.x * 16;
    int c0 = blockIdx.y * 16;
    int b  = blockIdx.z;
    int tx = threadIdx.x, ty = threadIdx.y;   // read: x = x0+tx, c = c0+ty
    const float* src = g_rowcum + ((size_t)(b * NUM_C + c0 + ty) * IMG_H) * IMG_W + x0 + tx;
    float* dstbase = g_itrans + (size_t)b * HW * NUM_C;
    float acc = 0.0f;
    for (int y0 = 0; y0 < IMG_H; y0 += 8) {
        float v[8];
        #pragma unroll
        for (int j = 0; j < 8; ++j) v[j] = src[(size_t)(y0 + j) * IMG_W];
        #pragma unroll
        for (int j = 0; j < 8; ++j) { acc += v[j]; tile[j][ty][tx] = acc; }
        __syncthreads();
        // write: x = x0+ty, c = c0+tx
        #pragma unroll
        for (int j = 0; j < 8; ++j)
            dstbase[((size_t)(y0 + j) * IMG_W + x0 + ty) * NUM_C + c0 + tx] = tile[j][tx][ty];
        __syncthreads();
    }
}

// ---------------- K4: sampling -> vox (fp16), vis-gated stores + block early-exit ----------
__global__ __launch_bounds__(256) void k_sample() {
    __shared__ int2 st[2][NLAYER][16];
    __shared__ float sinv[2][NLAYER];
    int m0 = blockIdx.x * 2;
    int b = m0 >> 14;
    int q0 = m0 & (NQ - 1);
    int tid = threadIdx.x;

    unsigned visw = g_vis[m0 >> 6];
    if (visw == 0) return;          // GEMM never reads any layer of this tile

    if (tid < 2 * NLAYER * 16) {
        int pair = tid / 80;
        int rem = tid % 80;
        int layer = rem >> 4, t = rem & 15;
        if ((visw >> layer) & 1u)
            st[pair][layer][t] = g_tap[((size_t)((b * NLAYER + layer) * NQ + q0 + pair)) * 16 + t];
    } else if (tid >= 192 && tid < 192 + 2 * NLAYER) {
        int e = tid - 192;
        int pair = e / NLAYER, layer = e % NLAYER;
        sinv[pair][layer] = g_bpa[(size_t)(b * NLAYER + layer) * NQ + q0 + pair];
    }
    __syncthreads();

    int pair = tid >> 7;
    int ch = tid & 127;
    int m = m0 + pair;
    const float2* I2 = (const float2*)(g_itrans + (size_t)b * HW * NUM_C) + ch;
    __half2* vdst = (__half2*)(g_vox + (size_t)m * NK) + ch;

    #pragma unroll
    for (int layer = 0; layer < NLAYER; ++layer) {
        if (!((visw >> layer) & 1u)) continue;   // chunk never read by GEMM
        float vx = 0.0f, vy = 0.0f;
        if (sinv[pair][layer] != 0.0f) {
            float2 d[16];
            #pragma unroll
            for (int t = 0; t < 16; ++t)
                d[t] = I2[(size_t)st[pair][layer][t].x * 128];
            float ax0 = 0.0f, ax1 = 0.0f, ax2 = 0.0f, ax3 = 0.0f;
            float ay0 = 0.0f, ay1 = 0.0f, ay2 = 0.0f, ay3 = 0.0f;
            #pragma unroll
            for (int t = 0; t < 4; ++t) {
                float f0 = __int_as_float(st[pair][layer][t].y);
                float f1 = __int_as_float(st[pair][layer][4 + t].y);
                float f2 = __int_as_float(st[pair][layer][8 + t].y);
                float f3 = __int_as_float(st[pair][layer][12 + t].y);
                ax0 = fmaf(d[t].x, f0, ax0);      ay0 = fmaf(d[t].y, f0, ay0);
                ax1 = fmaf(d[4 + t].x, f1, ax1);  ay1 = fmaf(d[4 + t].y, f1, ay1);
                ax2 = fmaf(d[8 + t].x, f2, ax2);  ay2 = fmaf(d[8 + t].y, f2, ay2);
                ax3 = fmaf(d[12 + t].x, f3, ax3); ay3 = fmaf(d[12 + t].y, f3, ay3);
            }
            vx = (ax0 + ax1) + (ax2 + ax3);
            vy = (ay0 + ay1) + (ay2 + ay3);
        }
        vdst[layer * 128] = __floats2half2_rn(vx, vy);
    }
}

// ---------------- K6: fp16 mma GEMM (CTA 64Mx128N, 8 warps 2Mx4N, warp 32x32) -------------
// K-chunks compacted by per-(Mtile,layer) visibility: skipped chunks are all-zero A rows.
#define STAGE_BYTES 24576
#define A_BYTES 8192
#define GSM_BYTES (3 * STAGE_BYTES)
#define NKT (NK / 64)   // 20

__global__ __launch_bounds__(256, 3) void k_gemm(const float* __restrict__ bc,
                                                 float* __restrict__ out) {
    extern __shared__ char smc[];
    __shared__ int s_list[NKT];
    __shared__ int s_n;
    uint32_t smb = smem_u32(smc);
    int tid = threadIdx.x;
    int wid = tid >> 5;
    int lane = tid & 31;
    int g = lane >> 2;
    int tg = lane & 3;
    int wm = wid & 1;          // 2 M halves (32 rows each)
    int wn = wid >> 1;         // 4 N quarters (32 cols each)
    int n0 = blockIdx.x * 128;
    int m0 = blockIdx.y * 64;

    if (tid == 0) {
        unsigned vis = g_vis[blockIdx.y];
        int n = 0;
        #pragma unroll
        for (int kt = 0; kt < NKT; ++kt)
            if ((vis >> (kt >> 2)) & 1u) s_list[n++] = kt;
        s_n = n;
    }
    __syncthreads();
    int nact = s_n;

    float acc[2][4][4];
    #pragma unroll
    for (int ms = 0; ms < 2; ++ms)
        #pragma unroll
        for (int ns = 0; ns < 4; ++ns)
            #pragma unroll
            for (int cc = 0; cc < 4; ++cc) acc[ms][ns][cc] = 0.0f;

    int a_row_l = wm * 32 + (lane & 7) + (((lane >> 3) & 1) << 3);
    int a_cadd  = lane >> 4;
    int b_row_l = wn * 32 + (lane & 7) + ((lane >> 4) << 3);
    int b_cadd  = (lane >> 3) & 1;

    #define FILL(slot, ktv) do { \
        int _kt = (ktv); \
        uint32_t _sb = smb + (uint32_t)((slot) * STAGE_BYTES); \
        int _ko = _kt * 64; \
        _Pragma("unroll") \
        for (int _i = 0; _i < 2; ++_i) { \
            int _idx = tid + _i * 256; \
            int _row = _idx >> 3, _c16 = _idx & 7; \
            cp16(_sb + (uint32_t)(_row * 128 + ((_c16 ^ (_row & 7)) << 4)), \
                 (const char*)g_vox + ((size_t)(m0 + _row) * NK + _ko) * 2 + _c16 * 16); \
        } \
        _Pragma("unroll") \
        for (int _i = 0; _i < 4; ++_i) { \
            int _idx = tid + _i * 256; \
            int _row = _idx >> 3, _c16 = _idx & 7; \
            cp16(_sb + (uint32_t)A_BYTES + (uint32_t)(_row * 128 + ((_c16 ^ (_row & 7)) << 4)), \
                 (const char*)g_wperm + ((size_t)(n0 + _row) * NK + _ko) * 2 + _c16 * 16); \
        } \
        asm volatile("cp.async.commit_group;" ::: "memory"); \
    } while (0)

    if (nact > 0) FILL(0, s_list[0]);
    if (nact > 1) FILL(1, s_list[1]);

    for (int it = 0; it < nact; ++it) {
        if (it + 2 < nact) {
            FILL((it + 2) % 3, s_list[it + 2]);
            asm volatile("cp.async.wait_group 2;" ::: "memory");
        } else if (it + 1 < nact) {
            asm volatile("cp.async.wait_group 1;" ::: "memory");
        } else {
            asm volatile("cp.async.wait_group 0;" ::: "memory");
        }
        __syncthreads();

        uint32_t sA = smb + (uint32_t)((it % 3) * STAGE_BYTES);
        uint32_t sB = sA + (uint32_t)A_BYTES;
        #pragma unroll
        for (int ks = 0; ks < 4; ++ks) {
            uint32_t a[2][4];
            #pragma unroll
            for (int ms = 0; ms < 2; ++ms) {
                int row = a_row_l + ms * 16;
                int c16 = 2 * ks + a_cadd;
                LDSM4(a[ms], sA + (uint32_t)(row * 128 + ((c16 ^ (row & 7)) << 4)));
            }
            uint32_t bf[2][4];
            #pragma unroll
            for (int np = 0; np < 2; ++np) {
                int row = b_row_l + np * 16;
                int c16 = 2 * ks + b_cadd;
                LDSM4(bf[np], sB + (uint32_t)(row * 128 + ((c16 ^ (row & 7)) << 4)));
            }
            #pragma unroll
            for (int ms = 0; ms < 2; ++ms)
                #pragma unroll
                for (int ns = 0; ns < 4; ++ns)
                    mma_f16(acc[ms][ns], a[ms], bf[ns >> 1][(ns & 1) * 2], bf[ns >> 1][(ns & 1) * 2 + 1]);
        }
        __syncthreads();
    }

    // Epilogue: out[b][n][q] = relu(acc + bc[n])
    int b = m0 >> 14;
    #pragma unroll
    for (int ms = 0; ms < 2; ++ms) {
        #pragma unroll
        for (int h = 0; h < 2; ++h) {
            int m = m0 + wm * 32 + ms * 16 + g + h * 8;
            int q = m & (NQ - 1);
            float* ob = out + (size_t)b * NUM_C * NQ + q;
            #pragma unroll
            for (int ns = 0; ns < 4; ++ns) {
                int n = n0 + wn * 32 + ns * 8 + tg * 2;
                float v0 = acc[ms][ns][h * 2 + 0] + __ldg(bc + n);
                float v1 = acc[ms][ns][h * 2 + 1] + __ldg(bc + n + 1);
                ob[(size_t)n * NQ] = fmaxf(v0, 0.0f);
                ob[(size_t)(n + 1) * NQ] = fmaxf(v1, 0.0f);
            }
        }
    }
}

extern "C" void kernel_launch(void* const* d_in, const int* in_sizes, int n_in,
                              void* d_out, int out_size) {
    const float* feature = (const float*)d_in[0];  // (2,256,96,320)
    const float* calib   = (const float*)d_in[1];  // (2,3,4)
    const float* grid    = (const float*)d_in[2];  // (128,128,3)
    const float* Wc      = (const float*)d_in[3];  // (256,1280)
    const float* bc      = (const float*)d_in[4];  // (256,)
    float* out = (float*)d_out;                    // (2,256,128,128)

    static cudaStream_t s2 = nullptr;
    static cudaEvent_t ev_fork = nullptr, ev_join = nullptr;
    if (s2 == nullptr) {
        cudaStreamCreateWithFlags(&s2, cudaStreamNonBlocking);
        cudaEventCreateWithFlags(&ev_fork, cudaEventDisableTiming);
        cudaEventCreateWithFlags(&ev_join, cudaEventDisableTiming);
        cudaFuncSetAttribute(k_gemm, cudaFuncAttributeMaxDynamicSharedMemorySize, GSM_BYTES);
    }

    void* visptr = nullptr;
    cudaGetSymbolAddress(&visptr, g_vis);

    // Fork: prep branch (vis memset + boxes/wperm) runs concurrently with the
    // integral branch (rowcum -> colcum). Joined before k_sample.
    cudaEventRecord(ev_fork, 0);
    cudaStreamWaitEvent(s2, ev_fork, 0);
    cudaMemsetAsync(visptr, 0, NMT * sizeof(unsigned), s2);
    k_prep<<<PREP_BLOCKS, 256, 0, s2>>>(calib, grid, Wc);
    cudaEventRecord(ev_join, s2);

    k_rowcum<<<NROWS / 16, 512>>>(feature);
    {
        dim3 g(IMG_W / 16, NUM_C / 16, NUM_B);   // 640 blocks
        dim3 blk(16, 16);
        k_colcum_t<<<g, blk>>>();
    }
    cudaStreamWaitEvent(0, ev_join, 0);

    k_sample<<<NM / 2, 256>>>();
    {
        dim3 gg(NUM_C / 128, NM / 64);   // 2 x 512 = 1024 CTAs; N fastest for A reuse
        k_gemm<<<gg, 256, GSM_BYTES>>>(bc, out);
    }
}

// round 15
// speedup vs baseline: 4.6058x; 1.0344x over previous
#include <cuda_runtime.h>
#include <cuda_fp16.h>
#include <math.h>
#include <stdint.h>

// Problem constants
#define NUM_B 2
#define NUM_C 256
#define IMG_H 96
#define IMG_W 320
#define NLAYER 5
#define NQ (128 * 128)           // 16384
#define NM (NUM_B * NQ)          // 32768
#define NK (NUM_C * NLAYER)      // 1280
#define HW (IMG_H * IMG_W)       // 30720
#define NROWS (NUM_B * NUM_C * IMG_H)     // 49152
#define NBOX (NUM_B * NLAYER * NQ)        // 163840
#define NWP (NUM_C * NK)                  // 327680
#define NMT (NM / 64)                     // 512 M-tiles

// Scratch (device globals: allocation-free per harness rules)
__device__ float  g_rowcum[NUM_B * NUM_C * IMG_H * IMG_W];     // 63MB
__device__ float  g_itrans[NUM_B * IMG_H * IMG_W * NUM_C];     // 63MB, [b][y][x][c]
__device__ __align__(256) __half g_vox[NM * NK];               // 84MB, [m][k] fp16
__device__ __align__(256) __half g_wperm[NUM_C * NK];          // 0.65MB, [co][k] fp16
__device__ float  g_bpa[NBOX];                                 // visible ? 1/area : 0
__device__ int2   g_tap[NBOX * 16];                            // {pixel idx, weight bits}
__device__ unsigned g_vis[NMT];                                // per-Mtile layer visibility bits

__device__ __forceinline__ uint32_t smem_u32(const void* p) {
    uint32_t a;
    asm("{ .reg .u64 t; cvta.to.shared.u64 t, %1; cvt.u32.u64 %0, t; }" : "=r"(a) : "l"(p));
    return a;
}
__device__ __forceinline__ void cp16(uint32_t saddr, const void* gptr) {
    asm volatile("cp.async.cg.shared.global [%0], [%1], 16;" :: "r"(saddr), "l"(gptr) : "memory");
}
#define LDSM4(r, a) \
    asm volatile("ldmatrix.sync.aligned.m8n8.x4.shared.b16 {%0,%1,%2,%3}, [%4];" \
                 : "=r"((r)[0]), "=r"((r)[1]), "=r"((r)[2]), "=r"((r)[3]) : "r"(a))
__device__ __forceinline__ void mma_f16(float c[4], const uint32_t a[4], uint32_t b0, uint32_t b1) {
    asm volatile(
        "mma.sync.aligned.m16n8k16.row.col.f32.f16.f16.f32 "
        "{%0,%1,%2,%3}, {%4,%5,%6,%7}, {%8,%9}, {%0,%1,%2,%3};"
        : "+f"(c[0]), "+f"(c[1]), "+f"(c[2]), "+f"(c[3])
        : "r"(a[0]), "r"(a[1]), "r"(a[2]), "r"(a[3]), "r"(b0), "r"(b1));
}

// ---------------- K1a: row cumsum, warp-per-row, 2 elems/lane (5 chunks) ----------------
__global__ __launch_bounds__(512) void k_rowcum(const float* __restrict__ feat) {
    int w = blockIdx.x * 16 + (threadIdx.x >> 5);
    int lane = threadIdx.x & 31;
    const float2* src = (const float2*)(feat + (size_t)w * IMG_W);
    float2* dst = (float2*)(g_rowcum + (size_t)w * IMG_W);
    float carry = 0.0f;
    #pragma unroll
    for (int c = 0; c < 5; ++c) {
        float2 v = src[c * 32 + lane];
        float s = v.x + v.y;
        float incl = s;
        #pragma unroll
        for (int d = 1; d < 32; d <<= 1) {
            float n = __shfl_up_sync(0xFFFFFFFFu, incl, d);
            if (lane >= d) incl += n;
        }
        float excl = incl - s;
        float lo = carry + excl + v.x;
        float hi = lo + v.y;
        dst[c * 32 + lane] = make_float2(lo, hi);
        carry += __shfl_sync(0xFFFFFFFFu, incl, 31);
    }
}

// ---------------- K1b: prep (boxes tap table + vis bits + Wc permute) ----------------
#define PREP_BLOCKS ((NBOX + NWP + 255) / 256)

__global__ __launch_bounds__(256) void k_prep(const float* __restrict__ calib,
                                              const float* __restrict__ grid,
                                              const float* __restrict__ Wc) {
    int gi = blockIdx.x * blockDim.x + threadIdx.x;
    if (gi >= NBOX) {
        int idx = gi - NBOX;
        if (idx < NWP) {
            int co = idx / NK;
            int kd = idx % NK;
            int layer = kd / NUM_C;
            int c = kd % NUM_C;
            g_wperm[(size_t)co * NK + layer * NUM_C + c] = __float2half(Wc[co * NK + c * NLAYER + layer]);
        }
        return;
    }
    int i = gi;
    int q = i % NQ;
    int layer = (i / NQ) % NLAYER;
    int b = i / (NQ * NLAYER);

    float gx = grid[q * 3 + 0];
    float gy = grid[q * 3 + 1];
    float gz = grid[q * 3 + 2] + 32.0f * (float)layer;

    const float* M = calib + b * 12;
    float m00 = M[0], m01 = M[1], m02 = M[2],  m03 = M[3];
    float m10 = M[4], m11 = M[5], m12 = M[6],  m13 = M[7];
    float m20 = M[8], m21 = M[9], m22 = M[10], m23 = M[11];

    const float ox[8] = {-12.5f, 12.5f, 12.5f, -12.5f, -12.5f, 12.5f, 12.5f, -12.5f};
    const float oy[8] = {-12.5f, -12.5f, 12.5f, 12.5f, -12.5f, -12.5f, 12.5f, 12.5f};
    const float oz[8] = {0.0f, 0.0f, 0.0f, 0.0f, 32.0f, 32.0f, 32.0f, 32.0f};

    float mnx = 1e30f, mny = 1e30f, mxx = -1e30f, mxy = -1e30f;
    #pragma unroll
    for (int k = 0; k < 8; ++k) {
        float X = gx + ox[k];
        float Y = gy + oy[k];
        float Z = gz + oz[k];
        float px = m00 * X + m01 * Y + m02 * Z + m03;
        float py = m10 * X + m11 * Y + m12 * Z + m13;
        float pz = m20 * X + m21 * Y + m22 * Z + m23;
        float zc = fmaxf(pz, 1e-6f);
        float ix = px / zc;
        float iy = py / zc;
        float nx = fminf(fmaxf(2.0f * ix / 320.0f - 1.0f, -1.0f), 0.95f);
        float ny = fminf(fmaxf(2.0f * iy / 96.0f - 1.0f, -1.0f), 0.95f);
        mnx = fminf(mnx, nx);
        mny = fminf(mny, ny);
        mxx = fmaxf(mxx, nx);
        mxy = fmaxf(mxy, ny);
    }

    float area = ((mxx - mnx) * (mxy - mny)) * (float)HW + 1e-6f;
    bool visible = (area > 1e-6f) && (area < (float)HW * 0.3f);
    float inv = visible ? (1.0f / area) : 0.0f;
    g_bpa[i] = inv;
    if (visible)
        atomicOr(&g_vis[(b * NQ + q) >> 6], 1u << layer);

    float xs[2], ys[2];
    xs[0] = ((mnx + 1.0f) * 320.0f - 1.0f) * 0.5f;
    xs[1] = ((mxx + 1.0f) * 320.0f - 1.0f) * 0.5f;
    ys[0] = ((mny + 1.0f) * 96.0f - 1.0f) * 0.5f;
    ys[1] = ((mxy + 1.0f) * 96.0f - 1.0f) * 0.5f;

    // corners: lt(min,min,+), rb(max,max,+), rt(max,min,-), lb(min,max,-)
    const int cxi[4] = {0, 1, 1, 0};
    const int cyi[4] = {0, 1, 0, 1};
    const float csg[4] = {1.0f, 1.0f, -1.0f, -1.0f};
    int2* tp = g_tap + (size_t)i * 16;
    #pragma unroll
    for (int cc = 0; cc < 4; ++cc) {
        float sx = xs[cxi[cc]], sy = ys[cyi[cc]];
        float fx = floorf(sx), fy = floorf(sy);
        int x0 = (int)fx, y0 = (int)fy;
        float wx1 = sx - fx, wy1 = sy - fy;
        float wx0 = 1.0f - wx1, wy0 = 1.0f - wy1;
        float s = csg[cc] * inv;
        #pragma unroll
        for (int tt = 0; tt < 4; ++tt) {
            int xi = x0 + (tt & 1);
            int yi = y0 + (tt >> 1);
            float w = ((tt & 1) ? wx1 : wx0) * ((tt >> 1) ? wy1 : wy0) * s;
            bool valid = visible && ((unsigned)xi < (unsigned)IMG_W) && ((unsigned)yi < (unsigned)IMG_H);
            int idx = valid ? (yi * IMG_W + xi) : 0;
            if (!valid) w = 0.0f;
            tp[cc * 4 + tt] = make_int2(idx, __float_as_int(w));
        }
    }
}

// ---------------- K2: column cumsum + transpose, (16x,16c) tiles, 640 blocks ----------------
__global__ __launch_bounds__(256) void k_colcum_t() {
    __shared__ float tile[8][16][17];
    int x0 = blockIdx.x * 16;
    int c0 = blockIdx.y * 16;
    int b  = blockIdx.z;
    int tx = threadIdx.x, ty = threadIdx.y;   // read: x = x0+tx, c = c0+ty
    const float* src = g_rowcum + ((size_t)(b * NUM_C + c0 + ty) * IMG_H) * IMG_W + x0 + tx;
    float* dstbase = g_itrans + (size_t)b * HW * NUM_C;
    float acc = 0.0f;
    for (int y0 = 0; y0 < IMG_H; y0 += 8) {
        float v[8];
        #pragma unroll
        for (int j = 0; j < 8; ++j) v[j] = src[(size_t)(y0 + j) * IMG_W];
        #pragma unroll
        for (int j = 0; j < 8; ++j) { acc += v[j]; tile[j][ty][tx] = acc; }
        __syncthreads();
        // write: x = x0+ty, c = c0+tx
        #pragma unroll
        for (int j = 0; j < 8; ++j)
            dstbase[((size_t)(y0 + j) * IMG_W + x0 + ty) * NUM_C + c0 + tx] = tile[j][tx][ty];
        __syncthreads();
    }
}

// ---------------- K4: sampling -> vox (fp16), vis-gated, m-offset for pipelining ----------
__global__ __launch_bounds__(256) void k_sample(int m_off) {
    __shared__ int2 st[2][NLAYER][16];
    __shared__ float sinv[2][NLAYER];
    int m0 = m_off + blockIdx.x * 2;
    int b = m0 >> 14;
    int q0 = m0 & (NQ - 1);
    int tid = threadIdx.x;

    unsigned visw = g_vis[m0 >> 6];
    if (visw == 0) return;          // GEMM never reads any layer of this tile

    if (tid < 2 * NLAYER * 16) {
        int pair = tid / 80;
        int rem = tid % 80;
        int layer = rem >> 4, t = rem & 15;
        if ((visw >> layer) & 1u)
            st[pair][layer][t] = g_tap[((size_t)((b * NLAYER + layer) * NQ + q0 + pair)) * 16 + t];
    } else if (tid >= 192 && tid < 192 + 2 * NLAYER) {
        int e = tid - 192;
        int pair = e / NLAYER, layer = e % NLAYER;
        sinv[pair][layer] = g_bpa[(size_t)(b * NLAYER + layer) * NQ + q0 + pair];
    }
    __syncthreads();

    int pair = tid >> 7;
    int ch = tid & 127;
    int m = m0 + pair;
    const float2* I2 = (const float2*)(g_itrans + (size_t)b * HW * NUM_C) + ch;
    __half2* vdst = (__half2*)(g_vox + (size_t)m * NK) + ch;

    #pragma unroll
    for (int layer = 0; layer < NLAYER; ++layer) {
        if (!((visw >> layer) & 1u)) continue;   // chunk never read by GEMM
        float vx = 0.0f, vy = 0.0f;
        if (sinv[pair][layer] != 0.0f) {
            float2 d[16];
            #pragma unroll
            for (int t = 0; t < 16; ++t)
                d[t] = I2[(size_t)st[pair][layer][t].x * 128];
            float ax0 = 0.0f, ax1 = 0.0f, ax2 = 0.0f, ax3 = 0.0f;
            float ay0 = 0.0f, ay1 = 0.0f, ay2 = 0.0f, ay3 = 0.0f;
            #pragma unroll
            for (int t = 0; t < 4; ++t) {
                float f0 = __int_as_float(st[pair][layer][t].y);
                float f1 = __int_as_float(st[pair][layer][4 + t].y);
                float f2 = __int_as_float(st[pair][layer][8 + t].y);
                float f3 = __int_as_float(st[pair][layer][12 + t].y);
                ax0 = fmaf(d[t].x, f0, ax0);      ay0 = fmaf(d[t].y, f0, ay0);
                ax1 = fmaf(d[4 + t].x, f1, ax1);  ay1 = fmaf(d[4 + t].y, f1, ay1);
                ax2 = fmaf(d[8 + t].x, f2, ax2);  ay2 = fmaf(d[8 + t].y, f2, ay2);
                ax3 = fmaf(d[12 + t].x, f3, ax3); ay3 = fmaf(d[12 + t].y, f3, ay3);
            }
            vx = (ax0 + ax1) + (ax2 + ax3);
            vy = (ay0 + ay1) + (ay2 + ay3);
        }
        vdst[layer * 128] = __floats2half2_rn(vx, vy);
    }
}

// ---------------- K6: fp16 mma GEMM (CTA 64Mx128N), vis-compacted K, Mtile offset ----------
#define STAGE_BYTES 24576
#define A_BYTES 8192
#define GSM_BYTES (3 * STAGE_BYTES)
#define NKT (NK / 64)   // 20

__global__ __launch_bounds__(256, 3) void k_gemm(const float* __restrict__ bc,
                                                 float* __restrict__ out, int mt_off) {
    extern __shared__ char smc[];
    __shared__ int s_list[NKT];
    __shared__ int s_n;
    uint32_t smb = smem_u32(smc);
    int tid = threadIdx.x;
    int wid = tid >> 5;
    int lane = tid & 31;
    int g = lane >> 2;
    int tg = lane & 3;
    int wm = wid & 1;          // 2 M halves (32 rows each)
    int wn = wid >> 1;         // 4 N quarters (32 cols each)
    int mt = mt_off + blockIdx.y;
    int n0 = blockIdx.x * 128;
    int m0 = mt * 64;

    if (tid == 0) {
        unsigned vis = g_vis[mt];
        int n = 0;
        #pragma unroll
        for (int kt = 0; kt < NKT; ++kt)
            if ((vis >> (kt >> 2)) & 1u) s_list[n++] = kt;
        s_n = n;
    }
    __syncthreads();
    int nact = s_n;

    float acc[2][4][4];
    #pragma unroll
    for (int ms = 0; ms < 2; ++ms)
        #pragma unroll
        for (int ns = 0; ns < 4; ++ns)
            #pragma unroll
            for (int cc = 0; cc < 4; ++cc) acc[ms][ns][cc] = 0.0f;

    int a_row_l = wm * 32 + (lane & 7) + (((lane >> 3) & 1) << 3);
    int a_cadd  = lane >> 4;
    int b_row_l = wn * 32 + (lane & 7) + ((lane >> 4) << 3);
    int b_cadd  = (lane >> 3) & 1;

    #define FILL(slot, ktv) do { \
        int _kt = (ktv); \
        uint32_t _sb = smb + (uint32_t)((slot) * STAGE_BYTES); \
        int _ko = _kt * 64; \
        _Pragma("unroll") \
        for (int _i = 0; _i < 2; ++_i) { \
            int _idx = tid + _i * 256; \
            int _row = _idx >> 3, _c16 = _idx & 7; \
            cp16(_sb + (uint32_t)(_row * 128 + ((_c16 ^ (_row & 7)) << 4)), \
                 (const char*)g_vox + ((size_t)(m0 + _row) * NK + _ko) * 2 + _c16 * 16); \
        } \
        _Pragma("unroll") \
        for (int _i = 0; _i < 4; ++_i) { \
            int _idx = tid + _i * 256; \
            int _row = _idx >> 3, _c16 = _idx & 7; \
            cp16(_sb + (uint32_t)A_BYTES + (uint32_t)(_row * 128 + ((_c16 ^ (_row & 7)) << 4)), \
                 (const char*)g_wperm + ((size_t)(n0 + _row) * NK + _ko) * 2 + _c16 * 16); \
        } \
        asm volatile("cp.async.commit_group;" ::: "memory"); \
    } while (0)

    if (nact > 0) FILL(0, s_list[0]);
    if (nact > 1) FILL(1, s_list[1]);

    for (int it = 0; it < nact; ++it) {
        if (it + 2 < nact) {
            FILL((it + 2) % 3, s_list[it + 2]);
            asm volatile("cp.async.wait_group 2;" ::: "memory");
        } else if (it + 1 < nact) {
            asm volatile("cp.async.wait_group 1;" ::: "memory");
        } else {
            asm volatile("cp.async.wait_group 0;" ::: "memory");
        }
        __syncthreads();

        uint32_t sA = smb + (uint32_t)((it % 3) * STAGE_BYTES);
        uint32_t sB = sA + (uint32_t)A_BYTES;
        #pragma unroll
        for (int ks = 0; ks < 4; ++ks) {
            uint32_t a[2][4];
            #pragma unroll
            for (int ms = 0; ms < 2; ++ms) {
                int row = a_row_l + ms * 16;
                int c16 = 2 * ks + a_cadd;
                LDSM4(a[ms], sA + (uint32_t)(row * 128 + ((c16 ^ (row & 7)) << 4)));
            }
            uint32_t bf[2][4];
            #pragma unroll
            for (int np = 0; np < 2; ++np) {
                int row = b_row_l + np * 16;
                int c16 = 2 * ks + b_cadd;
                LDSM4(bf[np], sB + (uint32_t)(row * 128 + ((c16 ^ (row & 7)) << 4)));
            }
            #pragma unroll
            for (int ms = 0; ms < 2; ++ms)
                #pragma unroll
                for (int ns = 0; ns < 4; ++ns)
                    mma_f16(acc[ms][ns], a[ms], bf[ns >> 1][(ns & 1) * 2], bf[ns >> 1][(ns & 1) * 2 + 1]);
        }
        __syncthreads();
    }

    // Epilogue: out[b][n][q] = relu(acc + bc[n])
    int b = m0 >> 14;
    #pragma unroll
    for (int ms = 0; ms < 2; ++ms) {
        #pragma unroll
        for (int h = 0; h < 2; ++h) {
            int m = m0 + wm * 32 + ms * 16 + g + h * 8;
            int q = m & (NQ - 1);
            float* ob = out + (size_t)b * NUM_C * NQ + q;
            #pragma unroll
            for (int ns = 0; ns < 4; ++ns) {
                int n = n0 + wn * 32 + ns * 8 + tg * 2;
                float v0 = acc[ms][ns][h * 2 + 0] + __ldg(bc + n);
                float v1 = acc[ms][ns][h * 2 + 1] + __ldg(bc + n + 1);
                ob[(size_t)n * NQ] = fmaxf(v0, 0.0f);
                ob[(size_t)(n + 1) * NQ] = fmaxf(v1, 0.0f);
            }
        }
    }
}

extern "C" void kernel_launch(void* const* d_in, const int* in_sizes, int n_in,
                              void* d_out, int out_size) {
    const float* feature = (const float*)d_in[0];  // (2,256,96,320)
    const float* calib   = (const float*)d_in[1];  // (2,3,4)
    const float* grid    = (const float*)d_in[2];  // (128,128,3)
    const float* Wc      = (const float*)d_in[3];  // (256,1280)
    const float* bc      = (const float*)d_in[4];  // (256,)
    float* out = (float*)d_out;                    // (2,256,128,128)

    static cudaStream_t s2 = nullptr;
    static cudaEvent_t ev_fork = nullptr, ev_join = nullptr, ev_mid = nullptr, ev_done = nullptr;
    if (s2 == nullptr) {
        cudaStreamCreateWithFlags(&s2, cudaStreamNonBlocking);
        cudaEventCreateWithFlags(&ev_fork, cudaEventDisableTiming);
        cudaEventCreateWithFlags(&ev_join, cudaEventDisableTiming);
        cudaEventCreateWithFlags(&ev_mid, cudaEventDisableTiming);
        cudaEventCreateWithFlags(&ev_done, cudaEventDisableTiming);
        cudaFuncSetAttribute(k_gemm, cudaFuncAttributeMaxDynamicSharedMemorySize, GSM_BYTES);
    }

    void* visptr = nullptr;
    cudaGetSymbolAddress(&visptr, g_vis);

    // Fork: prep branch (vis memset + boxes/wperm) concurrent with integral branch.
    cudaEventRecord(ev_fork, 0);
    cudaStreamWaitEvent(s2, ev_fork, 0);
    cudaMemsetAsync(visptr, 0, NMT * sizeof(unsigned), s2);
    k_prep<<<PREP_BLOCKS, 256, 0, s2>>>(calib, grid, Wc);
    cudaEventRecord(ev_join, s2);

    k_rowcum<<<NROWS / 16, 512>>>(feature);
    {
        dim3 g(IMG_W / 16, NUM_C / 16, NUM_B);   // 640 blocks
        dim3 blk(16, 16);
        k_colcum_t<<<g, blk>>>();
    }
    cudaStreamWaitEvent(0, ev_join, 0);

    // 2-stage pipeline across batches: sample(b1) overlaps gemm(b0).
    cudaEventRecord(ev_mid, 0);
    cudaStreamWaitEvent(s2, ev_mid, 0);

    // stream0: batch 0
    k_sample<<<NM / 4, 256>>>(0);
    {
        dim3 gg(NUM_C / 128, NMT / 2);
        k_gemm<<<gg, 256, GSM_BYTES>>>(bc, out, 0);
    }
    // stream s2: batch 1
    k_sample<<<NM / 4, 256, 0, s2>>>(NM / 2);
    {
        dim3 gg(NUM_C / 128, NMT / 2);
        k_gemm<<<gg, 256, GSM_BYTES, s2>>>(bc, out, NMT / 2);
    }
    cudaEventRecord(ev_done, s2);
    cudaStreamWaitEvent(0, ev_done, 0);
}

// round 16
// speedup vs baseline: 4.7369x; 1.0285x over previous
#include <cuda_runtime.h>
#include <cuda_fp16.h>
#include <math.h>
#include <stdint.h>

// Problem constants
#define NUM_B 2
#define NUM_C 256
#define IMG_H 96
#define IMG_W 320
#define NLAYER 5
#define NQ (128 * 128)           // 16384
#define NM (NUM_B * NQ)          // 32768
#define NK (NUM_C * NLAYER)      // 1280
#define HW (IMG_H * IMG_W)       // 30720
#define NROWS (NUM_B * NUM_C * IMG_H)     // 49152
#define NBOX (NUM_B * NLAYER * NQ)        // 163840
#define NWP (NUM_C * NK)                  // 327680
#define NMT (NM / 64)                     // 512 M-tiles

// Scratch (device globals: allocation-free per harness rules)
__device__ float  g_rowcum[NUM_B * NUM_C * IMG_H * IMG_W];     // 63MB
__device__ float  g_itrans[NUM_B * IMG_H * IMG_W * NUM_C];     // 63MB, [b][y][x][c]
__device__ __align__(256) __half g_vox[NM * NK];               // 84MB, [m][k] fp16
__device__ __align__(256) __half g_wperm[NUM_C * NK];          // 0.65MB, [co][k] fp16
__device__ float  g_bpa[NBOX];                                 // visible ? 1/area : 0
__device__ int2   g_tap[NBOX * 16];                            // {pixel idx, weight bits}
__device__ unsigned g_vis[NMT];                                // per-Mtile layer visibility bits

__device__ __forceinline__ uint32_t smem_u32(const void* p) {
    uint32_t a;
    asm("{ .reg .u64 t; cvta.to.shared.u64 t, %1; cvt.u32.u64 %0, t; }" : "=r"(a) : "l"(p));
    return a;
}
__device__ __forceinline__ void cp16(uint32_t saddr, const void* gptr) {
    asm volatile("cp.async.cg.shared.global [%0], [%1], 16;" :: "r"(saddr), "l"(gptr) : "memory");
}
#define LDSM4(r, a) \
    asm volatile("ldmatrix.sync.aligned.m8n8.x4.shared.b16 {%0,%1,%2,%3}, [%4];" \
                 : "=r"((r)[0]), "=r"((r)[1]), "=r"((r)[2]), "=r"((r)[3]) : "r"(a))
__device__ __forceinline__ void mma_f16(float c[4], const uint32_t a[4], uint32_t b0, uint32_t b1) {
    asm volatile(
        "mma.sync.aligned.m16n8k16.row.col.f32.f16.f16.f32 "
        "{%0,%1,%2,%3}, {%4,%5,%6,%7}, {%8,%9}, {%0,%1,%2,%3};"
        : "+f"(c[0]), "+f"(c[1]), "+f"(c[2]), "+f"(c[3])
        : "r"(a[0]), "r"(a[1]), "r"(a[2]), "r"(a[3]), "r"(b0), "r"(b1));
}

// ---------------- K1a: row cumsum, warp-per-row, 2 elems/lane, batch-offset ----------------
__global__ __launch_bounds__(512) void k_rowcum(const float* __restrict__ feat, int w_off) {
    int w = w_off + blockIdx.x * 16 + (threadIdx.x >> 5);
    int lane = threadIdx.x & 31;
    const float2* src = (const float2*)(feat + (size_t)w * IMG_W);
    float2* dst = (float2*)(g_rowcum + (size_t)w * IMG_W);
    float carry = 0.0f;
    #pragma unroll
    for (int c = 0; c < 5; ++c) {
        float2 v = src[c * 32 + lane];
        float s = v.x + v.y;
        float incl = s;
        #pragma unroll
        for (int d = 1; d < 32; d <<= 1) {
            float n = __shfl_up_sync(0xFFFFFFFFu, incl, d);
            if (lane >= d) incl += n;
        }
        float excl = incl - s;
        float lo = carry + excl + v.x;
        float hi = lo + v.y;
        dst[c * 32 + lane] = make_float2(lo, hi);
        carry += __shfl_sync(0xFFFFFFFFu, incl, 31);
    }
}

// ---------------- K1b: prep (boxes tap table + vis bits + Wc permute) ----------------
#define PREP_BLOCKS ((NBOX + NWP + 255) / 256)

__global__ __launch_bounds__(256) void k_prep(const float* __restrict__ calib,
                                              const float* __restrict__ grid,
                                              const float* __restrict__ Wc) {
    int gi = blockIdx.x * blockDim.x + threadIdx.x;
    if (gi >= NBOX) {
        int idx = gi - NBOX;
        if (idx < NWP) {
            int co = idx / NK;
            int kd = idx % NK;
            int layer = kd / NUM_C;
            int c = kd % NUM_C;
            g_wperm[(size_t)co * NK + layer * NUM_C + c] = __float2half(Wc[co * NK + c * NLAYER + layer]);
        }
        return;
    }
    int i = gi;
    int q = i % NQ;
    int layer = (i / NQ) % NLAYER;
    int b = i / (NQ * NLAYER);

    float gx = grid[q * 3 + 0];
    float gy = grid[q * 3 + 1];
    float gz = grid[q * 3 + 2] + 32.0f * (float)layer;

    const float* M = calib + b * 12;
    float m00 = M[0], m01 = M[1], m02 = M[2],  m03 = M[3];
    float m10 = M[4], m11 = M[5], m12 = M[6],  m13 = M[7];
    float m20 = M[8], m21 = M[9], m22 = M[10], m23 = M[11];

    const float ox[8] = {-12.5f, 12.5f, 12.5f, -12.5f, -12.5f, 12.5f, 12.5f, -12.5f};
    const float oy[8] = {-12.5f, -12.5f, 12.5f, 12.5f, -12.5f, -12.5f, 12.5f, 12.5f};
    const float oz[8] = {0.0f, 0.0f, 0.0f, 0.0f, 32.0f, 32.0f, 32.0f, 32.0f};

    float mnx = 1e30f, mny = 1e30f, mxx = -1e30f, mxy = -1e30f;
    #pragma unroll
    for (int k = 0; k < 8; ++k) {
        float X = gx + ox[k];
        float Y = gy + oy[k];
        float Z = gz + oz[k];
        float px = m00 * X + m01 * Y + m02 * Z + m03;
        float py = m10 * X + m11 * Y + m12 * Z + m13;
        float pz = m20 * X + m21 * Y + m22 * Z + m23;
        float zc = fmaxf(pz, 1e-6f);
        float ix = px / zc;
        float iy = py / zc;
        float nx = fminf(fmaxf(2.0f * ix / 320.0f - 1.0f, -1.0f), 0.95f);
        float ny = fminf(fmaxf(2.0f * iy / 96.0f - 1.0f, -1.0f), 0.95f);
        mnx = fminf(mnx, nx);
        mny = fminf(mny, ny);
        mxx = fmaxf(mxx, nx);
        mxy = fmaxf(mxy, ny);
    }

    float area = ((mxx - mnx) * (mxy - mny)) * (float)HW + 1e-6f;
    bool visible = (area > 1e-6f) && (area < (float)HW * 0.3f);
    float inv = visible ? (1.0f / area) : 0.0f;
    g_bpa[i] = inv;
    if (visible)
        atomicOr(&g_vis[(b * NQ + q) >> 6], 1u << layer);

    float xs[2], ys[2];
    xs[0] = ((mnx + 1.0f) * 320.0f - 1.0f) * 0.5f;
    xs[1] = ((mxx + 1.0f) * 320.0f - 1.0f) * 0.5f;
    ys[0] = ((mny + 1.0f) * 96.0f - 1.0f) * 0.5f;
    ys[1] = ((mxy + 1.0f) * 96.0f - 1.0f) * 0.5f;

    // corners: lt(min,min,+), rb(max,max,+), rt(max,min,-), lb(min,max,-)
    const int cxi[4] = {0, 1, 1, 0};
    const int cyi[4] = {0, 1, 0, 1};
    const float csg[4] = {1.0f, 1.0f, -1.0f, -1.0f};
    int2* tp = g_tap + (size_t)i * 16;
    #pragma unroll
    for (int cc = 0; cc < 4; ++cc) {
        float sx = xs[cxi[cc]], sy = ys[cyi[cc]];
        float fx = floorf(sx), fy = floorf(sy);
        int x0 = (int)fx, y0 = (int)fy;
        float wx1 = sx - fx, wy1 = sy - fy;
        float wx0 = 1.0f - wx1, wy0 = 1.0f - wy1;
        float s = csg[cc] * inv;
        #pragma unroll
        for (int tt = 0; tt < 4; ++tt) {
            int xi = x0 + (tt & 1);
            int yi = y0 + (tt >> 1);
            float w = ((tt & 1) ? wx1 : wx0) * ((tt >> 1) ? wy1 : wy0) * s;
            bool valid = visible && ((unsigned)xi < (unsigned)IMG_W) && ((unsigned)yi < (unsigned)IMG_H);
            int idx = valid ? (yi * IMG_W + xi) : 0;
            if (!valid) w = 0.0f;
            tp[cc * 4 + tt] = make_int2(idx, __float_as_int(w));
        }
    }
}

// ---------------- K2: column cumsum + transpose, (16x,16c) tiles, per-batch ----------------
__global__ __launch_bounds__(256) void k_colcum_t(int b) {
    __shared__ float tile[8][16][17];
    int x0 = blockIdx.x * 16;
    int c0 = blockIdx.y * 16;
    int tx = threadIdx.x, ty = threadIdx.y;   // read: x = x0+tx, c = c0+ty
    const float* src = g_rowcum + ((size_t)(b * NUM_C + c0 + ty) * IMG_H) * IMG_W + x0 + tx;
    float* dstbase = g_itrans + (size_t)b * HW * NUM_C;
    float acc = 0.0f;
    for (int y0 = 0; y0 < IMG_H; y0 += 8) {
        float v[8];
        #pragma unroll
        for (int j = 0; j < 8; ++j) v[j] = src[(size_t)(y0 + j) * IMG_W];
        #pragma unroll
        for (int j = 0; j < 8; ++j) { acc += v[j]; tile[j][ty][tx] = acc; }
        __syncthreads();
        // write: x = x0+ty, c = c0+tx
        #pragma unroll
        for (int j = 0; j < 8; ++j)
            dstbase[((size_t)(y0 + j) * IMG_W + x0 + ty) * NUM_C + c0 + tx] = tile[j][tx][ty];
        __syncthreads();
    }
}

// ---------------- K4: sampling -> vox (fp16), vis-gated, m-offset ----------
__global__ __launch_bounds__(256) void k_sample(int m_off) {
    __shared__ int2 st[2][NLAYER][16];
    __shared__ float sinv[2][NLAYER];
    int m0 = m_off + blockIdx.x * 2;
    int b = m0 >> 14;
    int q0 = m0 & (NQ - 1);
    int tid = threadIdx.x;

    unsigned visw = g_vis[m0 >> 6];
    if (visw == 0) return;          // GEMM never reads any layer of this tile

    if (tid < 2 * NLAYER * 16) {
        int pair = tid / 80;
        int rem = tid % 80;
        int layer = rem >> 4, t = rem & 15;
        if ((visw >> layer) & 1u)
            st[pair][layer][t] = g_tap[((size_t)((b * NLAYER + layer) * NQ + q0 + pair)) * 16 + t];
    } else if (tid >= 192 && tid < 192 + 2 * NLAYER) {
        int e = tid - 192;
        int pair = e / NLAYER, layer = e % NLAYER;
        sinv[pair][layer] = g_bpa[(size_t)(b * NLAYER + layer) * NQ + q0 + pair];
    }
    __syncthreads();

    int pair = tid >> 7;
    int ch = tid & 127;
    int m = m0 + pair;
    const float2* I2 = (const float2*)(g_itrans + (size_t)b * HW * NUM_C) + ch;
    __half2* vdst = (__half2*)(g_vox + (size_t)m * NK) + ch;

    #pragma unroll
    for (int layer = 0; layer < NLAYER; ++layer) {
        if (!((visw >> layer) & 1u)) continue;   // chunk never read by GEMM
        float vx = 0.0f, vy = 0.0f;
        if (sinv[pair][layer] != 0.0f) {
            float2 d[16];
            #pragma unroll
            for (int t = 0; t < 16; ++t)
                d[t] = I2[(size_t)st[pair][layer][t].x * 128];
            float ax0 = 0.0f, ax1 = 0.0f, ax2 = 0.0f, ax3 = 0.0f;
            float ay0 = 0.0f, ay1 = 0.0f, ay2 = 0.0f, ay3 = 0.0f;
            #pragma unroll
            for (int t = 0; t < 4; ++t) {
                float f0 = __int_as_float(st[pair][layer][t].y);
                float f1 = __int_as_float(st[pair][layer][4 + t].y);
                float f2 = __int_as_float(st[pair][layer][8 + t].y);
                float f3 = __int_as_float(st[pair][layer][12 + t].y);
                ax0 = fmaf(d[t].x, f0, ax0);      ay0 = fmaf(d[t].y, f0, ay0);
                ax1 = fmaf(d[4 + t].x, f1, ax1);  ay1 = fmaf(d[4 + t].y, f1, ay1);
                ax2 = fmaf(d[8 + t].x, f2, ax2);  ay2 = fmaf(d[8 + t].y, f2, ay2);
                ax3 = fmaf(d[12 + t].x, f3, ax3); ay3 = fmaf(d[12 + t].y, f3, ay3);
            }
            vx = (ax0 + ax1) + (ax2 + ax3);
            vy = (ay0 + ay1) + (ay2 + ay3);
        }
        vdst[layer * 128] = __floats2half2_rn(vx, vy);
    }
}

// ---------------- K6: fp16 mma GEMM (CTA 64Mx128N), vis-compacted K, Mtile offset ----------
#define STAGE_BYTES 24576
#define A_BYTES 8192
#define GSM_BYTES (3 * STAGE_BYTES)
#define NKT (NK / 64)   // 20

__global__ __launch_bounds__(256, 3) void k_gemm(const float* __restrict__ bc,
                                                 float* __restrict__ out, int mt_off) {
    extern __shared__ char smc[];
    __shared__ int s_list[NKT];
    __shared__ int s_n;
    uint32_t smb = smem_u32(smc);
    int tid = threadIdx.x;
    int wid = tid >> 5;
    int lane = tid & 31;
    int g = lane >> 2;
    int tg = lane & 3;
    int wm = wid & 1;          // 2 M halves (32 rows each)
    int wn = wid >> 1;         // 4 N quarters (32 cols each)
    int mt = mt_off + blockIdx.y;
    int n0 = blockIdx.x * 128;
    int m0 = mt * 64;

    if (tid == 0) {
        unsigned vis = g_vis[mt];
        int n = 0;
        #pragma unroll
        for (int kt = 0; kt < NKT; ++kt)
            if ((vis >> (kt >> 2)) & 1u) s_list[n++] = kt;
        s_n = n;
    }
    __syncthreads();
    int nact = s_n;

    float acc[2][4][4];
    #pragma unroll
    for (int ms = 0; ms < 2; ++ms)
        #pragma unroll
        for (int ns = 0; ns < 4; ++ns)
            #pragma unroll
            for (int cc = 0; cc < 4; ++cc) acc[ms][ns][cc] = 0.0f;

    int a_row_l = wm * 32 + (lane & 7) + (((lane >> 3) & 1) << 3);
    int a_cadd  = lane >> 4;
    int b_row_l = wn * 32 + (lane & 7) + ((lane >> 4) << 3);
    int b_cadd  = (lane >> 3) & 1;

    #define FILL(slot, ktv) do { \
        int _kt = (ktv); \
        uint32_t _sb = smb + (uint32_t)((slot) * STAGE_BYTES); \
        int _ko = _kt * 64; \
        _Pragma("unroll") \
        for (int _i = 0; _i < 2; ++_i) { \
            int _idx = tid + _i * 256; \
            int _row = _idx >> 3, _c16 = _idx & 7; \
            cp16(_sb + (uint32_t)(_row * 128 + ((_c16 ^ (_row & 7)) << 4)), \
                 (const char*)g_vox + ((size_t)(m0 + _row) * NK + _ko) * 2 + _c16 * 16); \
        } \
        _Pragma("unroll") \
        for (int _i = 0; _i < 4; ++_i) { \
            int _idx = tid + _i * 256; \
            int _row = _idx >> 3, _c16 = _idx & 7; \
            cp16(_sb + (uint32_t)A_BYTES + (uint32_t)(_row * 128 + ((_c16 ^ (_row & 7)) << 4)), \
                 (const char*)g_wperm + ((size_t)(n0 + _row) * NK + _ko) * 2 + _c16 * 16); \
        } \
        asm volatile("cp.async.commit_group;" ::: "memory"); \
    } while (0)

    if (nact > 0) FILL(0, s_list[0]);
    if (nact > 1) FILL(1, s_list[1]);

    for (int it = 0; it < nact; ++it) {
        if (it + 2 < nact) {
            FILL((it + 2) % 3, s_list[it + 2]);
            asm volatile("cp.async.wait_group 2;" ::: "memory");
        } else if (it + 1 < nact) {
            asm volatile("cp.async.wait_group 1;" ::: "memory");
        } else {
            asm volatile("cp.async.wait_group 0;" ::: "memory");
        }
        __syncthreads();

        uint32_t sA = smb + (uint32_t)((it % 3) * STAGE_BYTES);
        uint32_t sB = sA + (uint32_t)A_BYTES;
        #pragma unroll
        for (int ks = 0; ks < 4; ++ks) {
            uint32_t a[2][4];
            #pragma unroll
            for (int ms = 0; ms < 2; ++ms) {
                int row = a_row_l + ms * 16;
                int c16 = 2 * ks + a_cadd;
                LDSM4(a[ms], sA + (uint32_t)(row * 128 + ((c16 ^ (row & 7)) << 4)));
            }
            uint32_t bf[2][4];
            #pragma unroll
            for (int np = 0; np < 2; ++np) {
                int row = b_row_l + np * 16;
                int c16 = 2 * ks + b_cadd;
                LDSM4(bf[np], sB + (uint32_t)(row * 128 + ((c16 ^ (row & 7)) << 4)));
            }
            #pragma unroll
            for (int ms = 0; ms < 2; ++ms)
                #pragma unroll
                for (int ns = 0; ns < 4; ++ns)
                    mma_f16(acc[ms][ns], a[ms], bf[ns >> 1][(ns & 1) * 2], bf[ns >> 1][(ns & 1) * 2 + 1]);
        }
        __syncthreads();
    }

    // Epilogue: out[b][n][q] = relu(acc + bc[n])
    int b = m0 >> 14;
    #pragma unroll
    for (int ms = 0; ms < 2; ++ms) {
        #pragma unroll
        for (int h = 0; h < 2; ++h) {
            int m = m0 + wm * 32 + ms * 16 + g + h * 8;
            int q = m & (NQ - 1);
            float* ob = out + (size_t)b * NUM_C * NQ + q;
            #pragma unroll
            for (int ns = 0; ns < 4; ++ns) {
                int n = n0 + wn * 32 + ns * 8 + tg * 2;
                float v0 = acc[ms][ns][h * 2 + 0] + __ldg(bc + n);
                float v1 = acc[ms][ns][h * 2 + 1] + __ldg(bc + n + 1);
                ob[(size_t)n * NQ] = fmaxf(v0, 0.0f);
                ob[(size_t)(n + 1) * NQ] = fmaxf(v1, 0.0f);
            }
        }
    }
}

extern "C" void kernel_launch(void* const* d_in, const int* in_sizes, int n_in,
                              void* d_out, int out_size) {
    const float* feature = (const float*)d_in[0];  // (2,256,96,320)
    const float* calib   = (const float*)d_in[1];  // (2,3,4)
    const float* grid    = (const float*)d_in[2];  // (128,128,3)
    const float* Wc      = (const float*)d_in[3];  // (256,1280)
    const float* bc      = (const float*)d_in[4];  // (256,)
    float* out = (float*)d_out;                    // (2,256,128,128)

    static cudaStream_t s2 = nullptr, s3 = nullptr;
    static cudaEvent_t ev_fork = nullptr, ev_prep = nullptr, ev_done = nullptr;
    if (s2 == nullptr) {
        cudaStreamCreateWithFlags(&s2, cudaStreamNonBlocking);
        cudaStreamCreateWithFlags(&s3, cudaStreamNonBlocking);
        cudaEventCreateWithFlags(&ev_fork, cudaEventDisableTiming);
        cudaEventCreateWithFlags(&ev_prep, cudaEventDisableTiming);
        cudaEventCreateWithFlags(&ev_done, cudaEventDisableTiming);
        cudaFuncSetAttribute(k_gemm, cudaFuncAttributeMaxDynamicSharedMemorySize, GSM_BYTES);
    }

    void* visptr = nullptr;
    cudaGetSymbolAddress(&visptr, g_vis);

    // Fork three branches off the capture stream.
    cudaEventRecord(ev_fork, 0);
    cudaStreamWaitEvent(s2, ev_fork, 0);
    cudaStreamWaitEvent(s3, ev_fork, 0);

    // Branch s3: prep (vis memset + boxes/wperm)
    cudaMemsetAsync(visptr, 0, NMT * sizeof(unsigned), s3);
    k_prep<<<PREP_BLOCKS, 256, 0, s3>>>(calib, grid, Wc);
    cudaEventRecord(ev_prep, s3);

    // Branch s0 (capture stream): batch 0 pipeline
    k_rowcum<<<NROWS / 32, 512>>>(feature, 0);
    {
        dim3 g(IMG_W / 16, NUM_C / 16, 1);
        dim3 blk(16, 16);
        k_colcum_t<<<g, blk>>>(0);
    }
    cudaStreamWaitEvent(0, ev_prep, 0);
    k_sample<<<NM / 4, 256>>>(0);
    {
        dim3 gg(NUM_C / 128, NMT / 2);
        k_gemm<<<gg, 256, GSM_BYTES>>>(bc, out, 0);
    }

    // Branch s2: batch 1 pipeline
    k_rowcum<<<NROWS / 32, 512, 0, s2>>>(feature, NROWS / 2);
    {
        dim3 g(IMG_W / 16, NUM_C / 16, 1);
        dim3 blk(16, 16);
        k_colcum_t<<<g, blk, 0, s2>>>(1);
    }
    cudaStreamWaitEvent(s2, ev_prep, 0);
    k_sample<<<NM / 4, 256, 0, s2>>>(NM / 2);
    {
        dim3 gg(NUM_C / 128, NMT / 2);
        k_gemm<<<gg, 256, GSM_BYTES, s2>>>(bc, out, NMT / 2);
    }
    cudaEventRecord(ev_done, s2);
    cudaStreamWaitEvent(0, ev_done, 0);
}